// round 10
// baseline (speedup 1.0000x reference)
#include <cuda_runtime.h>
#include <cuda_bf16.h>
#include <math.h>
#include <stdint.h>

#define N_NODES 512
#define TT 128
#define NE 4096
#define C0 64
#define C1 128
#define C2 128
#define EMB 256
#define NG 8
#define EPSV 1e-5f

// ---------------- scratch (device globals; no allocs allowed) ----------------
__device__ float g_y2[N_NODES*122*C1];
__device__ float g_gbuf[NG*30*C1];
__device__ float g_y3[NG*28*C2];
__device__ float g_pe[N_NODES*C0];
__device__ float g_A[NG*64*64];
__device__ int   g_deg[N_NODES];
__device__ float g_s1[C0], g_sq1[C0];
__device__ float g_s2[C1], g_sq2[C1];
__device__ float g_mu3[C2], g_rs3[C2];

// bf16 split buffers
__device__ __nv_bfloat16 g_Ash[NG*64*64],        g_Asl[NG*64*64];
__device__ __nv_bfloat16 g_h0h[N_NODES*TT*C0],   g_h0l[N_NODES*TT*C0];
__device__ __nv_bfloat16 g_agg0h[N_NODES*TT*C0], g_agg0l[N_NODES*TT*C0];
__device__ __nv_bfloat16 g_h1h[N_NODES*TT*EMB],  g_h1l[N_NODES*TT*EMB];
__device__ __nv_bfloat16 g_agg1h[N_NODES*TT*EMB],g_agg1l[N_NODES*TT*EMB];
__device__ __nv_bfloat16 g_h2h[N_NODES*TT*EMB],  g_h2l[N_NODES*TT*EMB];
__device__ __nv_bfloat16 g_Wg1th[EMB*C0],  g_Wg1tl[EMB*C0];     // [256][64]
__device__ __nv_bfloat16 g_Wg2th[EMB*EMB], g_Wg2tl[EMB*EMB];    // [256][256]
__device__ __nv_bfloat16 g_W2th[C1*7*EMB], g_W2tl[C1*7*EMB];    // [128][1792]

// ---------------- helpers ----------------
__device__ __forceinline__ uint32_t smem_u32(const void* p) {
    uint32_t a;
    asm("{ .reg .u64 t; cvta.to.shared.u64 t, %1; cvt.u32.u64 %0, t; }" : "=r"(a) : "l"(p));
    return a;
}
#define CP16(dst, src) asm volatile("cp.async.cg.shared.global [%0], [%1], 16;" :: "r"(dst), "l"(src))
#define CP_COMMIT()    asm volatile("cp.async.commit_group;" ::: "memory")
#define CP_WAITG2()    asm volatile("cp.async.wait_group 2;" ::: "memory")
#define CP_WAIT0()     asm volatile("cp.async.wait_group 0;" ::: "memory")
#define LDSM_X4(r0, r1, r2, r3, addr) \
    asm volatile("ldmatrix.sync.aligned.m8n8.x4.shared.b16 {%0,%1,%2,%3}, [%4];" \
        : "=r"(r0), "=r"(r1), "=r"(r2), "=r"(r3) : "r"(addr))
#define LDSM_X4T(r0, r1, r2, r3, addr) \
    asm volatile("ldmatrix.sync.aligned.m8n8.x4.trans.shared.b16 {%0,%1,%2,%3}, [%4];" \
        : "=r"(r0), "=r"(r1), "=r"(r2), "=r"(r3) : "r"(addr))
#define MMA16816(d, a, b) \
    asm volatile("mma.sync.aligned.m16n8k16.row.col.f32.bf16.bf16.f32 " \
        "{%0,%1,%2,%3}, {%4,%5,%6,%7}, {%8,%9}, {%0,%1,%2,%3};" \
        : "+f"((d)[0]), "+f"((d)[1]), "+f"((d)[2]), "+f"((d)[3]) \
        : "r"((a)[0]), "r"((a)[1]), "r"((a)[2]), "r"((a)[3]), "r"((b)[0]), "r"((b)[1]))

__device__ __forceinline__ void split_store(__nv_bfloat16* H, __nv_bfloat16* L,
                                            long long idx, float v0, float v1) {
    __nv_bfloat16 h0 = __float2bfloat16(v0), h1 = __float2bfloat16(v1);
    __nv_bfloat162 hv; hv.x = h0; hv.y = h1;
    __nv_bfloat162 lv;
    lv.x = __float2bfloat16(v0 - __bfloat162float(h0));
    lv.y = __float2bfloat16(v1 - __bfloat162float(h1));
    *(__nv_bfloat162*)&H[idx] = hv;
    *(__nv_bfloat162*)&L[idx] = lv;
}

__device__ __forceinline__ void split1(float v, __nv_bfloat16* H, __nv_bfloat16* L, int idx) {
    __nv_bfloat16 h = __float2bfloat16(v);
    H[idx] = h;
    L[idx] = __float2bfloat16(v - __bfloat162float(h));
}

// ---------------- setup kernels ----------------
__global__ void k_zero() {
    int i = blockIdx.x*256 + threadIdx.x;
    if (i < NG*64*64) g_A[i] = 0.f;
    if (i < N_NODES)  g_deg[i] = 0;
    if (i < C0) { g_s1[i]=0.f; g_sq1[i]=0.f; }
    if (i < C1) { g_s2[i]=0.f; g_sq2[i]=0.f; }
    if (i < NG*30*C1) g_gbuf[i] = 0.f;
}

__global__ void k_deg(const int* __restrict__ ei) {
    int e = blockIdx.x*256 + threadIdx.x;
    if (e < NE) atomicAdd(&g_deg[ei[NE + e]], 1);
}

__global__ void k_adj(const int* __restrict__ ei) {
    int i = blockIdx.x*256 + threadIdx.x;
    if (i < NE) {
        int s = ei[i], d = ei[NE + i];
        float nr = rsqrtf((float)(g_deg[s]+1)) * rsqrtf((float)(g_deg[d]+1));
        int g = d >> 6;
        atomicAdd(&g_A[(g<<12) + ((d&63)<<6) + (s&63)], nr);
    } else if (i < NE + N_NODES) {
        int n = i - NE;
        float di = 1.f / (float)(g_deg[n]+1);
        atomicAdd(&g_A[((n>>6)<<12) + ((n&63)<<6) + (n&63)], di);
    }
}

// fused weight/adjacency prep: Wg1t, Wg2t, W2t transposed splits + A split
__global__ void k_wprep(const float* __restrict__ Wg1, const float* __restrict__ Wg2,
                        const float* __restrict__ W2) {
    int i = blockIdx.x*256 + threadIdx.x;
    if (i < 16384) {
        int n = i >> 6, k = i & 63;
        split1(Wg1[k*256 + n], g_Wg1th, g_Wg1tl, i);
    } else if (i < 81920) {
        int j = i - 16384;
        int n = j >> 8, k = j & 255;
        split1(Wg2[k*256 + n], g_Wg2th, g_Wg2tl, j);
    } else if (i < 311296) {
        int j = i - 81920;
        int n = j / 1792, k = j - n*1792;
        split1(W2[k*128 + n], g_W2th, g_W2tl, j);
    } else if (i < 344064) {
        int j = i - 311296;
        split1(g_A[j], g_Ash, g_Asl, j);
    }
}

__global__ void k_pe(const float* __restrict__ pos, const float* __restrict__ Wp1,
                     const float* __restrict__ bp1, const float* __restrict__ Wp2,
                     const float* __restrict__ bp2) {
    __shared__ float t1[64];
    int n = blockIdx.x, j = threadIdx.x;
    float p0 = pos[n*3], p1 = pos[n*3+1], p2 = pos[n*3+2];
    t1[j] = fmaxf(p0*Wp1[j] + p1*Wp1[64+j] + p2*Wp1[128+j] + bp1[j], 0.f);
    __syncthreads();
    float s = bp2[j];
    #pragma unroll 8
    for (int k = 0; k < 64; ++k) s += t1[k]*Wp2[k*64 + j];
    g_pe[n*64 + j] = s;
}

// conv1 BN statistics only (y1 never materialized; recomputed in k_bn1pe)
__global__ void k_conv1stats(const float* __restrict__ x, const float* __restrict__ W1) {
    __shared__ float sx[70];
    __shared__ float red[256];
    int b = blockIdx.x;
    int n = b >> 1;
    int t0 = (b & 1) * 64;
    int tid = threadIdx.x;
    if (tid < 70) {
        int t = t0 - 3 + tid;
        sx[tid] = (t >= 0 && t < TT) ? x[n*TT + t] : 0.f;
    }
    __syncthreads();
    int c = tid & 63, r0 = tid >> 6;
    float w[7];
    #pragma unroll
    for (int k = 0; k < 7; ++k) w[k] = W1[k*64 + c];
    float ls = 0.f, lq = 0.f;
    for (int rr = r0; rr < 64; rr += 4) {
        float y = 0.f;
        #pragma unroll
        for (int k = 0; k < 7; ++k) y += sx[rr + k] * w[k];
        ls += y; lq += y*y;
    }
    red[tid] = ls; __syncthreads();
    if (tid < 64) atomicAdd(&g_s1[c], red[tid]+red[tid+64]+red[tid+128]+red[tid+192]);
    __syncthreads();
    red[tid] = lq; __syncthreads();
    if (tid < 64) atomicAdd(&g_sq1[c], red[tid]+red[tid+64]+red[tid+128]+red[tid+192]);
}

// recompute conv1 + BN1 apply + ReLU + add pe -> h0 bf16 split
__global__ void k_bn1pe(const float* __restrict__ x, const float* __restrict__ W1,
                        const float* __restrict__ g1w, const float* __restrict__ b1w) {
    __shared__ float sx[70];
    int b = blockIdx.x;
    int n = b >> 1;
    int t0 = (b & 1) * 64;
    int tid = threadIdx.x;
    if (tid < 70) {
        int t = t0 - 3 + tid;
        sx[tid] = (t >= 0 && t < TT) ? x[n*TT + t] : 0.f;
    }
    __syncthreads();
    int c0 = (tid & 31) * 2;
    int r0 = tid >> 5;
    float w0[7], w1[7];
    #pragma unroll
    for (int k = 0; k < 7; ++k) { w0[k] = W1[k*64 + c0]; w1[k] = W1[k*64 + c0 + 1]; }
    float mu0  = g_s1[c0]   * (1.f/65536.f);
    float var0 = g_sq1[c0]  * (1.f/65536.f) - mu0*mu0;
    float a0 = g1w[c0] * rsqrtf(var0 + EPSV);
    float bb0 = b1w[c0] - mu0*a0;
    float mu1  = g_s1[c0+1]  * (1.f/65536.f);
    float var1 = g_sq1[c0+1] * (1.f/65536.f) - mu1*mu1;
    float a1 = g1w[c0+1] * rsqrtf(var1 + EPSV);
    float bb1 = b1w[c0+1] - mu1*a1;
    float pe0 = g_pe[n*64 + c0], pe1 = g_pe[n*64 + c0 + 1];
    for (int r = r0; r < 64; r += 8) {
        float y0 = 0.f, y1 = 0.f;
        #pragma unroll
        for (int k = 0; k < 7; ++k) { y0 += sx[r+k]*w0[k]; y1 += sx[r+k]*w1[k]; }
        float v0 = fmaxf(a0*y0 + bb0, 0.f) + pe0;
        float v1 = fmaxf(a1*y1 + bb1, 0.f) + pe1;
        split_store(g_h0h, g_h0l, (long long)(b*64 + r)*64 + c0, v0, v1);
    }
}

// ---------------- fp32 SIMT GEMM (conv3 only) ----------------
__global__ void k_gemm(const float* __restrict__ Aall, const float* __restrict__ Ball,
                       float* __restrict__ Call,
                       int M, int N, int K, int Tout, int Tin, int rowC)
{
    const float* A = Aall;
    const float* B = Ball;

    __shared__ __align__(16) float As[16][68];
    __shared__ __align__(16) float Bs[16][68];

    int tid = threadIdx.x;
    int tx = tid & 15, ty = tid >> 4;
    int m0 = blockIdx.y * 64;
    int n0 = blockIdx.x * 64;

    int abase[4]; bool aok[4];
    #pragma unroll
    for (int p = 0; p < 4; ++p) {
        int row = m0 + p*16 + (tid >> 4);
        aok[p] = (row < M);
        abase[p] = aok[p] ? ((row / Tout) * Tin + (row % Tout)) * rowC : 0;
    }
    int akk = tid & 15;

    float acc[4][4] = {};

    for (int k0 = 0; k0 < K; k0 += 16) {
        #pragma unroll
        for (int p = 0; p < 4; ++p) {
            float v = aok[p] ? A[abase[p] + k0 + akk] : 0.f;
            As[akk][p*16 + (tid >> 4)] = v;
        }
        #pragma unroll
        for (int p = 0; p < 4; ++p) {
            int kk = p*4 + (tid >> 6);
            Bs[kk][tid & 63] = B[(k0 + kk) * N + n0 + (tid & 63)];
        }
        __syncthreads();
        #pragma unroll
        for (int kk = 0; kk < 16; ++kk) {
            float4 av = *(const float4*)&As[kk][ty*4];
            float4 bv = *(const float4*)&Bs[kk][tx*4];
            float a_[4] = {av.x, av.y, av.z, av.w};
            float b_[4] = {bv.x, bv.y, bv.z, bv.w};
            #pragma unroll
            for (int i = 0; i < 4; ++i)
                #pragma unroll
                for (int j = 0; j < 4; ++j)
                    acc[i][j] += a_[i] * b_[j];
        }
        __syncthreads();
    }

    #pragma unroll
    for (int i = 0; i < 4; ++i) {
        int row = m0 + ty*4 + i;
        if (row >= M) continue;
        #pragma unroll
        for (int j = 0; j < 4; ++j) {
            int col = n0 + tx*4 + j;
            Call[(long long)row * N + col] = acc[i][j];
        }
    }
}

// ---------------- TC aggregation: O = A(64x64) @ H(64xF) per graph -----------
#define ASTR 72
#define HSTR 264
#define AGG_SMEM (2*64*ASTR*2 + 2*64*HSTR*2)   // 86016

__global__ void __launch_bounds__(256, 2)
k_agg_tc(const __nv_bfloat16* __restrict__ Hh, const __nv_bfloat16* __restrict__ Hl,
         __nv_bfloat16* __restrict__ Oh, __nv_bfloat16* __restrict__ Ol, int F)
{
    extern __shared__ char dsm[];
    uint32_t sAh = smem_u32(dsm);
    uint32_t sAl = sAh + 64*ASTR*2;
    uint32_t sHh = sAl + 64*ASTR*2;
    uint32_t sHl = sHh + 64*HSTR*2;

    int g = blockIdx.y;
    int n0 = blockIdx.x * 256;
    int tid = threadIdx.x, lane = tid & 31, wid = tid >> 5;

    const char* Agh = (const char*)(g_Ash + g*4096);
    const char* Agl = (const char*)(g_Asl + g*4096);
    #pragma unroll
    for (int it = 0; it < 2; ++it) {
        int sid = it*256 + tid;
        int row = sid >> 3, seg = (sid & 7) * 8;
        CP16(sAh + (row*ASTR + seg)*2, Agh + (row*64 + seg)*2);
        CP16(sAl + (row*ASTR + seg)*2, Agl + (row*64 + seg)*2);
    }
    long long hbase = (long long)(g*64) * F + n0;
    #pragma unroll
    for (int it = 0; it < 8; ++it) {
        int sid = it*256 + tid;
        int row = sid >> 5, seg = (sid & 31) * 8;
        long long go = (hbase + (long long)row*F + seg) * 2;
        CP16(sHh + (row*HSTR + seg)*2, (const char*)Hh + go);
        CP16(sHl + (row*HSTR + seg)*2, (const char*)Hl + go);
    }
    CP_COMMIT();
    CP_WAIT0();
    __syncthreads();

    float acc[4][4][4] = {};
    int nw = wid * 32;
    uint32_t arow = lane & 15, ahi = (lane >> 4) * 8;

    #pragma unroll
    for (int kk = 0; kk < 4; ++kk) {
        uint32_t ah[4][4], al[4][4];
        uint32_t acol = kk*16 + ahi;
        #pragma unroll
        for (int i = 0; i < 4; ++i) {
            LDSM_X4(ah[i][0], ah[i][1], ah[i][2], ah[i][3],
                    sAh + ((i*16 + arow)*ASTR + acol)*2);
            LDSM_X4(al[i][0], al[i][1], al[i][2], al[i][3],
                    sAl + ((i*16 + arow)*ASTR + acol)*2);
        }
        uint32_t brow = kk*16 + (lane & 15);
        #pragma unroll
        for (int jp = 0; jp < 2; ++jp) {
            uint32_t bh2[2][2], bl2[2][2];
            uint32_t bcol = nw + jp*16 + ahi;
            uint32_t t0, t1, t2, t3;
            LDSM_X4T(t0, t1, t2, t3, sHh + (brow*HSTR + bcol)*2);
            bh2[0][0] = t0; bh2[0][1] = t1; bh2[1][0] = t2; bh2[1][1] = t3;
            LDSM_X4T(t0, t1, t2, t3, sHl + (brow*HSTR + bcol)*2);
            bl2[0][0] = t0; bl2[0][1] = t1; bl2[1][0] = t2; bl2[1][1] = t3;
            #pragma unroll
            for (int i = 0; i < 4; ++i)
                #pragma unroll
                for (int j2 = 0; j2 < 2; ++j2) {
                    MMA16816(acc[i][jp*2+j2], ah[i], bh2[j2]);
                    MMA16816(acc[i][jp*2+j2], ah[i], bl2[j2]);
                    MMA16816(acc[i][jp*2+j2], al[i], bh2[j2]);
                }
        }
    }

    int rb = lane >> 2;
    int cb = n0 + nw + (lane & 3)*2;
    #pragma unroll
    for (int i = 0; i < 4; ++i)
        #pragma unroll
        for (int j = 0; j < 4; ++j)
            #pragma unroll
            for (int half = 0; half < 2; ++half) {
                int row = i*16 + rb + half*8;
                long long idx = (long long)(g*64 + row) * F + cb + j*8;
                split_store(Oh, Ol, idx, acc[i][j][half*2], acc[i][j][half*2+1]);
            }
}

// ---------------- bf16-split tensor-core GEMM via mma.sync --------------------
// 256x128 block tile, 512 threads (16 warps, 64x32 warp tiles), 4-stage
// cp.async ring with ONE __syncthreads per 32-k chunk, wait_group 2.
// SMEM: zero-padded 64B rows, XOR swizzle phys_chunk = chunk ^ ((row>>1)&3).
// mode 0: fp32 store; 2: bias+relu -> bf16 split store; 3: fp32 store + BN2 stats
#define KC 32
#define ROWB 64
#define A_ARR (256*ROWB)                    // 16384
#define B_ARR (128*ROWB)                    // 8192
#define STAGE_BYTES (2*A_ARR + 2*B_ARR)     // 49152
#define NSTAGE 4

__global__ void __launch_bounds__(512, 1)
k_gemm_tc(const __nv_bfloat16* __restrict__ Ah, const __nv_bfloat16* __restrict__ Al,
          const __nv_bfloat16* __restrict__ Bh, const __nv_bfloat16* __restrict__ Bl,
          const float* __restrict__ bias,
          float* __restrict__ Cf, __nv_bfloat16* __restrict__ Chi, __nv_bfloat16* __restrict__ Clo,
          int K, int Tout, int Tin, int rowC, int ldc, int mode)
{
    extern __shared__ char dsm[];
    __shared__ float s_sum[128], s_sq[128];
    uint32_t sbase = smem_u32(dsm);
    int tid = threadIdx.x, lane = tid & 31, wid = tid >> 5;
    int m0 = blockIdx.y * 256, n0 = blockIdx.x * 128;

    // copy geometry: 512 threads; row = tid/4 (0..127), seg = tid&3
    int crow = tid >> 2;
    int seg  = tid & 3;
    int pseg = seg ^ ((crow >> 1) & 3);     // same for crow and crow+128
    long long gA0, gA1, gB0;
    {
        int rg0 = m0 + crow;
        int rg1 = m0 + crow + 128;
        gA0 = (long long)((rg0 / Tout) * Tin + (rg0 % Tout)) * rowC + seg*8;
        gA1 = (long long)((rg1 / Tout) * Tin + (rg1 % Tout)) * rowC + seg*8;
        gB0 = (long long)(n0 + crow) * K + seg*8;
    }
    uint32_t soA0 = (uint32_t)(crow*ROWB + pseg*16);
    uint32_t soA1 = soA0 + 128*ROWB;
    uint32_t soB0 = (uint32_t)(crow*ROWB + pseg*16);

    // warp tile: wm in 0..3 (64-row subtiles of 256), wn in 0..3 (32-col of 128)
    int wm = wid & 3, wn = wid >> 2;
    uint32_t aRowB = (uint32_t)(wm*64 + (lane & 15)) * ROWB;
    uint32_t aSub  = lane >> 4;
    uint32_t xorA  = ((lane & 15) >> 1) & 3;
    uint32_t bRowB = (uint32_t)(wn*32 + ((lane >> 4) & 1)*8 + (lane & 7)) * ROWB;
    uint32_t bSub  = (lane >> 3) & 1;
    uint32_t xorB  = ((lane & 7) >> 1) & 3;

    float acc[4][4][4] = {};

    int nc = K >> 5;
    // prologue: chunks 0..2 -> stages 0..2 (commit 3 groups, empty if beyond nc)
    #pragma unroll
    for (int pc = 0; pc < 3; ++pc) {
        if (pc < nc) {
            uint32_t st = sbase + pc*STAGE_BYTES;
            long long k0 = (long long)pc*KC;
            CP16(st +             soA0, (const char*)Ah + (gA0+k0)*2);
            CP16(st +             soA1, (const char*)Ah + (gA1+k0)*2);
            CP16(st + A_ARR +     soA0, (const char*)Al + (gA0+k0)*2);
            CP16(st + A_ARR +     soA1, (const char*)Al + (gA1+k0)*2);
            CP16(st + 2*A_ARR +         soB0, (const char*)Bh + (gB0+k0)*2);
            CP16(st + 2*A_ARR + B_ARR + soB0, (const char*)Bl + (gB0+k0)*2);
        }
        CP_COMMIT();
    }

    for (int c = 0; c < nc; ++c) {
        CP_WAITG2();
        __syncthreads();

        if (c + 3 < nc) {
            uint32_t st = sbase + ((c+3) & 3)*STAGE_BYTES;
            long long k0 = (long long)(c+3)*KC;
            CP16(st +             soA0, (const char*)Ah + (gA0+k0)*2);
            CP16(st +             soA1, (const char*)Ah + (gA1+k0)*2);
            CP16(st + A_ARR +     soA0, (const char*)Al + (gA0+k0)*2);
            CP16(st + A_ARR +     soA1, (const char*)Al + (gA1+k0)*2);
            CP16(st + 2*A_ARR +         soB0, (const char*)Bh + (gB0+k0)*2);
            CP16(st + 2*A_ARR + B_ARR + soB0, (const char*)Bl + (gB0+k0)*2);
        }
        CP_COMMIT();

        uint32_t st = sbase + (c & 3)*STAGE_BYTES;

        #pragma unroll
        for (int k16 = 0; k16 < 2; ++k16) {
            uint32_t physA = (((uint32_t)k16*2 + aSub) ^ xorA) * 16;
            uint32_t physB = (((uint32_t)k16*2 + bSub) ^ xorB) * 16;
            uint32_t ah[4][4], al[4][4];
            #pragma unroll
            for (int i = 0; i < 4; ++i) {
                uint32_t ro = aRowB + i*(16*ROWB) + physA;
                LDSM_X4(ah[i][0], ah[i][1], ah[i][2], ah[i][3], st + ro);
                LDSM_X4(al[i][0], al[i][1], al[i][2], al[i][3], st + A_ARR + ro);
            }
            #pragma unroll
            for (int jj = 0; jj < 2; ++jj) {
                uint32_t bh2[2][2], bl2[2][2];
                uint32_t ro = bRowB + jj*(16*ROWB) + physB;
                uint32_t t0, t1, t2, t3;
                LDSM_X4(t0, t1, t2, t3, st + 2*A_ARR + ro);
                bh2[0][0] = t0; bh2[0][1] = t1; bh2[1][0] = t2; bh2[1][1] = t3;
                LDSM_X4(t0, t1, t2, t3, st + 2*A_ARR + B_ARR + ro);
                bl2[0][0] = t0; bl2[0][1] = t1; bl2[1][0] = t2; bl2[1][1] = t3;
                #pragma unroll
                for (int i = 0; i < 4; ++i)
                    #pragma unroll
                    for (int j2 = 0; j2 < 2; ++j2) {
                        MMA16816(acc[i][jj*2+j2], ah[i], bh2[j2]);
                        MMA16816(acc[i][jj*2+j2], ah[i], bl2[j2]);
                        MMA16816(acc[i][jj*2+j2], al[i], bh2[j2]);
                    }
            }
        }
    }

    if (mode == 3) {
        __syncthreads();
        if (tid < 128) { s_sum[tid] = 0.f; s_sq[tid] = 0.f; }
        __syncthreads();
    }

    float psum[8] = {}, psq[8] = {};
    int rbase = m0 + wm*64 + (lane >> 2);
    int cbase = n0 + wn*32 + (lane & 3)*2;
    #pragma unroll
    for (int i = 0; i < 4; ++i) {
        #pragma unroll
        for (int j = 0; j < 4; ++j) {
            int gc = cbase + j*8;
            #pragma unroll
            for (int half = 0; half < 2; ++half) {
                long long gr = rbase + i*16 + half*8;
                float v0 = acc[i][j][half*2], v1 = acc[i][j][half*2 + 1];
                long long idx = gr * ldc + gc;
                if (mode == 2) {
                    v0 = fmaxf(v0 + bias[gc], 0.f);
                    v1 = fmaxf(v1 + bias[gc+1], 0.f);
                    split_store(Chi, Clo, idx, v0, v1);
                } else {
                    *(float2*)&Cf[idx] = make_float2(v0, v1);
                    if (mode == 3) {
                        psum[j*2]   += v0;  psq[j*2]   += v0*v0;
                        psum[j*2+1] += v1;  psq[j*2+1] += v1*v1;
                    }
                }
            }
        }
    }

    if (mode == 3) {
        int lc = wn*32 + (lane & 3)*2;
        #pragma unroll
        for (int j = 0; j < 4; ++j) {
            atomicAdd(&s_sum[lc + j*8],     psum[j*2]);
            atomicAdd(&s_sum[lc + j*8 + 1], psum[j*2+1]);
            atomicAdd(&s_sq[lc + j*8],      psq[j*2]);
            atomicAdd(&s_sq[lc + j*8 + 1],  psq[j*2+1]);
        }
        __syncthreads();
        if (tid < 128) {
            atomicAdd(&g_s2[n0 + tid],  s_sum[tid]);
            atomicAdd(&g_sq2[n0 + tid], s_sq[tid]);
        }
    }
}

// ---------------- pool / BN3 / tail ----------------
__global__ void k_pool(const float* __restrict__ g2w, const float* __restrict__ b2w) {
    int c = threadIdx.x;
    int chunk = blockIdx.x;
    int tp = blockIdx.y;
    int g = blockIdx.z;
    float mu  = g_s2[c]  * (1.f/62464.f);
    float var = g_sq2[c] * (1.f/62464.f) - mu*mu;
    float a = g2w[c] * rsqrtf(var + EPSV);
    float bb = b2w[c] - mu*a;
    float acc = 0.f;
    for (int nl = 0; nl < 16; ++nl) {
        int n = g*64 + chunk*16 + nl;
        const float* p = &g_y2[(n*122 + tp*4)*128 + c];
        float s4 = p[0] + p[128] + p[256] + p[384];
        acc += fmaxf(a * (s4 * 0.25f) + bb, 0.f);
    }
    atomicAdd(&g_gbuf[(g*30 + tp)*128 + c], acc * (1.f/64.f));
}

__global__ void k_bn3stats() {
    __shared__ float red[256];
    int tid = threadIdx.x;
    int c = tid & 127, r0 = tid >> 7;
    float ls = 0.f, lq = 0.f;
    for (int r = r0; r < 224; r += 2) { float v = g_y3[r*128 + c]; ls += v; lq += v*v; }
    red[tid] = ls; __syncthreads();
    float ssum = 0.f;
    if (tid < 128) ssum = red[tid] + red[tid+128];
    __syncthreads();
    red[tid] = lq; __syncthreads();
    if (tid < 128) {
        float q = red[tid] + red[tid+128];
        float mu = ssum * (1.f/224.f);
        float var = q * (1.f/224.f) - mu*mu;
        g_mu3[tid] = mu;
        g_rs3[tid] = rsqrtf(var + EPSV);
    }
}

__global__ void k_tail(const float* __restrict__ g3w, const float* __restrict__ b3w,
                       const float* __restrict__ Wd, const float* __restrict__ bd,
                       float* __restrict__ out) {
    __shared__ float gg[896];
    __shared__ float slog[4];
    int b = blockIdx.x, tid = threadIdx.x;
    int c = tid;
    float a = g3w[c] * g_rs3[c];
    float bb = b3w[c] - g_mu3[c]*a;
    #pragma unroll
    for (int tp = 0; tp < 7; ++tp) {
        const float* p = &g_y3[(b*28 + tp*4)*128 + c];
        float s4 = (p[0] + p[128] + p[256] + p[384]) * 0.25f;
        gg[tp*128 + c] = fmaxf(a*s4 + bb, 0.f);
    }
    __syncthreads();
    int w = tid >> 5, lane = tid & 31;
    float s = 0.f;
    for (int i = lane; i < 896; i += 32) s += gg[i] * Wd[i*4 + w];
    #pragma unroll
    for (int off = 16; off; off >>= 1) s += __shfl_xor_sync(0xffffffffu, s, off);
    if (lane == 0) slog[w] = s + bd[w];
    __syncthreads();
    if (tid == 0) {
        float m = fmaxf(fmaxf(slog[0], slog[1]), fmaxf(slog[2], slog[3]));
        float se = expf(slog[0]-m)+expf(slog[1]-m)+expf(slog[2]-m)+expf(slog[3]-m);
        float lse = logf(se);
        #pragma unroll
        for (int j = 0; j < 4; ++j) out[b*4 + j] = slog[j] - m - lse;
    }
}

// ---------------- launch ----------------
extern "C" void kernel_launch(void* const* d_in, const int* in_sizes, int n_in,
                              void* d_out, int out_size) {
    const float* x   = (const float*)d_in[0];
    const float* pos = (const float*)d_in[1];
    const int*   ei  = (const int*)d_in[2];
    const float* W1  = (const float*)d_in[4];
    const float* g1  = (const float*)d_in[5];
    const float* b1  = (const float*)d_in[6];
    const float* Wp1 = (const float*)d_in[7];
    const float* bp1 = (const float*)d_in[8];
    const float* Wp2 = (const float*)d_in[9];
    const float* bp2 = (const float*)d_in[10];
    const float* Wg1 = (const float*)d_in[11];
    const float* bg1 = (const float*)d_in[12];
    const float* Wg2 = (const float*)d_in[13];
    const float* bg2 = (const float*)d_in[14];
    const float* W2  = (const float*)d_in[15];
    const float* g2  = (const float*)d_in[16];
    const float* b2  = (const float*)d_in[17];
    const float* W3  = (const float*)d_in[18];
    const float* g3  = (const float*)d_in[19];
    const float* b3  = (const float*)d_in[20];
    const float* Wd  = (const float*)d_in[21];
    const float* bd  = (const float*)d_in[22];
    float* out = (float*)d_out;

    float *pY2, *pGbuf, *pY3;
    __nv_bfloat16 *pH0h, *pH0l, *pA0h, *pA0l, *pH1h, *pH1l, *pA1h, *pA1l, *pH2h, *pH2l;
    __nv_bfloat16 *pWg1h, *pWg1l, *pWg2h, *pWg2l, *pW2h, *pW2l;
    cudaGetSymbolAddress((void**)&pY2,   g_y2);
    cudaGetSymbolAddress((void**)&pGbuf, g_gbuf);
    cudaGetSymbolAddress((void**)&pY3,   g_y3);
    cudaGetSymbolAddress((void**)&pH0h,  g_h0h);
    cudaGetSymbolAddress((void**)&pH0l,  g_h0l);
    cudaGetSymbolAddress((void**)&pA0h,  g_agg0h);
    cudaGetSymbolAddress((void**)&pA0l,  g_agg0l);
    cudaGetSymbolAddress((void**)&pH1h,  g_h1h);
    cudaGetSymbolAddress((void**)&pH1l,  g_h1l);
    cudaGetSymbolAddress((void**)&pA1h,  g_agg1h);
    cudaGetSymbolAddress((void**)&pA1l,  g_agg1l);
    cudaGetSymbolAddress((void**)&pH2h,  g_h2h);
    cudaGetSymbolAddress((void**)&pH2l,  g_h2l);
    cudaGetSymbolAddress((void**)&pWg1h, g_Wg1th);
    cudaGetSymbolAddress((void**)&pWg1l, g_Wg1tl);
    cudaGetSymbolAddress((void**)&pWg2h, g_Wg2th);
    cudaGetSymbolAddress((void**)&pWg2l, g_Wg2tl);
    cudaGetSymbolAddress((void**)&pW2h,  g_W2th);
    cudaGetSymbolAddress((void**)&pW2l,  g_W2tl);

    const int DSM = NSTAGE*STAGE_BYTES;   // 196608
    cudaFuncSetAttribute(k_gemm_tc, cudaFuncAttributeMaxDynamicSharedMemorySize, DSM);
    cudaFuncSetAttribute(k_agg_tc, cudaFuncAttributeMaxDynamicSharedMemorySize, AGG_SMEM);

    k_zero<<<128, 256>>>();
    k_deg<<<16, 256>>>(ei);
    k_adj<<<18, 256>>>(ei);
    k_wprep<<<1344, 256>>>(Wg1, Wg2, W2);
    k_pe<<<512, 64>>>(pos, Wp1, bp1, Wp2, bp2);
    k_conv1stats<<<1024, 256>>>(x, W1);
    k_bn1pe<<<1024, 256>>>(x, W1, g1, b1);

    // agg0 = A @ h0  (TC, split out), F = T*C0 = 8192
    k_agg_tc<<<dim3(32, 8), 256, AGG_SMEM>>>(pH0h, pH0l, pA0h, pA0l, 8192);
    // gcn1: h1 = relu(agg0 @ Wg1^T + bg1)  (TC, split out)  M=65536/256=256
    k_gemm_tc<<<dim3(2, 256), 512, DSM>>>(pA0h, pA0l, pWg1h, pWg1l, bg1,
                                          nullptr, pH1h, pH1l,
                                          64, 65536, 65536, 64, 256, 2);
    // agg1 = A @ h1  (TC, split out), F = T*EMB = 32768
    k_agg_tc<<<dim3(128, 8), 256, AGG_SMEM>>>(pH1h, pH1l, pA1h, pA1l, 32768);
    // gcn2: h2 = relu(agg1 @ Wg2^T + bg2)  (TC, split out)
    k_gemm_tc<<<dim3(2, 256), 512, DSM>>>(pA1h, pA1l, pWg2h, pWg2l, bg2,
                                          nullptr, pH2h, pH2l,
                                          256, 65536, 65536, 256, 256, 2);
    // conv2 (k=7 VALID, 256->128) implicit GEMM (TC, fp32 out + fused BN2 stats)
    // M = 62464 = 244*256
    k_gemm_tc<<<dim3(1, 244), 512, DSM>>>(pH2h, pH2l, pW2h, pW2l, nullptr,
                                          pY2, nullptr, nullptr,
                                          1792, 122, 128, 256, 128, 3);
    k_pool<<<dim3(4, 30, 8), 128>>>(g2, b2);
    // conv3 (k=3 VALID, 128->128) SIMT
    k_gemm<<<dim3(2, 4, 1), 256>>>(pGbuf, W3, pY3, 224, 128, 384, 28, 30, 128);
    k_bn3stats<<<1, 256>>>();
    k_tail<<<8, 128>>>(g3, b3, Wd, bd, out);
}

// round 11
// speedup vs baseline: 1.1189x; 1.1189x over previous
#include <cuda_runtime.h>
#include <cuda_bf16.h>
#include <math.h>
#include <stdint.h>

#define N_NODES 512
#define TT 128
#define NE 4096
#define C0 64
#define C1 128
#define C2 128
#define EMB 256
#define NG 8
#define EPSV 1e-5f

// ---------------- scratch (device globals; no allocs allowed) ----------------
__device__ float g_y2[N_NODES*122*C1];
__device__ float g_gbuf[NG*30*C1];
__device__ float g_y3[NG*28*C2];
__device__ float g_pe[N_NODES*C0];
__device__ float g_A[NG*64*64];
__device__ int   g_deg[N_NODES];
__device__ float g_s1[C0], g_sq1[C0];
__device__ float g_s2[C1], g_sq2[C1];
__device__ float g_mu3[C2], g_rs3[C2];

// bf16 split buffers
__device__ __nv_bfloat16 g_Ash[NG*64*64],        g_Asl[NG*64*64];
__device__ __nv_bfloat16 g_h0h[N_NODES*TT*C0],   g_h0l[N_NODES*TT*C0];
__device__ __nv_bfloat16 g_agg0h[N_NODES*TT*C0], g_agg0l[N_NODES*TT*C0];
__device__ __nv_bfloat16 g_h1h[N_NODES*TT*EMB],  g_h1l[N_NODES*TT*EMB];
__device__ __nv_bfloat16 g_agg1h[N_NODES*TT*EMB],g_agg1l[N_NODES*TT*EMB];
__device__ __nv_bfloat16 g_h2h[N_NODES*TT*EMB],  g_h2l[N_NODES*TT*EMB];
__device__ __nv_bfloat16 g_Wg1th[EMB*C0],  g_Wg1tl[EMB*C0];     // [256][64]
__device__ __nv_bfloat16 g_Wg2th[EMB*EMB], g_Wg2tl[EMB*EMB];    // [256][256]
__device__ __nv_bfloat16 g_W2th[C1*7*EMB], g_W2tl[C1*7*EMB];    // [128][1792]

// ---------------- helpers ----------------
__device__ __forceinline__ uint32_t smem_u32(const void* p) {
    uint32_t a;
    asm("{ .reg .u64 t; cvta.to.shared.u64 t, %1; cvt.u32.u64 %0, t; }" : "=r"(a) : "l"(p));
    return a;
}
#define CP16(dst, src) asm volatile("cp.async.cg.shared.global [%0], [%1], 16;" :: "r"(dst), "l"(src))
#define CP_COMMIT()    asm volatile("cp.async.commit_group;" ::: "memory")
#define CP_WAITG1()    asm volatile("cp.async.wait_group 1;" ::: "memory")
#define CP_WAITG2()    asm volatile("cp.async.wait_group 2;" ::: "memory")
#define CP_WAIT0()     asm volatile("cp.async.wait_group 0;" ::: "memory")
#define LDSM_X4(r0, r1, r2, r3, addr) \
    asm volatile("ldmatrix.sync.aligned.m8n8.x4.shared.b16 {%0,%1,%2,%3}, [%4];" \
        : "=r"(r0), "=r"(r1), "=r"(r2), "=r"(r3) : "r"(addr))
#define LDSM_X4T(r0, r1, r2, r3, addr) \
    asm volatile("ldmatrix.sync.aligned.m8n8.x4.trans.shared.b16 {%0,%1,%2,%3}, [%4];" \
        : "=r"(r0), "=r"(r1), "=r"(r2), "=r"(r3) : "r"(addr))
#define MMA16816(d, a, b) \
    asm volatile("mma.sync.aligned.m16n8k16.row.col.f32.bf16.bf16.f32 " \
        "{%0,%1,%2,%3}, {%4,%5,%6,%7}, {%8,%9}, {%0,%1,%2,%3};" \
        : "+f"((d)[0]), "+f"((d)[1]), "+f"((d)[2]), "+f"((d)[3]) \
        : "r"((a)[0]), "r"((a)[1]), "r"((a)[2]), "r"((a)[3]), "r"((b)[0]), "r"((b)[1]))

__device__ __forceinline__ void split_store(__nv_bfloat16* H, __nv_bfloat16* L,
                                            long long idx, float v0, float v1) {
    __nv_bfloat16 h0 = __float2bfloat16(v0), h1 = __float2bfloat16(v1);
    __nv_bfloat162 hv; hv.x = h0; hv.y = h1;
    __nv_bfloat162 lv;
    lv.x = __float2bfloat16(v0 - __bfloat162float(h0));
    lv.y = __float2bfloat16(v1 - __bfloat162float(h1));
    *(__nv_bfloat162*)&H[idx] = hv;
    *(__nv_bfloat162*)&L[idx] = lv;
}

__device__ __forceinline__ void split1(float v, __nv_bfloat16* H, __nv_bfloat16* L, int idx) {
    __nv_bfloat16 h = __float2bfloat16(v);
    H[idx] = h;
    L[idx] = __float2bfloat16(v - __bfloat162float(h));
}

// ---------------- setup kernels ----------------
__global__ void k_zero() {
    int i = blockIdx.x*256 + threadIdx.x;
    if (i < NG*64*64) g_A[i] = 0.f;
    if (i < N_NODES)  g_deg[i] = 0;
    if (i < C0) { g_s1[i]=0.f; g_sq1[i]=0.f; }
    if (i < C1) { g_s2[i]=0.f; g_sq2[i]=0.f; }
    if (i < NG*30*C1) g_gbuf[i] = 0.f;
}

__global__ void k_deg(const int* __restrict__ ei) {
    int e = blockIdx.x*256 + threadIdx.x;
    if (e < NE) atomicAdd(&g_deg[ei[NE + e]], 1);
}

__global__ void k_adj(const int* __restrict__ ei) {
    int i = blockIdx.x*256 + threadIdx.x;
    if (i < NE) {
        int s = ei[i], d = ei[NE + i];
        float nr = rsqrtf((float)(g_deg[s]+1)) * rsqrtf((float)(g_deg[d]+1));
        int g = d >> 6;
        atomicAdd(&g_A[(g<<12) + ((d&63)<<6) + (s&63)], nr);
    } else if (i < NE + N_NODES) {
        int n = i - NE;
        float di = 1.f / (float)(g_deg[n]+1);
        atomicAdd(&g_A[((n>>6)<<12) + ((n&63)<<6) + (n&63)], di);
    }
}

// fused weight/adjacency prep: Wg1t, Wg2t, W2t transposed splits + A split
__global__ void k_wprep(const float* __restrict__ Wg1, const float* __restrict__ Wg2,
                        const float* __restrict__ W2) {
    int i = blockIdx.x*256 + threadIdx.x;
    if (i < 16384) {
        int n = i >> 6, k = i & 63;
        split1(Wg1[k*256 + n], g_Wg1th, g_Wg1tl, i);
    } else if (i < 81920) {
        int j = i - 16384;
        int n = j >> 8, k = j & 255;
        split1(Wg2[k*256 + n], g_Wg2th, g_Wg2tl, j);
    } else if (i < 311296) {
        int j = i - 81920;
        int n = j / 1792, k = j - n*1792;
        split1(W2[k*128 + n], g_W2th, g_W2tl, j);
    } else if (i < 344064) {
        int j = i - 311296;
        split1(g_A[j], g_Ash, g_Asl, j);
    }
}

__global__ void k_pe(const float* __restrict__ pos, const float* __restrict__ Wp1,
                     const float* __restrict__ bp1, const float* __restrict__ Wp2,
                     const float* __restrict__ bp2) {
    __shared__ float t1[64];
    int n = blockIdx.x, j = threadIdx.x;
    float p0 = pos[n*3], p1 = pos[n*3+1], p2 = pos[n*3+2];
    t1[j] = fmaxf(p0*Wp1[j] + p1*Wp1[64+j] + p2*Wp1[128+j] + bp1[j], 0.f);
    __syncthreads();
    float s = bp2[j];
    #pragma unroll 8
    for (int k = 0; k < 64; ++k) s += t1[k]*Wp2[k*64 + j];
    g_pe[n*64 + j] = s;
}

// conv1 BN statistics only
__global__ void k_conv1stats(const float* __restrict__ x, const float* __restrict__ W1) {
    __shared__ float sx[70];
    __shared__ float red[256];
    int b = blockIdx.x;
    int n = b >> 1;
    int t0 = (b & 1) * 64;
    int tid = threadIdx.x;
    if (tid < 70) {
        int t = t0 - 3 + tid;
        sx[tid] = (t >= 0 && t < TT) ? x[n*TT + t] : 0.f;
    }
    __syncthreads();
    int c = tid & 63, r0 = tid >> 6;
    float w[7];
    #pragma unroll
    for (int k = 0; k < 7; ++k) w[k] = W1[k*64 + c];
    float ls = 0.f, lq = 0.f;
    for (int rr = r0; rr < 64; rr += 4) {
        float y = 0.f;
        #pragma unroll
        for (int k = 0; k < 7; ++k) y += sx[rr + k] * w[k];
        ls += y; lq += y*y;
    }
    red[tid] = ls; __syncthreads();
    if (tid < 64) atomicAdd(&g_s1[c], red[tid]+red[tid+64]+red[tid+128]+red[tid+192]);
    __syncthreads();
    red[tid] = lq; __syncthreads();
    if (tid < 64) atomicAdd(&g_sq1[c], red[tid]+red[tid+64]+red[tid+128]+red[tid+192]);
}

// recompute conv1 + BN1 apply + ReLU + add pe -> h0 bf16 split
__global__ void k_bn1pe(const float* __restrict__ x, const float* __restrict__ W1,
                        const float* __restrict__ g1w, const float* __restrict__ b1w) {
    __shared__ float sx[70];
    int b = blockIdx.x;
    int n = b >> 1;
    int t0 = (b & 1) * 64;
    int tid = threadIdx.x;
    if (tid < 70) {
        int t = t0 - 3 + tid;
        sx[tid] = (t >= 0 && t < TT) ? x[n*TT + t] : 0.f;
    }
    __syncthreads();
    int c0 = (tid & 31) * 2;
    int r0 = tid >> 5;
    float w0[7], w1[7];
    #pragma unroll
    for (int k = 0; k < 7; ++k) { w0[k] = W1[k*64 + c0]; w1[k] = W1[k*64 + c0 + 1]; }
    float mu0  = g_s1[c0]   * (1.f/65536.f);
    float var0 = g_sq1[c0]  * (1.f/65536.f) - mu0*mu0;
    float a0 = g1w[c0] * rsqrtf(var0 + EPSV);
    float bb0 = b1w[c0] - mu0*a0;
    float mu1  = g_s1[c0+1]  * (1.f/65536.f);
    float var1 = g_sq1[c0+1] * (1.f/65536.f) - mu1*mu1;
    float a1 = g1w[c0+1] * rsqrtf(var1 + EPSV);
    float bb1 = b1w[c0+1] - mu1*a1;
    float pe0 = g_pe[n*64 + c0], pe1 = g_pe[n*64 + c0 + 1];
    for (int r = r0; r < 64; r += 8) {
        float y0 = 0.f, y1 = 0.f;
        #pragma unroll
        for (int k = 0; k < 7; ++k) { y0 += sx[r+k]*w0[k]; y1 += sx[r+k]*w1[k]; }
        float v0 = fmaxf(a0*y0 + bb0, 0.f) + pe0;
        float v1 = fmaxf(a1*y1 + bb1, 0.f) + pe1;
        split_store(g_h0h, g_h0l, (long long)(b*64 + r)*64 + c0, v0, v1);
    }
}

// ---------------- fp32 SIMT GEMM (conv3 only) ----------------
__global__ void k_gemm(const float* __restrict__ Aall, const float* __restrict__ Ball,
                       float* __restrict__ Call,
                       int M, int N, int K, int Tout, int Tin, int rowC)
{
    const float* A = Aall;
    const float* B = Ball;

    __shared__ __align__(16) float As[16][68];
    __shared__ __align__(16) float Bs[16][68];

    int tid = threadIdx.x;
    int tx = tid & 15, ty = tid >> 4;
    int m0 = blockIdx.y * 64;
    int n0 = blockIdx.x * 64;

    int abase[4]; bool aok[4];
    #pragma unroll
    for (int p = 0; p < 4; ++p) {
        int row = m0 + p*16 + (tid >> 4);
        aok[p] = (row < M);
        abase[p] = aok[p] ? ((row / Tout) * Tin + (row % Tout)) * rowC : 0;
    }
    int akk = tid & 15;

    float acc[4][4] = {};

    for (int k0 = 0; k0 < K; k0 += 16) {
        #pragma unroll
        for (int p = 0; p < 4; ++p) {
            float v = aok[p] ? A[abase[p] + k0 + akk] : 0.f;
            As[akk][p*16 + (tid >> 4)] = v;
        }
        #pragma unroll
        for (int p = 0; p < 4; ++p) {
            int kk = p*4 + (tid >> 6);
            Bs[kk][tid & 63] = B[(k0 + kk) * N + n0 + (tid & 63)];
        }
        __syncthreads();
        #pragma unroll
        for (int kk = 0; kk < 16; ++kk) {
            float4 av = *(const float4*)&As[kk][ty*4];
            float4 bv = *(const float4*)&Bs[kk][tx*4];
            float a_[4] = {av.x, av.y, av.z, av.w};
            float b_[4] = {bv.x, bv.y, bv.z, bv.w};
            #pragma unroll
            for (int i = 0; i < 4; ++i)
                #pragma unroll
                for (int j = 0; j < 4; ++j)
                    acc[i][j] += a_[i] * b_[j];
        }
        __syncthreads();
    }

    #pragma unroll
    for (int i = 0; i < 4; ++i) {
        int row = m0 + ty*4 + i;
        if (row >= M) continue;
        #pragma unroll
        for (int j = 0; j < 4; ++j) {
            int col = n0 + tx*4 + j;
            Call[(long long)row * N + col] = acc[i][j];
        }
    }
}

// ---------------- TC aggregation: O = A(64x64) @ H(64xF) per graph -----------
#define ASTR 72
#define HSTR 264
#define AGG_SMEM (2*64*ASTR*2 + 2*64*HSTR*2)   // 86016

__global__ void __launch_bounds__(256, 2)
k_agg_tc(const __nv_bfloat16* __restrict__ Hh, const __nv_bfloat16* __restrict__ Hl,
         __nv_bfloat16* __restrict__ Oh, __nv_bfloat16* __restrict__ Ol, int F)
{
    extern __shared__ char dsm[];
    uint32_t sAh = smem_u32(dsm);
    uint32_t sAl = sAh + 64*ASTR*2;
    uint32_t sHh = sAl + 64*ASTR*2;
    uint32_t sHl = sHh + 64*HSTR*2;

    int g = blockIdx.y;
    int n0 = blockIdx.x * 256;
    int tid = threadIdx.x, lane = tid & 31, wid = tid >> 5;

    const char* Agh = (const char*)(g_Ash + g*4096);
    const char* Agl = (const char*)(g_Asl + g*4096);
    #pragma unroll
    for (int it = 0; it < 2; ++it) {
        int sid = it*256 + tid;
        int row = sid >> 3, seg = (sid & 7) * 8;
        CP16(sAh + (row*ASTR + seg)*2, Agh + (row*64 + seg)*2);
        CP16(sAl + (row*ASTR + seg)*2, Agl + (row*64 + seg)*2);
    }
    long long hbase = (long long)(g*64) * F + n0;
    #pragma unroll
    for (int it = 0; it < 8; ++it) {
        int sid = it*256 + tid;
        int row = sid >> 5, seg = (sid & 31) * 8;
        long long go = (hbase + (long long)row*F + seg) * 2;
        CP16(sHh + (row*HSTR + seg)*2, (const char*)Hh + go);
        CP16(sHl + (row*HSTR + seg)*2, (const char*)Hl + go);
    }
    CP_COMMIT();
    CP_WAIT0();
    __syncthreads();

    float acc[4][4][4] = {};
    int nw = wid * 32;
    uint32_t arow = lane & 15, ahi = (lane >> 4) * 8;

    #pragma unroll
    for (int kk = 0; kk < 4; ++kk) {
        uint32_t ah[4][4], al[4][4];
        uint32_t acol = kk*16 + ahi;
        #pragma unroll
        for (int i = 0; i < 4; ++i) {
            LDSM_X4(ah[i][0], ah[i][1], ah[i][2], ah[i][3],
                    sAh + ((i*16 + arow)*ASTR + acol)*2);
            LDSM_X4(al[i][0], al[i][1], al[i][2], al[i][3],
                    sAl + ((i*16 + arow)*ASTR + acol)*2);
        }
        uint32_t brow = kk*16 + (lane & 15);
        #pragma unroll
        for (int jp = 0; jp < 2; ++jp) {
            uint32_t bh2[2][2], bl2[2][2];
            uint32_t bcol = nw + jp*16 + ahi;
            uint32_t t0, t1, t2, t3;
            LDSM_X4T(t0, t1, t2, t3, sHh + (brow*HSTR + bcol)*2);
            bh2[0][0] = t0; bh2[0][1] = t1; bh2[1][0] = t2; bh2[1][1] = t3;
            LDSM_X4T(t0, t1, t2, t3, sHl + (brow*HSTR + bcol)*2);
            bl2[0][0] = t0; bl2[0][1] = t1; bl2[1][0] = t2; bl2[1][1] = t3;
            #pragma unroll
            for (int i = 0; i < 4; ++i)
                #pragma unroll
                for (int j2 = 0; j2 < 2; ++j2) {
                    MMA16816(acc[i][jp*2+j2], ah[i], bh2[j2]);
                    MMA16816(acc[i][jp*2+j2], ah[i], bl2[j2]);
                    MMA16816(acc[i][jp*2+j2], al[i], bh2[j2]);
                }
        }
    }

    int rb = lane >> 2;
    int cb = n0 + nw + (lane & 3)*2;
    #pragma unroll
    for (int i = 0; i < 4; ++i)
        #pragma unroll
        for (int j = 0; j < 4; ++j)
            #pragma unroll
            for (int half = 0; half < 2; ++half) {
                int row = i*16 + rb + half*8;
                long long idx = (long long)(g*64 + row) * F + cb + j*8;
                split_store(Oh, Ol, idx, acc[i][j][half*2], acc[i][j][half*2+1]);
            }
}

// ---------------- bf16-split tensor-core GEMM (R9 config: 128x128, 3-stage) ---
#define KC 32
#define ROWB 64
#define ARR_BYTES (128*ROWB)                // 8192
#define STAGE_BYTES (4*ARR_BYTES)           // 32768
#define NSTAGE 3

__global__ void __launch_bounds__(256, 2)
k_gemm_tc(const __nv_bfloat16* __restrict__ Ah, const __nv_bfloat16* __restrict__ Al,
          const __nv_bfloat16* __restrict__ Bh, const __nv_bfloat16* __restrict__ Bl,
          const float* __restrict__ bias,
          __nv_bfloat16* __restrict__ Chi, __nv_bfloat16* __restrict__ Clo,
          int K, int ldc)
{
    extern __shared__ char dsm[];
    uint32_t sbase = smem_u32(dsm);
    int tid = threadIdx.x, lane = tid & 31, wid = tid >> 5;
    int m0 = blockIdx.y * 128, n0 = blockIdx.x * 128;

    long long gA0, gB0;
    uint32_t so0;
    {
        int row = tid >> 2;         // 0..63
        int seg = tid & 3;
        // two row groups handled via +64 below
        gA0 = (long long)(m0 + row) * K + seg*8;
        gB0 = (long long)(n0 + row) * K + seg*8;
        int pseg = seg ^ ((row >> 1) & 3);
        so0 = (uint32_t)(row*ROWB + pseg*16);
    }
    long long gA1, gB1;
    uint32_t so1;
    {
        int row = (tid >> 2) + 64;
        int seg = tid & 3;
        gA1 = (long long)(m0 + row) * K + seg*8;
        gB1 = (long long)(n0 + row) * K + seg*8;
        int pseg = seg ^ ((row >> 1) & 3);
        so1 = (uint32_t)(row*ROWB + pseg*16);
    }

    int wm = wid & 1, wn = wid >> 1;
    uint32_t aRowB = (uint32_t)(wm*64 + (lane & 15)) * ROWB;
    uint32_t aSub  = lane >> 4;
    uint32_t xorA  = ((lane & 15) >> 1) & 3;
    uint32_t bRowB = (uint32_t)(wn*32 + ((lane >> 4) & 1)*8 + (lane & 7)) * ROWB;
    uint32_t bSub  = (lane >> 3) & 1;
    uint32_t xorB  = ((lane & 7) >> 1) & 3;

    float acc[4][4][4] = {};

    int nc = K >> 5;
    #pragma unroll
    for (int pc = 0; pc < 2; ++pc) {
        uint32_t st = sbase + pc*STAGE_BYTES;
        long long k0 = (long long)pc*KC;
        CP16(st +              so0, (const char*)Ah + (gA0+k0)*2);
        CP16(st +              so1, (const char*)Ah + (gA1+k0)*2);
        CP16(st + ARR_BYTES  + so0, (const char*)Al + (gA0+k0)*2);
        CP16(st + ARR_BYTES  + so1, (const char*)Al + (gA1+k0)*2);
        CP16(st + 2*ARR_BYTES+ so0, (const char*)Bh + (gB0+k0)*2);
        CP16(st + 2*ARR_BYTES+ so1, (const char*)Bh + (gB1+k0)*2);
        CP16(st + 3*ARR_BYTES+ so0, (const char*)Bl + (gB0+k0)*2);
        CP16(st + 3*ARR_BYTES+ so1, (const char*)Bl + (gB1+k0)*2);
        CP_COMMIT();
    }

    int scur = 0, snext2 = 2;
    for (int c = 0; c < nc; ++c) {
        CP_WAITG1();
        __syncthreads();

        if (c + 2 < nc) {
            uint32_t st = sbase + snext2*STAGE_BYTES;
            long long k0 = (long long)(c+2)*KC;
            CP16(st +              so0, (const char*)Ah + (gA0+k0)*2);
            CP16(st +              so1, (const char*)Ah + (gA1+k0)*2);
            CP16(st + ARR_BYTES  + so0, (const char*)Al + (gA0+k0)*2);
            CP16(st + ARR_BYTES  + so1, (const char*)Al + (gA1+k0)*2);
            CP16(st + 2*ARR_BYTES+ so0, (const char*)Bh + (gB0+k0)*2);
            CP16(st + 2*ARR_BYTES+ so1, (const char*)Bh + (gB1+k0)*2);
            CP16(st + 3*ARR_BYTES+ so0, (const char*)Bl + (gB0+k0)*2);
            CP16(st + 3*ARR_BYTES+ so1, (const char*)Bl + (gB1+k0)*2);
        }
        CP_COMMIT();

        uint32_t st = sbase + scur*STAGE_BYTES;

        #pragma unroll
        for (int k16 = 0; k16 < 2; ++k16) {
            uint32_t physA = (((uint32_t)k16*2 + aSub) ^ xorA) * 16;
            uint32_t physB = (((uint32_t)k16*2 + bSub) ^ xorB) * 16;
            uint32_t ah[4][4], al[4][4];
            #pragma unroll
            for (int i = 0; i < 4; ++i) {
                uint32_t ro = aRowB + i*(16*ROWB) + physA;
                LDSM_X4(ah[i][0], ah[i][1], ah[i][2], ah[i][3], st + ro);
                LDSM_X4(al[i][0], al[i][1], al[i][2], al[i][3], st + ARR_BYTES + ro);
            }
            #pragma unroll
            for (int jj = 0; jj < 2; ++jj) {
                uint32_t bh2[2][2], bl2[2][2];
                uint32_t ro = bRowB + jj*(16*ROWB) + physB;
                uint32_t t0, t1, t2, t3;
                LDSM_X4(t0, t1, t2, t3, st + 2*ARR_BYTES + ro);
                bh2[0][0] = t0; bh2[0][1] = t1; bh2[1][0] = t2; bh2[1][1] = t3;
                LDSM_X4(t0, t1, t2, t3, st + 3*ARR_BYTES + ro);
                bl2[0][0] = t0; bl2[0][1] = t1; bl2[1][0] = t2; bl2[1][1] = t3;
                #pragma unroll
                for (int i = 0; i < 4; ++i)
                    #pragma unroll
                    for (int j2 = 0; j2 < 2; ++j2) {
                        MMA16816(acc[i][jj*2+j2], ah[i], bh2[j2]);
                        MMA16816(acc[i][jj*2+j2], ah[i], bl2[j2]);
                        MMA16816(acc[i][jj*2+j2], al[i], bh2[j2]);
                    }
            }
        }
        scur = (scur == NSTAGE-1) ? 0 : scur+1;
        snext2 = (snext2 == NSTAGE-1) ? 0 : snext2+1;
    }

    int rbase = m0 + wm*64 + (lane >> 2);
    int cbase = n0 + wn*32 + (lane & 3)*2;
    #pragma unroll
    for (int i = 0; i < 4; ++i) {
        #pragma unroll
        for (int j = 0; j < 4; ++j) {
            int gc = cbase + j*8;
            #pragma unroll
            for (int half = 0; half < 2; ++half) {
                long long gr = rbase + i*16 + half*8;
                float v0 = fmaxf(acc[i][j][half*2]     + bias[gc],   0.f);
                float v1 = fmaxf(acc[i][j][half*2 + 1] + bias[gc+1], 0.f);
                split_store(Chi, Clo, gr * ldc + gc, v0, v1);
            }
        }
    }
}

// ---------------- sliding-window conv2: per-node, A reused across 7 taps -----
// Block = one node. M-tile = 128 output rows (122 valid), N = 128 couts.
// chunk c = cg*7 + tap; cg in 0..7 (32-ch groups), tap in 0..6.
// A (h2 rows of node, 32 ch): loaded once per cg, 2-stage ping-pong.
// B (W2t rows, 32 cols at tap*256+cg*32): 4-stage ring. One group/chunk.
#define CV_AROWS 144
#define CV_ASPL (CV_AROWS*ROWB)            // 9216
#define CV_BSPL (128*ROWB)                 // 8192
#define CV_BBASE (4*CV_ASPL)               // 36864
#define CV_SMEM (CV_BBASE + 8*CV_BSPL)     // 102400
#define CV_NC 56

__global__ void __launch_bounds__(256, 2)
k_conv2_sw(const float* __restrict__ g2w_unused)
{
    extern __shared__ char dsm[];
    __shared__ float s_sum[128], s_sq[128];
    uint32_t sb = smem_u32(dsm);
    int tid = threadIdx.x, lane = tid & 31, wid = tid >> 5;
    int n = blockIdx.y;

    // zero A pad rows 128..143 in all 4 A arrays (2 stages x 2 splits)
    {
        int arr = tid >> 6;          // 0..3
        int off = tid & 63;          // 16 rows x 4 segs
        int row = 128 + (off >> 2);
        int seg = off & 3;
        *(uint4*)(dsm + arr*CV_ASPL + row*ROWB + seg*16) = make_uint4(0,0,0,0);
    }

    // per-thread copy geometry (two passes of 64 rows each)
    int crow0 = tid >> 2, seg = tid & 3;
    int crow1 = crow0 + 64;
    uint32_t soA0 = (uint32_t)(crow0*ROWB + (seg ^ ((crow0 >> 1) & 3))*16);
    uint32_t soA1 = (uint32_t)(crow1*ROWB + (seg ^ ((crow1 >> 1) & 3))*16);
    long long hbase = ((long long)n*128) * 256 + seg*8;

    int wm = wid & 1, wn = wid >> 1;
    uint32_t aRowT = (uint32_t)(wm*64 + (lane & 15));     // logical out-row within tile
    uint32_t aSub  = lane >> 4;
    uint32_t bRowB = (uint32_t)(wn*32 + ((lane >> 4) & 1)*8 + (lane & 7)) * ROWB;
    uint32_t bSub  = (lane >> 3) & 1;
    uint32_t xorB  = ((lane & 7) >> 1) & 3;

    float acc[4][4][4] = {};

    // prologue: chunks 0..2 -> B stages 0..2; A[cg=0] with chunk 0's group
    #pragma unroll
    for (int pc = 0; pc < 3; ++pc) {
        if (pc == 0) {
            CP16(sb +            soA0, (const char*)g_h2h + (hbase + (long long)crow0*256)*2);
            CP16(sb +            soA1, (const char*)g_h2h + (hbase + (long long)crow1*256)*2);
            CP16(sb + CV_ASPL +  soA0, (const char*)g_h2l + (hbase + (long long)crow0*256)*2);
            CP16(sb + CV_ASPL +  soA1, (const char*)g_h2l + (hbase + (long long)crow1*256)*2);
        }
        {
            uint32_t bst = sb + CV_BBASE + pc*(2*CV_BSPL);
            long long bcol = (long long)(pc)*256 + seg*8;     // cg=0: tap=pc
            CP16(bst +           soA0, (const char*)g_W2th + ((long long)crow0*1792 + bcol)*2);
            CP16(bst +           soA1, (const char*)g_W2th + ((long long)crow1*1792 + bcol)*2);
            CP16(bst + CV_BSPL + soA0, (const char*)g_W2tl + ((long long)crow0*1792 + bcol)*2);
            CP16(bst + CV_BSPL + soA1, (const char*)g_W2tl + ((long long)crow1*1792 + bcol)*2);
        }
        CP_COMMIT();
    }

    int cg = 0, tap = 0;
    for (int c = 0; c < CV_NC; ++c) {
        CP_WAITG2();
        __syncthreads();

        int cn = c + 3;
        if (cn < CV_NC) {
            int cgn = cn / 7, tapn = cn - cgn*7;
            if (tapn == 0) {
                uint32_t ast = sb + (cgn & 1)*(2*CV_ASPL);
                long long ac = hbase + cgn*32;
                CP16(ast +            soA0, (const char*)g_h2h + (ac + (long long)crow0*256)*2);
                CP16(ast +            soA1, (const char*)g_h2h + (ac + (long long)crow1*256)*2);
                CP16(ast + CV_ASPL +  soA0, (const char*)g_h2l + (ac + (long long)crow0*256)*2);
                CP16(ast + CV_ASPL +  soA1, (const char*)g_h2l + (ac + (long long)crow1*256)*2);
            }
            uint32_t bst = sb + CV_BBASE + (cn & 3)*(2*CV_BSPL);
            long long bcol = (long long)tapn*256 + cgn*32 + seg*8;
            CP16(bst +           soA0, (const char*)g_W2th + ((long long)crow0*1792 + bcol)*2);
            CP16(bst +           soA1, (const char*)g_W2th + ((long long)crow1*1792 + bcol)*2);
            CP16(bst + CV_BSPL + soA0, (const char*)g_W2tl + ((long long)crow0*1792 + bcol)*2);
            CP16(bst + CV_BSPL + soA1, (const char*)g_W2tl + ((long long)crow1*1792 + bcol)*2);
        }
        CP_COMMIT();

        uint32_t ast = sb + (cg & 1)*(2*CV_ASPL);
        uint32_t bst = sb + CV_BBASE + (c & 3)*(2*CV_BSPL);
        uint32_t arow = aRowT + tap;                       // shifted input row
        uint32_t xorA = ((arow >> 1) & 3);                 // i*16 doesn't affect (&3 of >>1)
        uint32_t aBase = arow * ROWB;

        #pragma unroll
        for (int k16 = 0; k16 < 2; ++k16) {
            uint32_t physA = (((uint32_t)k16*2 + aSub) ^ xorA) * 16;
            uint32_t physB = (((uint32_t)k16*2 + bSub) ^ xorB) * 16;
            uint32_t ah[4][4], al[4][4];
            #pragma unroll
            for (int i = 0; i < 4; ++i) {
                uint32_t ro = aBase + i*(16*ROWB) + physA;
                LDSM_X4(ah[i][0], ah[i][1], ah[i][2], ah[i][3], ast + ro);
                LDSM_X4(al[i][0], al[i][1], al[i][2], al[i][3], ast + CV_ASPL + ro);
            }
            #pragma unroll
            for (int jj = 0; jj < 2; ++jj) {
                uint32_t bh2[2][2], bl2[2][2];
                uint32_t ro = bRowB + jj*(16*ROWB) + physB;
                uint32_t t0, t1, t2, t3;
                LDSM_X4(t0, t1, t2, t3, bst + ro);
                bh2[0][0] = t0; bh2[0][1] = t1; bh2[1][0] = t2; bh2[1][1] = t3;
                LDSM_X4(t0, t1, t2, t3, bst + CV_BSPL + ro);
                bl2[0][0] = t0; bl2[0][1] = t1; bl2[1][0] = t2; bl2[1][1] = t3;
                #pragma unroll
                for (int i = 0; i < 4; ++i)
                    #pragma unroll
                    for (int j2 = 0; j2 < 2; ++j2) {
                        MMA16816(acc[i][jj*2+j2], ah[i], bh2[j2]);
                        MMA16816(acc[i][jj*2+j2], ah[i], bl2[j2]);
                        MMA16816(acc[i][jj*2+j2], al[i], bh2[j2]);
                    }
            }
        }
        if (++tap == 7) { tap = 0; ++cg; }
    }

    __syncthreads();
    if (tid < 128) { s_sum[tid] = 0.f; s_sq[tid] = 0.f; }
    __syncthreads();

    float psum[8] = {}, psq[8] = {};
    int rloc = wm*64 + (lane >> 2);
    int cbase = wn*32 + (lane & 3)*2;
    #pragma unroll
    for (int i = 0; i < 4; ++i) {
        #pragma unroll
        for (int j = 0; j < 4; ++j) {
            int gc = cbase + j*8;
            #pragma unroll
            for (int half = 0; half < 2; ++half) {
                int lr = rloc + i*16 + half*8;
                if (lr < 122) {
                    float v0 = acc[i][j][half*2], v1 = acc[i][j][half*2 + 1];
                    long long idx = (long long)(n*122 + lr)*128 + gc;
                    *(float2*)&g_y2[idx] = make_float2(v0, v1);
                    psum[j*2]   += v0;  psq[j*2]   += v0*v0;
                    psum[j*2+1] += v1;  psq[j*2+1] += v1*v1;
                }
            }
        }
    }
    int lc = cbase;
    #pragma unroll
    for (int j = 0; j < 4; ++j) {
        atomicAdd(&s_sum[lc + j*8],     psum[j*2]);
        atomicAdd(&s_sum[lc + j*8 + 1], psum[j*2+1]);
        atomicAdd(&s_sq[lc + j*8],      psq[j*2]);
        atomicAdd(&s_sq[lc + j*8 + 1],  psq[j*2+1]);
    }
    __syncthreads();
    if (tid < 128) {
        atomicAdd(&g_s2[tid],  s_sum[tid]);
        atomicAdd(&g_sq2[tid], s_sq[tid]);
    }
}

// ---------------- pool / BN3 / tail ----------------
__global__ void k_pool(const float* __restrict__ g2w, const float* __restrict__ b2w) {
    int c = threadIdx.x;
    int chunk = blockIdx.x;
    int tp = blockIdx.y;
    int g = blockIdx.z;
    float mu  = g_s2[c]  * (1.f/62464.f);
    float var = g_sq2[c] * (1.f/62464.f) - mu*mu;
    float a = g2w[c] * rsqrtf(var + EPSV);
    float bb = b2w[c] - mu*a;
    float acc = 0.f;
    for (int nl = 0; nl < 16; ++nl) {
        int n = g*64 + chunk*16 + nl;
        const float* p = &g_y2[(n*122 + tp*4)*128 + c];
        float s4 = p[0] + p[128] + p[256] + p[384];
        acc += fmaxf(a * (s4 * 0.25f) + bb, 0.f);
    }
    atomicAdd(&g_gbuf[(g*30 + tp)*128 + c], acc * (1.f/64.f));
}

__global__ void k_bn3stats() {
    __shared__ float red[256];
    int tid = threadIdx.x;
    int c = tid & 127, r0 = tid >> 7;
    float ls = 0.f, lq = 0.f;
    for (int r = r0; r < 224; r += 2) { float v = g_y3[r*128 + c]; ls += v; lq += v*v; }
    red[tid] = ls; __syncthreads();
    float ssum = 0.f;
    if (tid < 128) ssum = red[tid] + red[tid+128];
    __syncthreads();
    red[tid] = lq; __syncthreads();
    if (tid < 128) {
        float q = red[tid] + red[tid+128];
        float mu = ssum * (1.f/224.f);
        float var = q * (1.f/224.f) - mu*mu;
        g_mu3[tid] = mu;
        g_rs3[tid] = rsqrtf(var + EPSV);
    }
}

__global__ void k_tail(const float* __restrict__ g3w, const float* __restrict__ b3w,
                       const float* __restrict__ Wd, const float* __restrict__ bd,
                       float* __restrict__ out) {
    __shared__ float gg[896];
    __shared__ float slog[4];
    int b = blockIdx.x, tid = threadIdx.x;
    int c = tid;
    float a = g3w[c] * g_rs3[c];
    float bb = b3w[c] - g_mu3[c]*a;
    #pragma unroll
    for (int tp = 0; tp < 7; ++tp) {
        const float* p = &g_y3[(b*28 + tp*4)*128 + c];
        float s4 = (p[0] + p[128] + p[256] + p[384]) * 0.25f;
        gg[tp*128 + c] = fmaxf(a*s4 + bb, 0.f);
    }
    __syncthreads();
    int w = tid >> 5, lane = tid & 31;
    float s = 0.f;
    for (int i = lane; i < 896; i += 32) s += gg[i] * Wd[i*4 + w];
    #pragma unroll
    for (int off = 16; off; off >>= 1) s += __shfl_xor_sync(0xffffffffu, s, off);
    if (lane == 0) slog[w] = s + bd[w];
    __syncthreads();
    if (tid == 0) {
        float m = fmaxf(fmaxf(slog[0], slog[1]), fmaxf(slog[2], slog[3]));
        float se = expf(slog[0]-m)+expf(slog[1]-m)+expf(slog[2]-m)+expf(slog[3]-m);
        float lse = logf(se);
        #pragma unroll
        for (int j = 0; j < 4; ++j) out[b*4 + j] = slog[j] - m - lse;
    }
}

// ---------------- launch ----------------
extern "C" void kernel_launch(void* const* d_in, const int* in_sizes, int n_in,
                              void* d_out, int out_size) {
    const float* x   = (const float*)d_in[0];
    const float* pos = (const float*)d_in[1];
    const int*   ei  = (const int*)d_in[2];
    const float* W1  = (const float*)d_in[4];
    const float* g1  = (const float*)d_in[5];
    const float* b1  = (const float*)d_in[6];
    const float* Wp1 = (const float*)d_in[7];
    const float* bp1 = (const float*)d_in[8];
    const float* Wp2 = (const float*)d_in[9];
    const float* bp2 = (const float*)d_in[10];
    const float* Wg1 = (const float*)d_in[11];
    const float* bg1 = (const float*)d_in[12];
    const float* Wg2 = (const float*)d_in[13];
    const float* bg2 = (const float*)d_in[14];
    const float* W2  = (const float*)d_in[15];
    const float* g2  = (const float*)d_in[16];
    const float* b2  = (const float*)d_in[17];
    const float* W3  = (const float*)d_in[18];
    const float* g3  = (const float*)d_in[19];
    const float* b3  = (const float*)d_in[20];
    const float* Wd  = (const float*)d_in[21];
    const float* bd  = (const float*)d_in[22];
    float* out = (float*)d_out;

    float *pGbuf, *pY3;
    __nv_bfloat16 *pH0h, *pH0l, *pA0h, *pA0l, *pH1h, *pH1l, *pA1h, *pA1l, *pH2h, *pH2l;
    __nv_bfloat16 *pWg1h, *pWg1l, *pWg2h, *pWg2l;
    cudaGetSymbolAddress((void**)&pGbuf, g_gbuf);
    cudaGetSymbolAddress((void**)&pY3,   g_y3);
    cudaGetSymbolAddress((void**)&pH0h,  g_h0h);
    cudaGetSymbolAddress((void**)&pH0l,  g_h0l);
    cudaGetSymbolAddress((void**)&pA0h,  g_agg0h);
    cudaGetSymbolAddress((void**)&pA0l,  g_agg0l);
    cudaGetSymbolAddress((void**)&pH1h,  g_h1h);
    cudaGetSymbolAddress((void**)&pH1l,  g_h1l);
    cudaGetSymbolAddress((void**)&pA1h,  g_agg1h);
    cudaGetSymbolAddress((void**)&pA1l,  g_agg1l);
    cudaGetSymbolAddress((void**)&pH2h,  g_h2h);
    cudaGetSymbolAddress((void**)&pH2l,  g_h2l);
    cudaGetSymbolAddress((void**)&pWg1h, g_Wg1th);
    cudaGetSymbolAddress((void**)&pWg1l, g_Wg1tl);
    cudaGetSymbolAddress((void**)&pWg2h, g_Wg2th);
    cudaGetSymbolAddress((void**)&pWg2l, g_Wg2tl);

    const int DSM = NSTAGE*STAGE_BYTES;   // 98304
    cudaFuncSetAttribute(k_gemm_tc, cudaFuncAttributeMaxDynamicSharedMemorySize, DSM);
    cudaFuncSetAttribute(k_agg_tc, cudaFuncAttributeMaxDynamicSharedMemorySize, AGG_SMEM);
    cudaFuncSetAttribute(k_conv2_sw, cudaFuncAttributeMaxDynamicSharedMemorySize, CV_SMEM);

    k_zero<<<128, 256>>>();
    k_deg<<<16, 256>>>(ei);
    k_adj<<<18, 256>>>(ei);
    k_wprep<<<1344, 256>>>(Wg1, Wg2, W2);
    k_pe<<<512, 64>>>(pos, Wp1, bp1, Wp2, bp2);
    k_conv1stats<<<1024, 256>>>(x, W1);
    k_bn1pe<<<1024, 256>>>(x, W1, g1, b1);

    // agg0 = A @ h0  (TC, split out), F = T*C0 = 8192
    k_agg_tc<<<dim3(32, 8), 256, AGG_SMEM>>>(pH0h, pH0l, pA0h, pA0l, 8192);
    // gcn1: h1 = relu(agg0 @ Wg1^T + bg1)
    k_gemm_tc<<<dim3(2, 512), 256, DSM>>>(pA0h, pA0l, pWg1h, pWg1l, bg1,
                                          pH1h, pH1l, 64, 256);
    // agg1 = A @ h1
    k_agg_tc<<<dim3(128, 8), 256, AGG_SMEM>>>(pH1h, pH1l, pA1h, pA1l, 32768);
    // gcn2: h2 = relu(agg1 @ Wg2^T + bg2)
    k_gemm_tc<<<dim3(2, 512), 256, DSM>>>(pA1h, pA1l, pWg2h, pWg2l, bg2,
                                          pH2h, pH2l, 256, 256);
    // conv2 sliding-window (per node) + fused BN2 stats
    k_conv2_sw<<<dim3(1, 512), 256, CV_SMEM>>>(nullptr);
    k_pool<<<dim3(4, 30, 8), 128>>>(g2, b2);
    // conv3 (k=3 VALID, 128->128) SIMT
    k_gemm<<<dim3(2, 4, 1), 256>>>(pGbuf, W3, pY3, 224, 128, 384, 28, 30, 128);
    k_bn3stats<<<1, 256>>>();
    k_tail<<<8, 128>>>(g3, b3, Wd, bd, out);
}

// round 12
// speedup vs baseline: 1.2921x; 1.1548x over previous
#include <cuda_runtime.h>
#include <cuda_bf16.h>
#include <cuda_fp16.h>
#include <math.h>
#include <stdint.h>

#define N_NODES 512
#define TT 128
#define NE 4096
#define C0 64
#define C1 128
#define C2 128
#define EMB 256
#define NG 8
#define EPSV 1e-5f

// ---------------- scratch (device globals; no allocs allowed) ----------------
__device__ float g_y2[N_NODES*122*C1];
__device__ float g_gbuf[NG*30*C1];
__device__ float g_y3[NG*28*C2];
__device__ float g_pe[N_NODES*C0];
__device__ float g_s1[C0], g_sq1[C0];
__device__ float g_s2[C1], g_sq2[C1];
__device__ float g_mu3[C2], g_rs3[C2];

// bf16 split buffers
__device__ __nv_bfloat16 g_Ash[NG*64*64],        g_Asl[NG*64*64];
__device__ __nv_bfloat16 g_h0h[N_NODES*TT*C0],   g_h0l[N_NODES*TT*C0];
__device__ __nv_bfloat16 g_agg0h[N_NODES*TT*C0], g_agg0l[N_NODES*TT*C0];
__device__ __nv_bfloat16 g_h1h[N_NODES*TT*EMB],  g_h1l[N_NODES*TT*EMB];
__device__ __nv_bfloat16 g_agg1h[N_NODES*TT*EMB],g_agg1l[N_NODES*TT*EMB];
__device__ __nv_bfloat16 g_Wg1th[EMB*C0],  g_Wg1tl[EMB*C0];     // [256][64]
__device__ __nv_bfloat16 g_Wg2th[EMB*EMB], g_Wg2tl[EMB*EMB];    // [256][256]

// fp16 buffers for conv2 (2-chain path)
__device__ __half g_h2h[N_NODES*TT*EMB], g_h2l[N_NODES*TT*EMB];
__device__ __half g_W2t[C1*7*EMB];                              // [128][1792]

// ---------------- helpers ----------------
__device__ __forceinline__ uint32_t smem_u32(const void* p) {
    uint32_t a;
    asm("{ .reg .u64 t; cvta.to.shared.u64 t, %1; cvt.u32.u64 %0, t; }" : "=r"(a) : "l"(p));
    return a;
}
#define CP16(dst, src) asm volatile("cp.async.cg.shared.global [%0], [%1], 16;" :: "r"(dst), "l"(src))
#define CP_COMMIT()    asm volatile("cp.async.commit_group;" ::: "memory")
#define CP_WAITG1()    asm volatile("cp.async.wait_group 1;" ::: "memory")
#define CP_WAITG2()    asm volatile("cp.async.wait_group 2;" ::: "memory")
#define CP_WAIT0()     asm volatile("cp.async.wait_group 0;" ::: "memory")
#define LDSM_X4(r0, r1, r2, r3, addr) \
    asm volatile("ldmatrix.sync.aligned.m8n8.x4.shared.b16 {%0,%1,%2,%3}, [%4];" \
        : "=r"(r0), "=r"(r1), "=r"(r2), "=r"(r3) : "r"(addr))
#define LDSM_X4T(r0, r1, r2, r3, addr) \
    asm volatile("ldmatrix.sync.aligned.m8n8.x4.trans.shared.b16 {%0,%1,%2,%3}, [%4];" \
        : "=r"(r0), "=r"(r1), "=r"(r2), "=r"(r3) : "r"(addr))
#define MMA16816(d, a, b) \
    asm volatile("mma.sync.aligned.m16n8k16.row.col.f32.bf16.bf16.f32 " \
        "{%0,%1,%2,%3}, {%4,%5,%6,%7}, {%8,%9}, {%0,%1,%2,%3};" \
        : "+f"((d)[0]), "+f"((d)[1]), "+f"((d)[2]), "+f"((d)[3]) \
        : "r"((a)[0]), "r"((a)[1]), "r"((a)[2]), "r"((a)[3]), "r"((b)[0]), "r"((b)[1]))
#define MMA16816H(d, a, b) \
    asm volatile("mma.sync.aligned.m16n8k16.row.col.f32.f16.f16.f32 " \
        "{%0,%1,%2,%3}, {%4,%5,%6,%7}, {%8,%9}, {%0,%1,%2,%3};" \
        : "+f"((d)[0]), "+f"((d)[1]), "+f"((d)[2]), "+f"((d)[3]) \
        : "r"((a)[0]), "r"((a)[1]), "r"((a)[2]), "r"((a)[3]), "r"((b)[0]), "r"((b)[1]))

__device__ __forceinline__ void split_store(__nv_bfloat16* H, __nv_bfloat16* L,
                                            long long idx, float v0, float v1) {
    __nv_bfloat16 h0 = __float2bfloat16(v0), h1 = __float2bfloat16(v1);
    __nv_bfloat162 hv; hv.x = h0; hv.y = h1;
    __nv_bfloat162 lv;
    lv.x = __float2bfloat16(v0 - __bfloat162float(h0));
    lv.y = __float2bfloat16(v1 - __bfloat162float(h1));
    *(__nv_bfloat162*)&H[idx] = hv;
    *(__nv_bfloat162*)&L[idx] = lv;
}

__device__ __forceinline__ void split_store_h(__half* H, __half* L,
                                              long long idx, float v0, float v1) {
    __half h0 = __float2half(v0), h1 = __float2half(v1);
    __half2 hv; hv.x = h0; hv.y = h1;
    __half2 lv;
    lv.x = __float2half(v0 - __half2float(h0));
    lv.y = __float2half(v1 - __half2float(h1));
    *(__half2*)&H[idx] = hv;
    *(__half2*)&L[idx] = lv;
}

__device__ __forceinline__ void split1(float v, __nv_bfloat16* H, __nv_bfloat16* L, int idx) {
    __nv_bfloat16 h = __float2bfloat16(v);
    H[idx] = h;
    L[idx] = __float2bfloat16(v - __bfloat162float(h));
}

// ---------------- setup kernels ----------------
__global__ void k_zero() {
    int i = blockIdx.x*256 + threadIdx.x;
    if (i < C0) { g_s1[i]=0.f; g_sq1[i]=0.f; }
    if (i < C1) { g_s2[i]=0.f; g_sq2[i]=0.f; }
    if (i < NG*30*C1) g_gbuf[i] = 0.f;
}

// fused per-graph adjacency build + bf16 split (edges are graph-contiguous)
__global__ void k_graph(const int* __restrict__ ei) {
    __shared__ int sdeg[64];
    __shared__ float sA[64*64];
    int g = blockIdx.x, tid = threadIdx.x;
    if (tid < 64) sdeg[tid] = 1;                 // +1 self loop
    for (int i = tid; i < 4096; i += 256) sA[i] = 0.f;
    __syncthreads();
    int e0 = g*512 + tid;
    atomicAdd(&sdeg[ei[NE + e0] & 63], 1);
    atomicAdd(&sdeg[ei[NE + e0 + 256] & 63], 1);
    __syncthreads();
    #pragma unroll
    for (int it = 0; it < 2; ++it) {
        int e = e0 + it*256;
        int s = ei[e] & 63, d = ei[NE + e] & 63;
        float nr = rsqrtf((float)sdeg[s]) * rsqrtf((float)sdeg[d]);
        atomicAdd(&sA[(d << 6) + s], nr);
    }
    __syncthreads();
    if (tid < 64) atomicAdd(&sA[tid*64 + tid], 1.f/(float)sdeg[tid]);
    __syncthreads();
    for (int i = tid; i < 4096; i += 256)
        split1(sA[i], g_Ash, g_Asl, g*4096 + i);
}

// fused weight prep: Wg1t/Wg2t bf16 splits, W2t fp16 single
__global__ void k_wprep(const float* __restrict__ Wg1, const float* __restrict__ Wg2,
                        const float* __restrict__ W2) {
    int i = blockIdx.x*256 + threadIdx.x;
    if (i < 16384) {
        int n = i >> 6, k = i & 63;
        split1(Wg1[k*256 + n], g_Wg1th, g_Wg1tl, i);
    } else if (i < 81920) {
        int j = i - 16384;
        int n = j >> 8, k = j & 255;
        split1(Wg2[k*256 + n], g_Wg2th, g_Wg2tl, j);
    } else if (i < 311296) {
        int j = i - 81920;
        int n = j / 1792, k = j - n*1792;
        g_W2t[j] = __float2half(W2[k*128 + n]);
    }
}

__global__ void k_pe(const float* __restrict__ pos, const float* __restrict__ Wp1,
                     const float* __restrict__ bp1, const float* __restrict__ Wp2,
                     const float* __restrict__ bp2) {
    __shared__ float t1[64];
    int n = blockIdx.x, j = threadIdx.x;
    float p0 = pos[n*3], p1 = pos[n*3+1], p2 = pos[n*3+2];
    t1[j] = fmaxf(p0*Wp1[j] + p1*Wp1[64+j] + p2*Wp1[128+j] + bp1[j], 0.f);
    __syncthreads();
    float s = bp2[j];
    #pragma unroll 8
    for (int k = 0; k < 64; ++k) s += t1[k]*Wp2[k*64 + j];
    g_pe[n*64 + j] = s;
}

__global__ void k_conv1stats(const float* __restrict__ x, const float* __restrict__ W1) {
    __shared__ float sx[70];
    __shared__ float red[256];
    int b = blockIdx.x;
    int n = b >> 1;
    int t0 = (b & 1) * 64;
    int tid = threadIdx.x;
    if (tid < 70) {
        int t = t0 - 3 + tid;
        sx[tid] = (t >= 0 && t < TT) ? x[n*TT + t] : 0.f;
    }
    __syncthreads();
    int c = tid & 63, r0 = tid >> 6;
    float w[7];
    #pragma unroll
    for (int k = 0; k < 7; ++k) w[k] = W1[k*64 + c];
    float ls = 0.f, lq = 0.f;
    for (int rr = r0; rr < 64; rr += 4) {
        float y = 0.f;
        #pragma unroll
        for (int k = 0; k < 7; ++k) y += sx[rr + k] * w[k];
        ls += y; lq += y*y;
    }
    red[tid] = ls; __syncthreads();
    if (tid < 64) atomicAdd(&g_s1[c], red[tid]+red[tid+64]+red[tid+128]+red[tid+192]);
    __syncthreads();
    red[tid] = lq; __syncthreads();
    if (tid < 64) atomicAdd(&g_sq1[c], red[tid]+red[tid+64]+red[tid+128]+red[tid+192]);
}

__global__ void k_bn1pe(const float* __restrict__ x, const float* __restrict__ W1,
                        const float* __restrict__ g1w, const float* __restrict__ b1w) {
    __shared__ float sx[70];
    int b = blockIdx.x;
    int n = b >> 1;
    int t0 = (b & 1) * 64;
    int tid = threadIdx.x;
    if (tid < 70) {
        int t = t0 - 3 + tid;
        sx[tid] = (t >= 0 && t < TT) ? x[n*TT + t] : 0.f;
    }
    __syncthreads();
    int c0 = (tid & 31) * 2;
    int r0 = tid >> 5;
    float w0[7], w1[7];
    #pragma unroll
    for (int k = 0; k < 7; ++k) { w0[k] = W1[k*64 + c0]; w1[k] = W1[k*64 + c0 + 1]; }
    float mu0  = g_s1[c0]   * (1.f/65536.f);
    float var0 = g_sq1[c0]  * (1.f/65536.f) - mu0*mu0;
    float a0 = g1w[c0] * rsqrtf(var0 + EPSV);
    float bb0 = b1w[c0] - mu0*a0;
    float mu1  = g_s1[c0+1]  * (1.f/65536.f);
    float var1 = g_sq1[c0+1] * (1.f/65536.f) - mu1*mu1;
    float a1 = g1w[c0+1] * rsqrtf(var1 + EPSV);
    float bb1 = b1w[c0+1] - mu1*a1;
    float pe0 = g_pe[n*64 + c0], pe1 = g_pe[n*64 + c0 + 1];
    for (int r = r0; r < 64; r += 8) {
        float y0 = 0.f, y1 = 0.f;
        #pragma unroll
        for (int k = 0; k < 7; ++k) { y0 += sx[r+k]*w0[k]; y1 += sx[r+k]*w1[k]; }
        float v0 = fmaxf(a0*y0 + bb0, 0.f) + pe0;
        float v1 = fmaxf(a1*y1 + bb1, 0.f) + pe1;
        split_store(g_h0h, g_h0l, (long long)(b*64 + r)*64 + c0, v0, v1);
    }
}

// ---------------- fp32 SIMT GEMM (conv3 only) ----------------
__global__ void k_gemm(const float* __restrict__ Aall, const float* __restrict__ Ball,
                       float* __restrict__ Call,
                       int M, int N, int K, int Tout, int Tin, int rowC)
{
    const float* A = Aall;
    const float* B = Ball;

    __shared__ __align__(16) float As[16][68];
    __shared__ __align__(16) float Bs[16][68];

    int tid = threadIdx.x;
    int tx = tid & 15, ty = tid >> 4;
    int m0 = blockIdx.y * 64;
    int n0 = blockIdx.x * 64;

    int abase[4]; bool aok[4];
    #pragma unroll
    for (int p = 0; p < 4; ++p) {
        int row = m0 + p*16 + (tid >> 4);
        aok[p] = (row < M);
        abase[p] = aok[p] ? ((row / Tout) * Tin + (row % Tout)) * rowC : 0;
    }
    int akk = tid & 15;

    float acc[4][4] = {};

    for (int k0 = 0; k0 < K; k0 += 16) {
        #pragma unroll
        for (int p = 0; p < 4; ++p) {
            float v = aok[p] ? A[abase[p] + k0 + akk] : 0.f;
            As[akk][p*16 + (tid >> 4)] = v;
        }
        #pragma unroll
        for (int p = 0; p < 4; ++p) {
            int kk = p*4 + (tid >> 6);
            Bs[kk][tid & 63] = B[(k0 + kk) * N + n0 + (tid & 63)];
        }
        __syncthreads();
        #pragma unroll
        for (int kk = 0; kk < 16; ++kk) {
            float4 av = *(const float4*)&As[kk][ty*4];
            float4 bv = *(const float4*)&Bs[kk][tx*4];
            float a_[4] = {av.x, av.y, av.z, av.w};
            float b_[4] = {bv.x, bv.y, bv.z, bv.w};
            #pragma unroll
            for (int i = 0; i < 4; ++i)
                #pragma unroll
                for (int j = 0; j < 4; ++j)
                    acc[i][j] += a_[i] * b_[j];
        }
        __syncthreads();
    }

    #pragma unroll
    for (int i = 0; i < 4; ++i) {
        int row = m0 + ty*4 + i;
        if (row >= M) continue;
        #pragma unroll
        for (int j = 0; j < 4; ++j) {
            int col = n0 + tx*4 + j;
            Call[(long long)row * N + col] = acc[i][j];
        }
    }
}

// ---------------- TC aggregation: O = A(64x64) @ H(64xF) per graph -----------
#define ASTR 72
#define HSTR 264
#define AGG_SMEM (2*64*ASTR*2 + 2*64*HSTR*2)   // 86016

__global__ void __launch_bounds__(256, 2)
k_agg_tc(const __nv_bfloat16* __restrict__ Hh, const __nv_bfloat16* __restrict__ Hl,
         __nv_bfloat16* __restrict__ Oh, __nv_bfloat16* __restrict__ Ol, int F)
{
    extern __shared__ char dsm[];
    uint32_t sAh = smem_u32(dsm);
    uint32_t sAl = sAh + 64*ASTR*2;
    uint32_t sHh = sAl + 64*ASTR*2;
    uint32_t sHl = sHh + 64*HSTR*2;

    int g = blockIdx.y;
    int n0 = blockIdx.x * 256;
    int tid = threadIdx.x, lane = tid & 31, wid = tid >> 5;

    const char* Agh = (const char*)(g_Ash + g*4096);
    const char* Agl = (const char*)(g_Asl + g*4096);
    #pragma unroll
    for (int it = 0; it < 2; ++it) {
        int sid = it*256 + tid;
        int row = sid >> 3, seg = (sid & 7) * 8;
        CP16(sAh + (row*ASTR + seg)*2, Agh + (row*64 + seg)*2);
        CP16(sAl + (row*ASTR + seg)*2, Agl + (row*64 + seg)*2);
    }
    long long hbase = (long long)(g*64) * F + n0;
    #pragma unroll
    for (int it = 0; it < 8; ++it) {
        int sid = it*256 + tid;
        int row = sid >> 5, seg = (sid & 31) * 8;
        long long go = (hbase + (long long)row*F + seg) * 2;
        CP16(sHh + (row*HSTR + seg)*2, (const char*)Hh + go);
        CP16(sHl + (row*HSTR + seg)*2, (const char*)Hl + go);
    }
    CP_COMMIT();
    CP_WAIT0();
    __syncthreads();

    float acc[4][4][4] = {};
    int nw = wid * 32;
    uint32_t arow = lane & 15, ahi = (lane >> 4) * 8;

    #pragma unroll
    for (int kk = 0; kk < 4; ++kk) {
        uint32_t ah[4][4], al[4][4];
        uint32_t acol = kk*16 + ahi;
        #pragma unroll
        for (int i = 0; i < 4; ++i) {
            LDSM_X4(ah[i][0], ah[i][1], ah[i][2], ah[i][3],
                    sAh + ((i*16 + arow)*ASTR + acol)*2);
            LDSM_X4(al[i][0], al[i][1], al[i][2], al[i][3],
                    sAl + ((i*16 + arow)*ASTR + acol)*2);
        }
        uint32_t brow = kk*16 + (lane & 15);
        #pragma unroll
        for (int jp = 0; jp < 2; ++jp) {
            uint32_t bh2[2][2], bl2[2][2];
            uint32_t bcol = nw + jp*16 + ahi;
            uint32_t t0, t1, t2, t3;
            LDSM_X4T(t0, t1, t2, t3, sHh + (brow*HSTR + bcol)*2);
            bh2[0][0] = t0; bh2[0][1] = t1; bh2[1][0] = t2; bh2[1][1] = t3;
            LDSM_X4T(t0, t1, t2, t3, sHl + (brow*HSTR + bcol)*2);
            bl2[0][0] = t0; bl2[0][1] = t1; bl2[1][0] = t2; bl2[1][1] = t3;
            #pragma unroll
            for (int i = 0; i < 4; ++i)
                #pragma unroll
                for (int j2 = 0; j2 < 2; ++j2) {
                    MMA16816(acc[i][jp*2+j2], ah[i], bh2[j2]);
                    MMA16816(acc[i][jp*2+j2], ah[i], bl2[j2]);
                    MMA16816(acc[i][jp*2+j2], al[i], bh2[j2]);
                }
        }
    }

    int rb = lane >> 2;
    int cb = n0 + nw + (lane & 3)*2;
    #pragma unroll
    for (int i = 0; i < 4; ++i)
        #pragma unroll
        for (int j = 0; j < 4; ++j)
            #pragma unroll
            for (int half = 0; half < 2; ++half) {
                int row = i*16 + rb + half*8;
                long long idx = (long long)(g*64 + row) * F + cb + j*8;
                split_store(Oh, Ol, idx, acc[i][j][half*2], acc[i][j][half*2+1]);
            }
}

// ---------------- bf16-split tensor-core GEMM (128x128, 3-stage) --------------
// f16out=0: bf16 split store; f16out=1: fp16 split store (for conv2 input)
#define KC 32
#define ROWB 64
#define ARR_BYTES (128*ROWB)                // 8192
#define STAGE_BYTES (4*ARR_BYTES)           // 32768
#define NSTAGE 3

__global__ void __launch_bounds__(256, 2)
k_gemm_tc(const __nv_bfloat16* __restrict__ Ah, const __nv_bfloat16* __restrict__ Al,
          const __nv_bfloat16* __restrict__ Bh, const __nv_bfloat16* __restrict__ Bl,
          const float* __restrict__ bias,
          void* __restrict__ Chi, void* __restrict__ Clo,
          int K, int ldc, int f16out)
{
    extern __shared__ char dsm[];
    uint32_t sbase = smem_u32(dsm);
    int tid = threadIdx.x, lane = tid & 31, wid = tid >> 5;
    int m0 = blockIdx.y * 128, n0 = blockIdx.x * 128;

    long long gA0, gB0, gA1, gB1;
    uint32_t so0, so1;
    {
        int row = tid >> 2, seg = tid & 3;
        gA0 = (long long)(m0 + row) * K + seg*8;
        gB0 = (long long)(n0 + row) * K + seg*8;
        so0 = (uint32_t)(row*ROWB + (seg ^ ((row >> 1) & 3))*16);
        row += 64;
        gA1 = (long long)(m0 + row) * K + seg*8;
        gB1 = (long long)(n0 + row) * K + seg*8;
        so1 = (uint32_t)(row*ROWB + (seg ^ ((row >> 1) & 3))*16);
    }

    int wm = wid & 1, wn = wid >> 1;
    uint32_t aRowB = (uint32_t)(wm*64 + (lane & 15)) * ROWB;
    uint32_t aSub  = lane >> 4;
    uint32_t xorA  = ((lane & 15) >> 1) & 3;
    uint32_t bRowB = (uint32_t)(wn*32 + ((lane >> 4) & 1)*8 + (lane & 7)) * ROWB;
    uint32_t bSub  = (lane >> 3) & 1;
    uint32_t xorB  = ((lane & 7) >> 1) & 3;

    float acc[4][4][4] = {};

    int nc = K >> 5;
    #pragma unroll
    for (int pc = 0; pc < 2; ++pc) {
        uint32_t st = sbase + pc*STAGE_BYTES;
        long long k0 = (long long)pc*KC;
        CP16(st +              so0, (const char*)Ah + (gA0+k0)*2);
        CP16(st +              so1, (const char*)Ah + (gA1+k0)*2);
        CP16(st + ARR_BYTES  + so0, (const char*)Al + (gA0+k0)*2);
        CP16(st + ARR_BYTES  + so1, (const char*)Al + (gA1+k0)*2);
        CP16(st + 2*ARR_BYTES+ so0, (const char*)Bh + (gB0+k0)*2);
        CP16(st + 2*ARR_BYTES+ so1, (const char*)Bh + (gB1+k0)*2);
        CP16(st + 3*ARR_BYTES+ so0, (const char*)Bl + (gB0+k0)*2);
        CP16(st + 3*ARR_BYTES+ so1, (const char*)Bl + (gB1+k0)*2);
        CP_COMMIT();
    }

    int scur = 0, snext2 = 2;
    for (int c = 0; c < nc; ++c) {
        CP_WAITG1();
        __syncthreads();

        if (c + 2 < nc) {
            uint32_t st = sbase + snext2*STAGE_BYTES;
            long long k0 = (long long)(c+2)*KC;
            CP16(st +              so0, (const char*)Ah + (gA0+k0)*2);
            CP16(st +              so1, (const char*)Ah + (gA1+k0)*2);
            CP16(st + ARR_BYTES  + so0, (const char*)Al + (gA0+k0)*2);
            CP16(st + ARR_BYTES  + so1, (const char*)Al + (gA1+k0)*2);
            CP16(st + 2*ARR_BYTES+ so0, (const char*)Bh + (gB0+k0)*2);
            CP16(st + 2*ARR_BYTES+ so1, (const char*)Bh + (gB1+k0)*2);
            CP16(st + 3*ARR_BYTES+ so0, (const char*)Bl + (gB0+k0)*2);
            CP16(st + 3*ARR_BYTES+ so1, (const char*)Bl + (gB1+k0)*2);
        }
        CP_COMMIT();

        uint32_t st = sbase + scur*STAGE_BYTES;

        #pragma unroll
        for (int k16 = 0; k16 < 2; ++k16) {
            uint32_t physA = (((uint32_t)k16*2 + aSub) ^ xorA) * 16;
            uint32_t physB = (((uint32_t)k16*2 + bSub) ^ xorB) * 16;
            uint32_t ah[4][4], al[4][4];
            #pragma unroll
            for (int i = 0; i < 4; ++i) {
                uint32_t ro = aRowB + i*(16*ROWB) + physA;
                LDSM_X4(ah[i][0], ah[i][1], ah[i][2], ah[i][3], st + ro);
                LDSM_X4(al[i][0], al[i][1], al[i][2], al[i][3], st + ARR_BYTES + ro);
            }
            #pragma unroll
            for (int jj = 0; jj < 2; ++jj) {
                uint32_t bh2[2][2], bl2[2][2];
                uint32_t ro = bRowB + jj*(16*ROWB) + physB;
                uint32_t t0, t1, t2, t3;
                LDSM_X4(t0, t1, t2, t3, st + 2*ARR_BYTES + ro);
                bh2[0][0] = t0; bh2[0][1] = t1; bh2[1][0] = t2; bh2[1][1] = t3;
                LDSM_X4(t0, t1, t2, t3, st + 3*ARR_BYTES + ro);
                bl2[0][0] = t0; bl2[0][1] = t1; bl2[1][0] = t2; bl2[1][1] = t3;
                #pragma unroll
                for (int i = 0; i < 4; ++i)
                    #pragma unroll
                    for (int j2 = 0; j2 < 2; ++j2) {
                        MMA16816(acc[i][jj*2+j2], ah[i], bh2[j2]);
                        MMA16816(acc[i][jj*2+j2], ah[i], bl2[j2]);
                        MMA16816(acc[i][jj*2+j2], al[i], bh2[j2]);
                    }
            }
        }
        scur = (scur == NSTAGE-1) ? 0 : scur+1;
        snext2 = (snext2 == NSTAGE-1) ? 0 : snext2+1;
    }

    int rbase = m0 + wm*64 + (lane >> 2);
    int cbase = n0 + wn*32 + (lane & 3)*2;
    #pragma unroll
    for (int i = 0; i < 4; ++i) {
        #pragma unroll
        for (int j = 0; j < 4; ++j) {
            int gc = cbase + j*8;
            #pragma unroll
            for (int half = 0; half < 2; ++half) {
                long long gr = rbase + i*16 + half*8;
                float v0 = fmaxf(acc[i][j][half*2]     + bias[gc],   0.f);
                float v1 = fmaxf(acc[i][j][half*2 + 1] + bias[gc+1], 0.f);
                long long idx = gr * ldc + gc;
                if (f16out) split_store_h((__half*)Chi, (__half*)Clo, idx, v0, v1);
                else        split_store((__nv_bfloat16*)Chi, (__nv_bfloat16*)Clo, idx, v0, v1);
            }
        }
    }
}

// ---------------- sliding-window conv2 (fp16, 2-chain) -----------------------
// Block = one node. A (h2 fp16 split) reused across 7 taps; B (W2t fp16 single).
#define CV_AROWS 144
#define CV_ASPL (CV_AROWS*ROWB)            // 9216
#define CV_BSPL (128*ROWB)                 // 8192
#define CV_BBASE (4*CV_ASPL)               // 36864
#define CV_SMEM (CV_BBASE + 4*CV_BSPL)     // 69632
#define CV_NC 56

__global__ void __launch_bounds__(256, 2)
k_conv2_sw()
{
    extern __shared__ char dsm[];
    __shared__ float s_sum[128], s_sq[128];
    uint32_t sb = smem_u32(dsm);
    int tid = threadIdx.x, lane = tid & 31, wid = tid >> 5;
    int n = blockIdx.y;

    // zero A pad rows 128..143 in all 4 A arrays (2 stages x 2 splits)
    {
        int arr = tid >> 6;
        int off = tid & 63;
        int row = 128 + (off >> 2);
        int seg = off & 3;
        *(uint4*)(dsm + arr*CV_ASPL + row*ROWB + seg*16) = make_uint4(0,0,0,0);
    }

    int crow0 = tid >> 2, seg = tid & 3;
    int crow1 = crow0 + 64;
    uint32_t soA0 = (uint32_t)(crow0*ROWB + (seg ^ ((crow0 >> 1) & 3))*16);
    uint32_t soA1 = (uint32_t)(crow1*ROWB + (seg ^ ((crow1 >> 1) & 3))*16);
    long long hbase = ((long long)n*128) * 256 + seg*8;

    int wm = wid & 1, wn = wid >> 1;
    uint32_t aRowT = (uint32_t)(wm*64 + (lane & 15));
    uint32_t aSub  = lane >> 4;
    uint32_t bRowB = (uint32_t)(wn*32 + ((lane >> 4) & 1)*8 + (lane & 7)) * ROWB;
    uint32_t bSub  = (lane >> 3) & 1;
    uint32_t xorB  = ((lane & 7) >> 1) & 3;

    float acc[4][4][4] = {};

    #pragma unroll
    for (int pc = 0; pc < 3; ++pc) {
        if (pc == 0) {
            CP16(sb +            soA0, (const char*)g_h2h + (hbase + (long long)crow0*256)*2);
            CP16(sb +            soA1, (const char*)g_h2h + (hbase + (long long)crow1*256)*2);
            CP16(sb + CV_ASPL +  soA0, (const char*)g_h2l + (hbase + (long long)crow0*256)*2);
            CP16(sb + CV_ASPL +  soA1, (const char*)g_h2l + (hbase + (long long)crow1*256)*2);
        }
        {
            uint32_t bst = sb + CV_BBASE + pc*CV_BSPL;
            long long bcol = (long long)pc*256 + seg*8;
            CP16(bst + soA0, (const char*)g_W2t + ((long long)crow0*1792 + bcol)*2);
            CP16(bst + soA1, (const char*)g_W2t + ((long long)crow1*1792 + bcol)*2);
        }
        CP_COMMIT();
    }

    int cg = 0, tap = 0;
    for (int c = 0; c < CV_NC; ++c) {
        CP_WAITG2();
        __syncthreads();

        int cn = c + 3;
        if (cn < CV_NC) {
            int cgn = cn / 7, tapn = cn - cgn*7;
            if (tapn == 0) {
                uint32_t ast = sb + (cgn & 1)*(2*CV_ASPL);
                long long ac = hbase + cgn*32;
                CP16(ast +            soA0, (const char*)g_h2h + (ac + (long long)crow0*256)*2);
                CP16(ast +            soA1, (const char*)g_h2h + (ac + (long long)crow1*256)*2);
                CP16(ast + CV_ASPL +  soA0, (const char*)g_h2l + (ac + (long long)crow0*256)*2);
                CP16(ast + CV_ASPL +  soA1, (const char*)g_h2l + (ac + (long long)crow1*256)*2);
            }
            uint32_t bst = sb + CV_BBASE + (cn & 3)*CV_BSPL;
            long long bcol = (long long)tapn*256 + cgn*32 + seg*8;
            CP16(bst + soA0, (const char*)g_W2t + ((long long)crow0*1792 + bcol)*2);
            CP16(bst + soA1, (const char*)g_W2t + ((long long)crow1*1792 + bcol)*2);
        }
        CP_COMMIT();

        uint32_t ast = sb + (cg & 1)*(2*CV_ASPL);
        uint32_t bst = sb + CV_BBASE + (c & 3)*CV_BSPL;
        uint32_t arow = aRowT + tap;
        uint32_t xorA = ((arow >> 1) & 3);
        uint32_t aBase = arow * ROWB;

        #pragma unroll
        for (int k16 = 0; k16 < 2; ++k16) {
            uint32_t physA = (((uint32_t)k16*2 + aSub) ^ xorA) * 16;
            uint32_t physB = (((uint32_t)k16*2 + bSub) ^ xorB) * 16;
            uint32_t ah[4][4], al[4][4];
            #pragma unroll
            for (int i = 0; i < 4; ++i) {
                uint32_t ro = aBase + i*(16*ROWB) + physA;
                LDSM_X4(ah[i][0], ah[i][1], ah[i][2], ah[i][3], ast + ro);
                LDSM_X4(al[i][0], al[i][1], al[i][2], al[i][3], ast + CV_ASPL + ro);
            }
            #pragma unroll
            for (int jj = 0; jj < 2; ++jj) {
                uint32_t bh2[2][2];
                uint32_t ro = bRowB + jj*(16*ROWB) + physB;
                uint32_t t0, t1, t2, t3;
                LDSM_X4(t0, t1, t2, t3, bst + ro);
                bh2[0][0] = t0; bh2[0][1] = t1; bh2[1][0] = t2; bh2[1][1] = t3;
                #pragma unroll
                for (int i = 0; i < 4; ++i)
                    #pragma unroll
                    for (int j2 = 0; j2 < 2; ++j2) {
                        MMA16816H(acc[i][jj*2+j2], ah[i], bh2[j2]);
                        MMA16816H(acc[i][jj*2+j2], al[i], bh2[j2]);
                    }
            }
        }
        if (++tap == 7) { tap = 0; ++cg; }
    }

    __syncthreads();
    if (tid < 128) { s_sum[tid] = 0.f; s_sq[tid] = 0.f; }
    __syncthreads();

    float psum[8] = {}, psq[8] = {};
    int rloc = wm*64 + (lane >> 2);
    int cbase = wn*32 + (lane & 3)*2;
    #pragma unroll
    for (int i = 0; i < 4; ++i) {
        #pragma unroll
        for (int j = 0; j < 4; ++j) {
            int gc = cbase + j*8;
            #pragma unroll
            for (int half = 0; half < 2; ++half) {
                int lr = rloc + i*16 + half*8;
                if (lr < 122) {
                    float v0 = acc[i][j][half*2], v1 = acc[i][j][half*2 + 1];
                    long long idx = (long long)(n*122 + lr)*128 + gc;
                    *(float2*)&g_y2[idx] = make_float2(v0, v1);
                    psum[j*2]   += v0;  psq[j*2]   += v0*v0;
                    psum[j*2+1] += v1;  psq[j*2+1] += v1*v1;
                }
            }
        }
    }
    #pragma unroll
    for (int j = 0; j < 4; ++j) {
        atomicAdd(&s_sum[cbase + j*8],     psum[j*2]);
        atomicAdd(&s_sum[cbase + j*8 + 1], psum[j*2+1]);
        atomicAdd(&s_sq[cbase + j*8],      psq[j*2]);
        atomicAdd(&s_sq[cbase + j*8 + 1],  psq[j*2+1]);
    }
    __syncthreads();
    if (tid < 128) {
        atomicAdd(&g_s2[tid],  s_sum[tid]);
        atomicAdd(&g_sq2[tid], s_sq[tid]);
    }
}

// ---------------- pool / BN3 / tail ----------------
__global__ void k_pool(const float* __restrict__ g2w, const float* __restrict__ b2w) {
    int c = threadIdx.x;
    int chunk = blockIdx.x;
    int tp = blockIdx.y;
    int g = blockIdx.z;
    float mu  = g_s2[c]  * (1.f/62464.f);
    float var = g_sq2[c] * (1.f/62464.f) - mu*mu;
    float a = g2w[c] * rsqrtf(var + EPSV);
    float bb = b2w[c] - mu*a;
    float acc = 0.f;
    for (int nl = 0; nl < 16; ++nl) {
        int n = g*64 + chunk*16 + nl;
        const float* p = &g_y2[(n*122 + tp*4)*128 + c];
        float s4 = p[0] + p[128] + p[256] + p[384];
        acc += fmaxf(a * (s4 * 0.25f) + bb, 0.f);
    }
    atomicAdd(&g_gbuf[(g*30 + tp)*128 + c], acc * (1.f/64.f));
}

__global__ void k_bn3stats() {
    __shared__ float red[256];
    int tid = threadIdx.x;
    int c = tid & 127, r0 = tid >> 7;
    float ls = 0.f, lq = 0.f;
    for (int r = r0; r < 224; r += 2) { float v = g_y3[r*128 + c]; ls += v; lq += v*v; }
    red[tid] = ls; __syncthreads();
    float ssum = 0.f;
    if (tid < 128) ssum = red[tid] + red[tid+128];
    __syncthreads();
    red[tid] = lq; __syncthreads();
    if (tid < 128) {
        float q = red[tid] + red[tid+128];
        float mu = ssum * (1.f/224.f);
        float var = q * (1.f/224.f) - mu*mu;
        g_mu3[tid] = mu;
        g_rs3[tid] = rsqrtf(var + EPSV);
    }
}

__global__ void k_tail(const float* __restrict__ g3w, const float* __restrict__ b3w,
                       const float* __restrict__ Wd, const float* __restrict__ bd,
                       float* __restrict__ out) {
    __shared__ float gg[896];
    __shared__ float slog[4];
    int b = blockIdx.x, tid = threadIdx.x;
    int c = tid;
    float a = g3w[c] * g_rs3[c];
    float bb = b3w[c] - g_mu3[c]*a;
    #pragma unroll
    for (int tp = 0; tp < 7; ++tp) {
        const float* p = &g_y3[(b*28 + tp*4)*128 + c];
        float s4 = (p[0] + p[128] + p[256] + p[384]) * 0.25f;
        gg[tp*128 + c] = fmaxf(a*s4 + bb, 0.f);
    }
    __syncthreads();
    int w = tid >> 5, lane = tid & 31;
    float s = 0.f;
    for (int i = lane; i < 896; i += 32) s += gg[i] * Wd[i*4 + w];
    #pragma unroll
    for (int off = 16; off; off >>= 1) s += __shfl_xor_sync(0xffffffffu, s, off);
    if (lane == 0) slog[w] = s + bd[w];
    __syncthreads();
    if (tid == 0) {
        float m = fmaxf(fmaxf(slog[0], slog[1]), fmaxf(slog[2], slog[3]));
        float se = expf(slog[0]-m)+expf(slog[1]-m)+expf(slog[2]-m)+expf(slog[3]-m);
        float lse = logf(se);
        #pragma unroll
        for (int j = 0; j < 4; ++j) out[b*4 + j] = slog[j] - m - lse;
    }
}

// ---------------- launch ----------------
extern "C" void kernel_launch(void* const* d_in, const int* in_sizes, int n_in,
                              void* d_out, int out_size) {
    const float* x   = (const float*)d_in[0];
    const float* pos = (const float*)d_in[1];
    const int*   ei  = (const int*)d_in[2];
    const float* W1  = (const float*)d_in[4];
    const float* g1  = (const float*)d_in[5];
    const float* b1  = (const float*)d_in[6];
    const float* Wp1 = (const float*)d_in[7];
    const float* bp1 = (const float*)d_in[8];
    const float* Wp2 = (const float*)d_in[9];
    const float* bp2 = (const float*)d_in[10];
    const float* Wg1 = (const float*)d_in[11];
    const float* bg1 = (const float*)d_in[12];
    const float* Wg2 = (const float*)d_in[13];
    const float* bg2 = (const float*)d_in[14];
    const float* W2  = (const float*)d_in[15];
    const float* g2  = (const float*)d_in[16];
    const float* b2  = (const float*)d_in[17];
    const float* W3  = (const float*)d_in[18];
    const float* g3  = (const float*)d_in[19];
    const float* b3  = (const float*)d_in[20];
    const float* Wd  = (const float*)d_in[21];
    const float* bd  = (const float*)d_in[22];
    float* out = (float*)d_out;

    float *pGbuf, *pY3;
    __nv_bfloat16 *pH0h, *pH0l, *pA0h, *pA0l, *pH1h, *pH1l, *pA1h, *pA1l;
    __nv_bfloat16 *pWg1h, *pWg1l, *pWg2h, *pWg2l;
    __half *pH2h, *pH2l;
    cudaGetSymbolAddress((void**)&pGbuf, g_gbuf);
    cudaGetSymbolAddress((void**)&pY3,   g_y3);
    cudaGetSymbolAddress((void**)&pH0h,  g_h0h);
    cudaGetSymbolAddress((void**)&pH0l,  g_h0l);
    cudaGetSymbolAddress((void**)&pA0h,  g_agg0h);
    cudaGetSymbolAddress((void**)&pA0l,  g_agg0l);
    cudaGetSymbolAddress((void**)&pH1h,  g_h1h);
    cudaGetSymbolAddress((void**)&pH1l,  g_h1l);
    cudaGetSymbolAddress((void**)&pA1h,  g_agg1h);
    cudaGetSymbolAddress((void**)&pA1l,  g_agg1l);
    cudaGetSymbolAddress((void**)&pH2h,  g_h2h);
    cudaGetSymbolAddress((void**)&pH2l,  g_h2l);
    cudaGetSymbolAddress((void**)&pWg1h, g_Wg1th);
    cudaGetSymbolAddress((void**)&pWg1l, g_Wg1tl);
    cudaGetSymbolAddress((void**)&pWg2h, g_Wg2th);
    cudaGetSymbolAddress((void**)&pWg2l, g_Wg2tl);

    const int DSM = NSTAGE*STAGE_BYTES;   // 98304
    cudaFuncSetAttribute(k_gemm_tc, cudaFuncAttributeMaxDynamicSharedMemorySize, DSM);
    cudaFuncSetAttribute(k_agg_tc, cudaFuncAttributeMaxDynamicSharedMemorySize, AGG_SMEM);
    cudaFuncSetAttribute(k_conv2_sw, cudaFuncAttributeMaxDynamicSharedMemorySize, CV_SMEM);

    k_zero<<<120, 256>>>();
    k_graph<<<8, 256>>>(ei);
    k_wprep<<<1216, 256>>>(Wg1, Wg2, W2);
    k_pe<<<512, 64>>>(pos, Wp1, bp1, Wp2, bp2);
    k_conv1stats<<<1024, 256>>>(x, W1);
    k_bn1pe<<<1024, 256>>>(x, W1, g1, b1);

    // agg0 = A @ h0  (TC, split out), F = T*C0 = 8192
    k_agg_tc<<<dim3(32, 8), 256, AGG_SMEM>>>(pH0h, pH0l, pA0h, pA0l, 8192);
    // gcn1: h1 = relu(agg0 @ Wg1^T + bg1) -> bf16 split
    k_gemm_tc<<<dim3(2, 512), 256, DSM>>>(pA0h, pA0l, pWg1h, pWg1l, bg1,
                                          pH1h, pH1l, 64, 256, 0);
    // agg1 = A @ h1
    k_agg_tc<<<dim3(128, 8), 256, AGG_SMEM>>>(pH1h, pH1l, pA1h, pA1l, 32768);
    // gcn2: h2 = relu(agg1 @ Wg2^T + bg2) -> fp16 split (conv2 input)
    k_gemm_tc<<<dim3(2, 512), 256, DSM>>>(pA1h, pA1l, pWg2h, pWg2l, bg2,
                                          pH2h, pH2l, 256, 256, 1);
    // conv2 sliding-window fp16 2-chain + fused BN2 stats
    k_conv2_sw<<<dim3(1, 512), 256, CV_SMEM>>>();
    k_pool<<<dim3(4, 30, 8), 128>>>(g2, b2);
    // conv3 (k=3 VALID, 128->128) SIMT
    k_gemm<<<dim3(2, 4, 1), 256>>>(pGbuf, W3, pY3, 224, 128, 384, 28, 30, 128);
    k_bn3stats<<<1, 256>>>();
    k_tail<<<8, 128>>>(g3, b3, Wd, bd, out);
}

// round 13
// speedup vs baseline: 1.3626x; 1.0546x over previous
#include <cuda_runtime.h>
#include <cuda_bf16.h>
#include <cuda_fp16.h>
#include <math.h>
#include <stdint.h>

#define N_NODES 512
#define TT 128
#define NE 4096
#define C0 64
#define C1 128
#define C2 128
#define EMB 256
#define NG 8
#define EPSV 1e-5f

// ---------------- scratch (device globals; no allocs allowed) ----------------
__device__ float g_y2[N_NODES*122*C1];
__device__ float g_gbuf[NG*30*C1];
__device__ float g_y3[NG*28*C2];
__device__ float g_pe[N_NODES*C0];
__device__ float g_s1[C0], g_sq1[C0];
__device__ float g_s2[C1], g_sq2[C1];
__device__ float g_mu3[C2], g_rs3[C2];

// bf16 buffers (agg0 + gcn1 inputs)
__device__ __nv_bfloat16 g_Ash[NG*64*64],        g_Asl[NG*64*64];
__device__ __nv_bfloat16 g_h0h[N_NODES*TT*C0],   g_h0l[N_NODES*TT*C0];
__device__ __nv_bfloat16 g_agg0h[N_NODES*TT*C0], g_agg0l[N_NODES*TT*C0];
__device__ __nv_bfloat16 g_Wg1th[EMB*C0],  g_Wg1tl[EMB*C0];     // [256][64]

// fp16 buffers (agg1 / gcn2 / conv2 2-chain path)
__device__ __half g_Asf[NG*64*64];                               // adjacency single
__device__ __half g_h1h[N_NODES*TT*EMB],  g_h1l[N_NODES*TT*EMB];
__device__ __half g_agg1h[N_NODES*TT*EMB],g_agg1l[N_NODES*TT*EMB];
__device__ __half g_Wg2tf[EMB*EMB];                              // [256][256] single
__device__ __half g_h2h[N_NODES*TT*EMB], g_h2l[N_NODES*TT*EMB];
__device__ __half g_W2t[C1*7*EMB];                               // [128][1792] single

// ---------------- helpers ----------------
__device__ __forceinline__ uint32_t smem_u32(const void* p) {
    uint32_t a;
    asm("{ .reg .u64 t; cvta.to.shared.u64 t, %1; cvt.u32.u64 %0, t; }" : "=r"(a) : "l"(p));
    return a;
}
#define CP16(dst, src) asm volatile("cp.async.cg.shared.global [%0], [%1], 16;" :: "r"(dst), "l"(src))
#define CP_COMMIT()    asm volatile("cp.async.commit_group;" ::: "memory")
#define CP_WAITG1()    asm volatile("cp.async.wait_group 1;" ::: "memory")
#define CP_WAITG2()    asm volatile("cp.async.wait_group 2;" ::: "memory")
#define CP_WAIT0()     asm volatile("cp.async.wait_group 0;" ::: "memory")
#define LDSM_X4(r0, r1, r2, r3, addr) \
    asm volatile("ldmatrix.sync.aligned.m8n8.x4.shared.b16 {%0,%1,%2,%3}, [%4];" \
        : "=r"(r0), "=r"(r1), "=r"(r2), "=r"(r3) : "r"(addr))
#define LDSM_X4T(r0, r1, r2, r3, addr) \
    asm volatile("ldmatrix.sync.aligned.m8n8.x4.trans.shared.b16 {%0,%1,%2,%3}, [%4];" \
        : "=r"(r0), "=r"(r1), "=r"(r2), "=r"(r3) : "r"(addr))
#define MMA16816(d, a, b) \
    asm volatile("mma.sync.aligned.m16n8k16.row.col.f32.bf16.bf16.f32 " \
        "{%0,%1,%2,%3}, {%4,%5,%6,%7}, {%8,%9}, {%0,%1,%2,%3};" \
        : "+f"((d)[0]), "+f"((d)[1]), "+f"((d)[2]), "+f"((d)[3]) \
        : "r"((a)[0]), "r"((a)[1]), "r"((a)[2]), "r"((a)[3]), "r"((b)[0]), "r"((b)[1]))
#define MMA16816H(d, a, b) \
    asm volatile("mma.sync.aligned.m16n8k16.row.col.f32.f16.f16.f32 " \
        "{%0,%1,%2,%3}, {%4,%5,%6,%7}, {%8,%9}, {%0,%1,%2,%3};" \
        : "+f"((d)[0]), "+f"((d)[1]), "+f"((d)[2]), "+f"((d)[3]) \
        : "r"((a)[0]), "r"((a)[1]), "r"((a)[2]), "r"((a)[3]), "r"((b)[0]), "r"((b)[1]))

__device__ __forceinline__ void split_store(__nv_bfloat16* H, __nv_bfloat16* L,
                                            long long idx, float v0, float v1) {
    __nv_bfloat16 h0 = __float2bfloat16(v0), h1 = __float2bfloat16(v1);
    __nv_bfloat162 hv; hv.x = h0; hv.y = h1;
    __nv_bfloat162 lv;
    lv.x = __float2bfloat16(v0 - __bfloat162float(h0));
    lv.y = __float2bfloat16(v1 - __bfloat162float(h1));
    *(__nv_bfloat162*)&H[idx] = hv;
    *(__nv_bfloat162*)&L[idx] = lv;
}

__device__ __forceinline__ void split_store_h(__half* H, __half* L,
                                              long long idx, float v0, float v1) {
    __half h0 = __float2half(v0), h1 = __float2half(v1);
    __half2 hv; hv.x = h0; hv.y = h1;
    __half2 lv;
    lv.x = __float2half(v0 - __half2float(h0));
    lv.y = __float2half(v1 - __half2float(h1));
    *(__half2*)&H[idx] = hv;
    *(__half2*)&L[idx] = lv;
}

__device__ __forceinline__ void split1(float v, __nv_bfloat16* H, __nv_bfloat16* L, int idx) {
    __nv_bfloat16 h = __float2bfloat16(v);
    H[idx] = h;
    L[idx] = __float2bfloat16(v - __bfloat162float(h));
}

// ---------------- setup kernels ----------------
__global__ void k_zero() {
    int i = blockIdx.x*256 + threadIdx.x;
    if (i < C0) { g_s1[i]=0.f; g_sq1[i]=0.f; }
    if (i < C1) { g_s2[i]=0.f; g_sq2[i]=0.f; }
    if (i < NG*30*C1) g_gbuf[i] = 0.f;
}

// fused per-graph adjacency build: bf16 split + fp16 single
__global__ void k_graph(const int* __restrict__ ei) {
    __shared__ int sdeg[64];
    __shared__ float sA[64*64];
    int g = blockIdx.x, tid = threadIdx.x;
    if (tid < 64) sdeg[tid] = 1;
    for (int i = tid; i < 4096; i += 256) sA[i] = 0.f;
    __syncthreads();
    int e0 = g*512 + tid;
    atomicAdd(&sdeg[ei[NE + e0] & 63], 1);
    atomicAdd(&sdeg[ei[NE + e0 + 256] & 63], 1);
    __syncthreads();
    #pragma unroll
    for (int it = 0; it < 2; ++it) {
        int e = e0 + it*256;
        int s = ei[e] & 63, d = ei[NE + e] & 63;
        float nr = rsqrtf((float)sdeg[s]) * rsqrtf((float)sdeg[d]);
        atomicAdd(&sA[(d << 6) + s], nr);
    }
    __syncthreads();
    if (tid < 64) atomicAdd(&sA[tid*64 + tid], 1.f/(float)sdeg[tid]);
    __syncthreads();
    for (int i = tid; i < 4096; i += 256) {
        split1(sA[i], g_Ash, g_Asl, g*4096 + i);
        g_Asf[g*4096 + i] = __float2half(sA[i]);
    }
}

// weight prep: Wg1t bf16 split, Wg2t fp16 single, W2t fp16 single
__global__ void k_wprep(const float* __restrict__ Wg1, const float* __restrict__ Wg2,
                        const float* __restrict__ W2) {
    int i = blockIdx.x*256 + threadIdx.x;
    if (i < 16384) {
        int n = i >> 6, k = i & 63;
        split1(Wg1[k*256 + n], g_Wg1th, g_Wg1tl, i);
    } else if (i < 81920) {
        int j = i - 16384;
        int n = j >> 8, k = j & 255;
        g_Wg2tf[j] = __float2half(Wg2[k*256 + n]);
    } else if (i < 311296) {
        int j = i - 81920;
        int n = j / 1792, k = j - n*1792;
        g_W2t[j] = __float2half(W2[k*128 + n]);
    }
}

__global__ void k_pe(const float* __restrict__ pos, const float* __restrict__ Wp1,
                     const float* __restrict__ bp1, const float* __restrict__ Wp2,
                     const float* __restrict__ bp2) {
    __shared__ float t1[64];
    int n = blockIdx.x, j = threadIdx.x;
    float p0 = pos[n*3], p1 = pos[n*3+1], p2 = pos[n*3+2];
    t1[j] = fmaxf(p0*Wp1[j] + p1*Wp1[64+j] + p2*Wp1[128+j] + bp1[j], 0.f);
    __syncthreads();
    float s = bp2[j];
    #pragma unroll 8
    for (int k = 0; k < 64; ++k) s += t1[k]*Wp2[k*64 + j];
    g_pe[n*64 + j] = s;
}

__global__ void k_conv1stats(const float* __restrict__ x, const float* __restrict__ W1) {
    __shared__ float sx[70];
    __shared__ float red[256];
    int b = blockIdx.x;
    int n = b >> 1;
    int t0 = (b & 1) * 64;
    int tid = threadIdx.x;
    if (tid < 70) {
        int t = t0 - 3 + tid;
        sx[tid] = (t >= 0 && t < TT) ? x[n*TT + t] : 0.f;
    }
    __syncthreads();
    int c = tid & 63, r0 = tid >> 6;
    float w[7];
    #pragma unroll
    for (int k = 0; k < 7; ++k) w[k] = W1[k*64 + c];
    float ls = 0.f, lq = 0.f;
    for (int rr = r0; rr < 64; rr += 4) {
        float y = 0.f;
        #pragma unroll
        for (int k = 0; k < 7; ++k) y += sx[rr + k] * w[k];
        ls += y; lq += y*y;
    }
    red[tid] = ls; __syncthreads();
    if (tid < 64) atomicAdd(&g_s1[c], red[tid]+red[tid+64]+red[tid+128]+red[tid+192]);
    __syncthreads();
    red[tid] = lq; __syncthreads();
    if (tid < 64) atomicAdd(&g_sq1[c], red[tid]+red[tid+64]+red[tid+128]+red[tid+192]);
}

__global__ void k_bn1pe(const float* __restrict__ x, const float* __restrict__ W1,
                        const float* __restrict__ g1w, const float* __restrict__ b1w) {
    __shared__ float sx[70];
    int b = blockIdx.x;
    int n = b >> 1;
    int t0 = (b & 1) * 64;
    int tid = threadIdx.x;
    if (tid < 70) {
        int t = t0 - 3 + tid;
        sx[tid] = (t >= 0 && t < TT) ? x[n*TT + t] : 0.f;
    }
    __syncthreads();
    int c0 = (tid & 31) * 2;
    int r0 = tid >> 5;
    float w0[7], w1[7];
    #pragma unroll
    for (int k = 0; k < 7; ++k) { w0[k] = W1[k*64 + c0]; w1[k] = W1[k*64 + c0 + 1]; }
    float mu0  = g_s1[c0]   * (1.f/65536.f);
    float var0 = g_sq1[c0]  * (1.f/65536.f) - mu0*mu0;
    float a0 = g1w[c0] * rsqrtf(var0 + EPSV);
    float bb0 = b1w[c0] - mu0*a0;
    float mu1  = g_s1[c0+1]  * (1.f/65536.f);
    float var1 = g_sq1[c0+1] * (1.f/65536.f) - mu1*mu1;
    float a1 = g1w[c0+1] * rsqrtf(var1 + EPSV);
    float bb1 = b1w[c0+1] - mu1*a1;
    float pe0 = g_pe[n*64 + c0], pe1 = g_pe[n*64 + c0 + 1];
    for (int r = r0; r < 64; r += 8) {
        float y0 = 0.f, y1 = 0.f;
        #pragma unroll
        for (int k = 0; k < 7; ++k) { y0 += sx[r+k]*w0[k]; y1 += sx[r+k]*w1[k]; }
        float v0 = fmaxf(a0*y0 + bb0, 0.f) + pe0;
        float v1 = fmaxf(a1*y1 + bb1, 0.f) + pe1;
        split_store(g_h0h, g_h0l, (long long)(b*64 + r)*64 + c0, v0, v1);
    }
}

// ---------------- fp32 SIMT GEMM (conv3 only) ----------------
__global__ void k_gemm(const float* __restrict__ Aall, const float* __restrict__ Ball,
                       float* __restrict__ Call,
                       int M, int N, int K, int Tout, int Tin, int rowC)
{
    const float* A = Aall;
    const float* B = Ball;

    __shared__ __align__(16) float As[16][68];
    __shared__ __align__(16) float Bs[16][68];

    int tid = threadIdx.x;
    int tx = tid & 15, ty = tid >> 4;
    int m0 = blockIdx.y * 64;
    int n0 = blockIdx.x * 64;

    int abase[4]; bool aok[4];
    #pragma unroll
    for (int p = 0; p < 4; ++p) {
        int row = m0 + p*16 + (tid >> 4);
        aok[p] = (row < M);
        abase[p] = aok[p] ? ((row / Tout) * Tin + (row % Tout)) * rowC : 0;
    }
    int akk = tid & 15;

    float acc[4][4] = {};

    for (int k0 = 0; k0 < K; k0 += 16) {
        #pragma unroll
        for (int p = 0; p < 4; ++p) {
            float v = aok[p] ? A[abase[p] + k0 + akk] : 0.f;
            As[akk][p*16 + (tid >> 4)] = v;
        }
        #pragma unroll
        for (int p = 0; p < 4; ++p) {
            int kk = p*4 + (tid >> 6);
            Bs[kk][tid & 63] = B[(k0 + kk) * N + n0 + (tid & 63)];
        }
        __syncthreads();
        #pragma unroll
        for (int kk = 0; kk < 16; ++kk) {
            float4 av = *(const float4*)&As[kk][ty*4];
            float4 bv = *(const float4*)&Bs[kk][tx*4];
            float a_[4] = {av.x, av.y, av.z, av.w};
            float b_[4] = {bv.x, bv.y, bv.z, bv.w};
            #pragma unroll
            for (int i = 0; i < 4; ++i)
                #pragma unroll
                for (int j = 0; j < 4; ++j)
                    acc[i][j] += a_[i] * b_[j];
        }
        __syncthreads();
    }

    #pragma unroll
    for (int i = 0; i < 4; ++i) {
        int row = m0 + ty*4 + i;
        if (row >= M) continue;
        #pragma unroll
        for (int j = 0; j < 4; ++j) {
            int col = n0 + tx*4 + j;
            Call[(long long)row * N + col] = acc[i][j];
        }
    }
}

// ---------------- TC aggregation agg0 (bf16, 3-chain) ------------------------
#define ASTR 72
#define HSTR 264
#define AGG_SMEM (2*64*ASTR*2 + 2*64*HSTR*2)   // 86016

__global__ void __launch_bounds__(256, 2)
k_agg_tc(const __nv_bfloat16* __restrict__ Hh, const __nv_bfloat16* __restrict__ Hl,
         __nv_bfloat16* __restrict__ Oh, __nv_bfloat16* __restrict__ Ol, int F)
{
    extern __shared__ char dsm[];
    uint32_t sAh = smem_u32(dsm);
    uint32_t sAl = sAh + 64*ASTR*2;
    uint32_t sHh = sAl + 64*ASTR*2;
    uint32_t sHl = sHh + 64*HSTR*2;

    int g = blockIdx.y;
    int n0 = blockIdx.x * 256;
    int tid = threadIdx.x, lane = tid & 31, wid = tid >> 5;

    const char* Agh = (const char*)(g_Ash + g*4096);
    const char* Agl = (const char*)(g_Asl + g*4096);
    #pragma unroll
    for (int it = 0; it < 2; ++it) {
        int sid = it*256 + tid;
        int row = sid >> 3, seg = (sid & 7) * 8;
        CP16(sAh + (row*ASTR + seg)*2, Agh + (row*64 + seg)*2);
        CP16(sAl + (row*ASTR + seg)*2, Agl + (row*64 + seg)*2);
    }
    long long hbase = (long long)(g*64) * F + n0;
    #pragma unroll
    for (int it = 0; it < 8; ++it) {
        int sid = it*256 + tid;
        int row = sid >> 5, seg = (sid & 31) * 8;
        long long go = (hbase + (long long)row*F + seg) * 2;
        CP16(sHh + (row*HSTR + seg)*2, (const char*)Hh + go);
        CP16(sHl + (row*HSTR + seg)*2, (const char*)Hl + go);
    }
    CP_COMMIT();
    CP_WAIT0();
    __syncthreads();

    float acc[4][4][4] = {};
    int nw = wid * 32;
    uint32_t arow = lane & 15, ahi = (lane >> 4) * 8;

    #pragma unroll
    for (int kk = 0; kk < 4; ++kk) {
        uint32_t ah[4][4], al[4][4];
        uint32_t acol = kk*16 + ahi;
        #pragma unroll
        for (int i = 0; i < 4; ++i) {
            LDSM_X4(ah[i][0], ah[i][1], ah[i][2], ah[i][3],
                    sAh + ((i*16 + arow)*ASTR + acol)*2);
            LDSM_X4(al[i][0], al[i][1], al[i][2], al[i][3],
                    sAl + ((i*16 + arow)*ASTR + acol)*2);
        }
        uint32_t brow = kk*16 + (lane & 15);
        #pragma unroll
        for (int jp = 0; jp < 2; ++jp) {
            uint32_t bh2[2][2], bl2[2][2];
            uint32_t bcol = nw + jp*16 + ahi;
            uint32_t t0, t1, t2, t3;
            LDSM_X4T(t0, t1, t2, t3, sHh + (brow*HSTR + bcol)*2);
            bh2[0][0] = t0; bh2[0][1] = t1; bh2[1][0] = t2; bh2[1][1] = t3;
            LDSM_X4T(t0, t1, t2, t3, sHl + (brow*HSTR + bcol)*2);
            bl2[0][0] = t0; bl2[0][1] = t1; bl2[1][0] = t2; bl2[1][1] = t3;
            #pragma unroll
            for (int i = 0; i < 4; ++i)
                #pragma unroll
                for (int j2 = 0; j2 < 2; ++j2) {
                    MMA16816(acc[i][jp*2+j2], ah[i], bh2[j2]);
                    MMA16816(acc[i][jp*2+j2], ah[i], bl2[j2]);
                    MMA16816(acc[i][jp*2+j2], al[i], bh2[j2]);
                }
        }
    }

    int rb = lane >> 2;
    int cb = n0 + nw + (lane & 3)*2;
    #pragma unroll
    for (int i = 0; i < 4; ++i)
        #pragma unroll
        for (int j = 0; j < 4; ++j)
            #pragma unroll
            for (int half = 0; half < 2; ++half) {
                int row = i*16 + rb + half*8;
                long long idx = (long long)(g*64 + row) * F + cb + j*8;
                split_store(Oh, Ol, idx, acc[i][j][half*2], acc[i][j][half*2+1]);
            }
}

// ---------------- TC aggregation agg1 (fp16, 2-chain: A single, H split) -----
#define AGGH_SMEM (64*ASTR*2 + 2*64*HSTR*2)    // 76800

__global__ void __launch_bounds__(256, 2)
k_agg_tc_h16(const __half* __restrict__ Hh, const __half* __restrict__ Hl,
             __half* __restrict__ Oh, __half* __restrict__ Ol, int F)
{
    extern __shared__ char dsm[];
    uint32_t sA  = smem_u32(dsm);
    uint32_t sHh = sA + 64*ASTR*2;
    uint32_t sHl = sHh + 64*HSTR*2;

    int g = blockIdx.y;
    int n0 = blockIdx.x * 256;
    int tid = threadIdx.x, lane = tid & 31, wid = tid >> 5;

    const char* Agf = (const char*)(g_Asf + g*4096);
    #pragma unroll
    for (int it = 0; it < 2; ++it) {
        int sid = it*256 + tid;
        int row = sid >> 3, seg = (sid & 7) * 8;
        CP16(sA + (row*ASTR + seg)*2, Agf + (row*64 + seg)*2);
    }
    long long hbase = (long long)(g*64) * F + n0;
    #pragma unroll
    for (int it = 0; it < 8; ++it) {
        int sid = it*256 + tid;
        int row = sid >> 5, seg = (sid & 31) * 8;
        long long go = (hbase + (long long)row*F + seg) * 2;
        CP16(sHh + (row*HSTR + seg)*2, (const char*)Hh + go);
        CP16(sHl + (row*HSTR + seg)*2, (const char*)Hl + go);
    }
    CP_COMMIT();
    CP_WAIT0();
    __syncthreads();

    float acc[4][4][4] = {};
    int nw = wid * 32;
    uint32_t arow = lane & 15, ahi = (lane >> 4) * 8;

    #pragma unroll
    for (int kk = 0; kk < 4; ++kk) {
        uint32_t ah[4][4];
        uint32_t acol = kk*16 + ahi;
        #pragma unroll
        for (int i = 0; i < 4; ++i)
            LDSM_X4(ah[i][0], ah[i][1], ah[i][2], ah[i][3],
                    sA + ((i*16 + arow)*ASTR + acol)*2);
        uint32_t brow = kk*16 + (lane & 15);
        #pragma unroll
        for (int jp = 0; jp < 2; ++jp) {
            uint32_t bh2[2][2], bl2[2][2];
            uint32_t bcol = nw + jp*16 + ahi;
            uint32_t t0, t1, t2, t3;
            LDSM_X4T(t0, t1, t2, t3, sHh + (brow*HSTR + bcol)*2);
            bh2[0][0] = t0; bh2[0][1] = t1; bh2[1][0] = t2; bh2[1][1] = t3;
            LDSM_X4T(t0, t1, t2, t3, sHl + (brow*HSTR + bcol)*2);
            bl2[0][0] = t0; bl2[0][1] = t1; bl2[1][0] = t2; bl2[1][1] = t3;
            #pragma unroll
            for (int i = 0; i < 4; ++i)
                #pragma unroll
                for (int j2 = 0; j2 < 2; ++j2) {
                    MMA16816H(acc[i][jp*2+j2], ah[i], bh2[j2]);
                    MMA16816H(acc[i][jp*2+j2], ah[i], bl2[j2]);
                }
        }
    }

    int rb = lane >> 2;
    int cb = n0 + nw + (lane & 3)*2;
    #pragma unroll
    for (int i = 0; i < 4; ++i)
        #pragma unroll
        for (int j = 0; j < 4; ++j)
            #pragma unroll
            for (int half = 0; half < 2; ++half) {
                int row = i*16 + rb + half*8;
                long long idx = (long long)(g*64 + row) * F + cb + j*8;
                split_store_h(Oh, Ol, idx, acc[i][j][half*2], acc[i][j][half*2+1]);
            }
}

// ---------------- bf16-split GEMM (gcn1: 128x128, 3-stage, fp16 split out) ----
#define KC 32
#define ROWB 64
#define ARR_BYTES (128*ROWB)                // 8192
#define STAGE_BYTES (4*ARR_BYTES)           // 32768
#define NSTAGE 3

__global__ void __launch_bounds__(256, 2)
k_gemm_tc(const __nv_bfloat16* __restrict__ Ah, const __nv_bfloat16* __restrict__ Al,
          const __nv_bfloat16* __restrict__ Bh, const __nv_bfloat16* __restrict__ Bl,
          const float* __restrict__ bias,
          __half* __restrict__ Chi, __half* __restrict__ Clo,
          int K, int ldc)
{
    extern __shared__ char dsm[];
    uint32_t sbase = smem_u32(dsm);
    int tid = threadIdx.x, lane = tid & 31, wid = tid >> 5;
    int m0 = blockIdx.y * 128, n0 = blockIdx.x * 128;

    long long gA0, gB0, gA1, gB1;
    uint32_t so0, so1;
    {
        int row = tid >> 2, seg = tid & 3;
        gA0 = (long long)(m0 + row) * K + seg*8;
        gB0 = (long long)(n0 + row) * K + seg*8;
        so0 = (uint32_t)(row*ROWB + (seg ^ ((row >> 1) & 3))*16);
        row += 64;
        gA1 = (long long)(m0 + row) * K + seg*8;
        gB1 = (long long)(n0 + row) * K + seg*8;
        so1 = (uint32_t)(row*ROWB + (seg ^ ((row >> 1) & 3))*16);
    }

    int wm = wid & 1, wn = wid >> 1;
    uint32_t aRowB = (uint32_t)(wm*64 + (lane & 15)) * ROWB;
    uint32_t aSub  = lane >> 4;
    uint32_t xorA  = ((lane & 15) >> 1) & 3;
    uint32_t bRowB = (uint32_t)(wn*32 + ((lane >> 4) & 1)*8 + (lane & 7)) * ROWB;
    uint32_t bSub  = (lane >> 3) & 1;
    uint32_t xorB  = ((lane & 7) >> 1) & 3;

    float acc[4][4][4] = {};

    int nc = K >> 5;
    #pragma unroll
    for (int pc = 0; pc < 2; ++pc) {
        uint32_t st = sbase + pc*STAGE_BYTES;
        long long k0 = (long long)pc*KC;
        CP16(st +              so0, (const char*)Ah + (gA0+k0)*2);
        CP16(st +              so1, (const char*)Ah + (gA1+k0)*2);
        CP16(st + ARR_BYTES  + so0, (const char*)Al + (gA0+k0)*2);
        CP16(st + ARR_BYTES  + so1, (const char*)Al + (gA1+k0)*2);
        CP16(st + 2*ARR_BYTES+ so0, (const char*)Bh + (gB0+k0)*2);
        CP16(st + 2*ARR_BYTES+ so1, (const char*)Bh + (gB1+k0)*2);
        CP16(st + 3*ARR_BYTES+ so0, (const char*)Bl + (gB0+k0)*2);
        CP16(st + 3*ARR_BYTES+ so1, (const char*)Bl + (gB1+k0)*2);
        CP_COMMIT();
    }

    int scur = 0, snext2 = 2;
    for (int c = 0; c < nc; ++c) {
        CP_WAITG1();
        __syncthreads();

        if (c + 2 < nc) {
            uint32_t st = sbase + snext2*STAGE_BYTES;
            long long k0 = (long long)(c+2)*KC;
            CP16(st +              so0, (const char*)Ah + (gA0+k0)*2);
            CP16(st +              so1, (const char*)Ah + (gA1+k0)*2);
            CP16(st + ARR_BYTES  + so0, (const char*)Al + (gA0+k0)*2);
            CP16(st + ARR_BYTES  + so1, (const char*)Al + (gA1+k0)*2);
            CP16(st + 2*ARR_BYTES+ so0, (const char*)Bh + (gB0+k0)*2);
            CP16(st + 2*ARR_BYTES+ so1, (const char*)Bh + (gB1+k0)*2);
            CP16(st + 3*ARR_BYTES+ so0, (const char*)Bl + (gB0+k0)*2);
            CP16(st + 3*ARR_BYTES+ so1, (const char*)Bl + (gB1+k0)*2);
        }
        CP_COMMIT();

        uint32_t st = sbase + scur*STAGE_BYTES;

        #pragma unroll
        for (int k16 = 0; k16 < 2; ++k16) {
            uint32_t physA = (((uint32_t)k16*2 + aSub) ^ xorA) * 16;
            uint32_t physB = (((uint32_t)k16*2 + bSub) ^ xorB) * 16;
            uint32_t ah[4][4], al[4][4];
            #pragma unroll
            for (int i = 0; i < 4; ++i) {
                uint32_t ro = aRowB + i*(16*ROWB) + physA;
                LDSM_X4(ah[i][0], ah[i][1], ah[i][2], ah[i][3], st + ro);
                LDSM_X4(al[i][0], al[i][1], al[i][2], al[i][3], st + ARR_BYTES + ro);
            }
            #pragma unroll
            for (int jj = 0; jj < 2; ++jj) {
                uint32_t bh2[2][2], bl2[2][2];
                uint32_t ro = bRowB + jj*(16*ROWB) + physB;
                uint32_t t0, t1, t2, t3;
                LDSM_X4(t0, t1, t2, t3, st + 2*ARR_BYTES + ro);
                bh2[0][0] = t0; bh2[0][1] = t1; bh2[1][0] = t2; bh2[1][1] = t3;
                LDSM_X4(t0, t1, t2, t3, st + 3*ARR_BYTES + ro);
                bl2[0][0] = t0; bl2[0][1] = t1; bl2[1][0] = t2; bl2[1][1] = t3;
                #pragma unroll
                for (int i = 0; i < 4; ++i)
                    #pragma unroll
                    for (int j2 = 0; j2 < 2; ++j2) {
                        MMA16816(acc[i][jj*2+j2], ah[i], bh2[j2]);
                        MMA16816(acc[i][jj*2+j2], ah[i], bl2[j2]);
                        MMA16816(acc[i][jj*2+j2], al[i], bh2[j2]);
                    }
            }
        }
        scur = (scur == NSTAGE-1) ? 0 : scur+1;
        snext2 = (snext2 == NSTAGE-1) ? 0 : snext2+1;
    }

    int rbase = m0 + wm*64 + (lane >> 2);
    int cbase = n0 + wn*32 + (lane & 3)*2;
    #pragma unroll
    for (int i = 0; i < 4; ++i) {
        #pragma unroll
        for (int j = 0; j < 4; ++j) {
            int gc = cbase + j*8;
            #pragma unroll
            for (int half = 0; half < 2; ++half) {
                long long gr = rbase + i*16 + half*8;
                float v0 = fmaxf(acc[i][j][half*2]     + bias[gc],   0.f);
                float v1 = fmaxf(acc[i][j][half*2 + 1] + bias[gc+1], 0.f);
                split_store_h(Chi, Clo, gr * ldc + gc, v0, v1);
            }
        }
    }
}

// ---------------- fp16 2-chain GEMM (gcn2: A split fp16, B single fp16) -------
#define STAGE_H (3*ARR_BYTES)               // 24576

__global__ void __launch_bounds__(256, 2)
k_gemm_tc_h16(const __half* __restrict__ Ah, const __half* __restrict__ Al,
              const __half* __restrict__ B, const float* __restrict__ bias,
              __half* __restrict__ Chi, __half* __restrict__ Clo,
              int K, int ldc)
{
    extern __shared__ char dsm[];
    uint32_t sbase = smem_u32(dsm);
    int tid = threadIdx.x, lane = tid & 31, wid = tid >> 5;
    int m0 = blockIdx.y * 128, n0 = blockIdx.x * 128;

    long long gA0, gB0, gA1, gB1;
    uint32_t so0, so1;
    {
        int row = tid >> 2, seg = tid & 3;
        gA0 = (long long)(m0 + row) * K + seg*8;
        gB0 = (long long)(n0 + row) * K + seg*8;
        so0 = (uint32_t)(row*ROWB + (seg ^ ((row >> 1) & 3))*16);
        row += 64;
        gA1 = (long long)(m0 + row) * K + seg*8;
        gB1 = (long long)(n0 + row) * K + seg*8;
        so1 = (uint32_t)(row*ROWB + (seg ^ ((row >> 1) & 3))*16);
    }

    int wm = wid & 1, wn = wid >> 1;
    uint32_t aRowB = (uint32_t)(wm*64 + (lane & 15)) * ROWB;
    uint32_t aSub  = lane >> 4;
    uint32_t xorA  = ((lane & 15) >> 1) & 3;
    uint32_t bRowB = (uint32_t)(wn*32 + ((lane >> 4) & 1)*8 + (lane & 7)) * ROWB;
    uint32_t bSub  = (lane >> 3) & 1;
    uint32_t xorB  = ((lane & 7) >> 1) & 3;

    float acc[4][4][4] = {};

    int nc = K >> 5;
    #pragma unroll
    for (int pc = 0; pc < 2; ++pc) {
        uint32_t st = sbase + pc*STAGE_H;
        long long k0 = (long long)pc*KC;
        CP16(st +              so0, (const char*)Ah + (gA0+k0)*2);
        CP16(st +              so1, (const char*)Ah + (gA1+k0)*2);
        CP16(st + ARR_BYTES  + so0, (const char*)Al + (gA0+k0)*2);
        CP16(st + ARR_BYTES  + so1, (const char*)Al + (gA1+k0)*2);
        CP16(st + 2*ARR_BYTES+ so0, (const char*)B  + (gB0+k0)*2);
        CP16(st + 2*ARR_BYTES+ so1, (const char*)B  + (gB1+k0)*2);
        CP_COMMIT();
    }

    int scur = 0, snext2 = 2;
    for (int c = 0; c < nc; ++c) {
        CP_WAITG1();
        __syncthreads();

        if (c + 2 < nc) {
            uint32_t st = sbase + snext2*STAGE_H;
            long long k0 = (long long)(c+2)*KC;
            CP16(st +              so0, (const char*)Ah + (gA0+k0)*2);
            CP16(st +              so1, (const char*)Ah + (gA1+k0)*2);
            CP16(st + ARR_BYTES  + so0, (const char*)Al + (gA0+k0)*2);
            CP16(st + ARR_BYTES  + so1, (const char*)Al + (gA1+k0)*2);
            CP16(st + 2*ARR_BYTES+ so0, (const char*)B  + (gB0+k0)*2);
            CP16(st + 2*ARR_BYTES+ so1, (const char*)B  + (gB1+k0)*2);
        }
        CP_COMMIT();

        uint32_t st = sbase + scur*STAGE_H;

        #pragma unroll
        for (int k16 = 0; k16 < 2; ++k16) {
            uint32_t physA = (((uint32_t)k16*2 + aSub) ^ xorA) * 16;
            uint32_t physB = (((uint32_t)k16*2 + bSub) ^ xorB) * 16;
            uint32_t ah[4][4], al[4][4];
            #pragma unroll
            for (int i = 0; i < 4; ++i) {
                uint32_t ro = aRowB + i*(16*ROWB) + physA;
                LDSM_X4(ah[i][0], ah[i][1], ah[i][2], ah[i][3], st + ro);
                LDSM_X4(al[i][0], al[i][1], al[i][2], al[i][3], st + ARR_BYTES + ro);
            }
            #pragma unroll
            for (int jj = 0; jj < 2; ++jj) {
                uint32_t bh2[2][2];
                uint32_t ro = bRowB + jj*(16*ROWB) + physB;
                uint32_t t0, t1, t2, t3;
                LDSM_X4(t0, t1, t2, t3, st + 2*ARR_BYTES + ro);
                bh2[0][0] = t0; bh2[0][1] = t1; bh2[1][0] = t2; bh2[1][1] = t3;
                #pragma unroll
                for (int i = 0; i < 4; ++i)
                    #pragma unroll
                    for (int j2 = 0; j2 < 2; ++j2) {
                        MMA16816H(acc[i][jj*2+j2], ah[i], bh2[j2]);
                        MMA16816H(acc[i][jj*2+j2], al[i], bh2[j2]);
                    }
            }
        }
        scur = (scur == NSTAGE-1) ? 0 : scur+1;
        snext2 = (snext2 == NSTAGE-1) ? 0 : snext2+1;
    }

    int rbase = m0 + wm*64 + (lane >> 2);
    int cbase = n0 + wn*32 + (lane & 3)*2;
    #pragma unroll
    for (int i = 0; i < 4; ++i) {
        #pragma unroll
        for (int j = 0; j < 4; ++j) {
            int gc = cbase + j*8;
            #pragma unroll
            for (int half = 0; half < 2; ++half) {
                long long gr = rbase + i*16 + half*8;
                float v0 = fmaxf(acc[i][j][half*2]     + bias[gc],   0.f);
                float v1 = fmaxf(acc[i][j][half*2 + 1] + bias[gc+1], 0.f);
                split_store_h(Chi, Clo, gr * ldc + gc, v0, v1);
            }
        }
    }
}

// ---------------- sliding-window conv2 (fp16, 2-chain) -----------------------
#define CV_AROWS 144
#define CV_ASPL (CV_AROWS*ROWB)            // 9216
#define CV_BSPL (128*ROWB)                 // 8192
#define CV_BBASE (4*CV_ASPL)               // 36864
#define CV_SMEM (CV_BBASE + 4*CV_BSPL)     // 69632
#define CV_NC 56

__global__ void __launch_bounds__(256, 2)
k_conv2_sw()
{
    extern __shared__ char dsm[];
    __shared__ float s_sum[128], s_sq[128];
    uint32_t sb = smem_u32(dsm);
    int tid = threadIdx.x, lane = tid & 31, wid = tid >> 5;
    int n = blockIdx.y;

    {
        int arr = tid >> 6;
        int off = tid & 63;
        int row = 128 + (off >> 2);
        int seg = off & 3;
        *(uint4*)(dsm + arr*CV_ASPL + row*ROWB + seg*16) = make_uint4(0,0,0,0);
    }

    int crow0 = tid >> 2, seg = tid & 3;
    int crow1 = crow0 + 64;
    uint32_t soA0 = (uint32_t)(crow0*ROWB + (seg ^ ((crow0 >> 1) & 3))*16);
    uint32_t soA1 = (uint32_t)(crow1*ROWB + (seg ^ ((crow1 >> 1) & 3))*16);
    long long hbase = ((long long)n*128) * 256 + seg*8;

    int wm = wid & 1, wn = wid >> 1;
    uint32_t aRowT = (uint32_t)(wm*64 + (lane & 15));
    uint32_t aSub  = lane >> 4;
    uint32_t bRowB = (uint32_t)(wn*32 + ((lane >> 4) & 1)*8 + (lane & 7)) * ROWB;
    uint32_t bSub  = (lane >> 3) & 1;
    uint32_t xorB  = ((lane & 7) >> 1) & 3;

    float acc[4][4][4] = {};

    #pragma unroll
    for (int pc = 0; pc < 3; ++pc) {
        if (pc == 0) {
            CP16(sb +            soA0, (const char*)g_h2h + (hbase + (long long)crow0*256)*2);
            CP16(sb +            soA1, (const char*)g_h2h + (hbase + (long long)crow1*256)*2);
            CP16(sb + CV_ASPL +  soA0, (const char*)g_h2l + (hbase + (long long)crow0*256)*2);
            CP16(sb + CV_ASPL +  soA1, (const char*)g_h2l + (hbase + (long long)crow1*256)*2);
        }
        {
            uint32_t bst = sb + CV_BBASE + pc*CV_BSPL;
            long long bcol = (long long)pc*256 + seg*8;
            CP16(bst + soA0, (const char*)g_W2t + ((long long)crow0*1792 + bcol)*2);
            CP16(bst + soA1, (const char*)g_W2t + ((long long)crow1*1792 + bcol)*2);
        }
        CP_COMMIT();
    }

    int cg = 0, tap = 0;
    for (int c = 0; c < CV_NC; ++c) {
        CP_WAITG2();
        __syncthreads();

        int cn = c + 3;
        if (cn < CV_NC) {
            int cgn = cn / 7, tapn = cn - cgn*7;
            if (tapn == 0) {
                uint32_t ast = sb + (cgn & 1)*(2*CV_ASPL);
                long long ac = hbase + cgn*32;
                CP16(ast +            soA0, (const char*)g_h2h + (ac + (long long)crow0*256)*2);
                CP16(ast +            soA1, (const char*)g_h2h + (ac + (long long)crow1*256)*2);
                CP16(ast + CV_ASPL +  soA0, (const char*)g_h2l + (ac + (long long)crow0*256)*2);
                CP16(ast + CV_ASPL +  soA1, (const char*)g_h2l + (ac + (long long)crow1*256)*2);
            }
            uint32_t bst = sb + CV_BBASE + (cn & 3)*CV_BSPL;
            long long bcol = (long long)tapn*256 + cgn*32 + seg*8;
            CP16(bst + soA0, (const char*)g_W2t + ((long long)crow0*1792 + bcol)*2);
            CP16(bst + soA1, (const char*)g_W2t + ((long long)crow1*1792 + bcol)*2);
        }
        CP_COMMIT();

        uint32_t ast = sb + (cg & 1)*(2*CV_ASPL);
        uint32_t bst = sb + CV_BBASE + (c & 3)*CV_BSPL;
        uint32_t arow = aRowT + tap;
        uint32_t xorA = ((arow >> 1) & 3);
        uint32_t aBase = arow * ROWB;

        #pragma unroll
        for (int k16 = 0; k16 < 2; ++k16) {
            uint32_t physA = (((uint32_t)k16*2 + aSub) ^ xorA) * 16;
            uint32_t physB = (((uint32_t)k16*2 + bSub) ^ xorB) * 16;
            uint32_t ah[4][4], al[4][4];
            #pragma unroll
            for (int i = 0; i < 4; ++i) {
                uint32_t ro = aBase + i*(16*ROWB) + physA;
                LDSM_X4(ah[i][0], ah[i][1], ah[i][2], ah[i][3], ast + ro);
                LDSM_X4(al[i][0], al[i][1], al[i][2], al[i][3], ast + CV_ASPL + ro);
            }
            #pragma unroll
            for (int jj = 0; jj < 2; ++jj) {
                uint32_t bh2[2][2];
                uint32_t ro = bRowB + jj*(16*ROWB) + physB;
                uint32_t t0, t1, t2, t3;
                LDSM_X4(t0, t1, t2, t3, bst + ro);
                bh2[0][0] = t0; bh2[0][1] = t1; bh2[1][0] = t2; bh2[1][1] = t3;
                #pragma unroll
                for (int i = 0; i < 4; ++i)
                    #pragma unroll
                    for (int j2 = 0; j2 < 2; ++j2) {
                        MMA16816H(acc[i][jj*2+j2], ah[i], bh2[j2]);
                        MMA16816H(acc[i][jj*2+j2], al[i], bh2[j2]);
                    }
            }
        }
        if (++tap == 7) { tap = 0; ++cg; }
    }

    __syncthreads();
    if (tid < 128) { s_sum[tid] = 0.f; s_sq[tid] = 0.f; }
    __syncthreads();

    float psum[8] = {}, psq[8] = {};
    int rloc = wm*64 + (lane >> 2);
    int cbase = wn*32 + (lane & 3)*2;
    #pragma unroll
    for (int i = 0; i < 4; ++i) {
        #pragma unroll
        for (int j = 0; j < 4; ++j) {
            int gc = cbase + j*8;
            #pragma unroll
            for (int half = 0; half < 2; ++half) {
                int lr = rloc + i*16 + half*8;
                if (lr < 122) {
                    float v0 = acc[i][j][half*2], v1 = acc[i][j][half*2 + 1];
                    long long idx = (long long)(n*122 + lr)*128 + gc;
                    *(float2*)&g_y2[idx] = make_float2(v0, v1);
                    psum[j*2]   += v0;  psq[j*2]   += v0*v0;
                    psum[j*2+1] += v1;  psq[j*2+1] += v1*v1;
                }
            }
        }
    }
    #pragma unroll
    for (int j = 0; j < 4; ++j) {
        atomicAdd(&s_sum[cbase + j*8],     psum[j*2]);
        atomicAdd(&s_sum[cbase + j*8 + 1], psum[j*2+1]);
        atomicAdd(&s_sq[cbase + j*8],      psq[j*2]);
        atomicAdd(&s_sq[cbase + j*8 + 1],  psq[j*2+1]);
    }
    __syncthreads();
    if (tid < 128) {
        atomicAdd(&g_s2[tid],  s_sum[tid]);
        atomicAdd(&g_sq2[tid], s_sq[tid]);
    }
}

// ---------------- pool / BN3 / tail ----------------
__global__ void k_pool(const float* __restrict__ g2w, const float* __restrict__ b2w) {
    int c = threadIdx.x;
    int chunk = blockIdx.x;
    int tp = blockIdx.y;
    int g = blockIdx.z;
    float mu  = g_s2[c]  * (1.f/62464.f);
    float var = g_sq2[c] * (1.f/62464.f) - mu*mu;
    float a = g2w[c] * rsqrtf(var + EPSV);
    float bb = b2w[c] - mu*a;
    float acc = 0.f;
    for (int nl = 0; nl < 16; ++nl) {
        int n = g*64 + chunk*16 + nl;
        const float* p = &g_y2[(n*122 + tp*4)*128 + c];
        float s4 = p[0] + p[128] + p[256] + p[384];
        acc += fmaxf(a * (s4 * 0.25f) + bb, 0.f);
    }
    atomicAdd(&g_gbuf[(g*30 + tp)*128 + c], acc * (1.f/64.f));
}

__global__ void k_bn3stats() {
    __shared__ float red[256];
    int tid = threadIdx.x;
    int c = tid & 127, r0 = tid >> 7;
    float ls = 0.f, lq = 0.f;
    for (int r = r0; r < 224; r += 2) { float v = g_y3[r*128 + c]; ls += v; lq += v*v; }
    red[tid] = ls; __syncthreads();
    float ssum = 0.f;
    if (tid < 128) ssum = red[tid] + red[tid+128];
    __syncthreads();
    red[tid] = lq; __syncthreads();
    if (tid < 128) {
        float q = red[tid] + red[tid+128];
        float mu = ssum * (1.f/224.f);
        float var = q * (1.f/224.f) - mu*mu;
        g_mu3[tid] = mu;
        g_rs3[tid] = rsqrtf(var + EPSV);
    }
}

__global__ void k_tail(const float* __restrict__ g3w, const float* __restrict__ b3w,
                       const float* __restrict__ Wd, const float* __restrict__ bd,
                       float* __restrict__ out) {
    __shared__ float gg[896];
    __shared__ float slog[4];
    int b = blockIdx.x, tid = threadIdx.x;
    int c = tid;
    float a = g3w[c] * g_rs3[c];
    float bb = b3w[c] - g_mu3[c]*a;
    #pragma unroll
    for (int tp = 0; tp < 7; ++tp) {
        const float* p = &g_y3[(b*28 + tp*4)*128 + c];
        float s4 = (p[0] + p[128] + p[256] + p[384]) * 0.25f;
        gg[tp*128 + c] = fmaxf(a*s4 + bb, 0.f);
    }
    __syncthreads();
    int w = tid >> 5, lane = tid & 31;
    float s = 0.f;
    for (int i = lane; i < 896; i += 32) s += gg[i] * Wd[i*4 + w];
    #pragma unroll
    for (int off = 16; off; off >>= 1) s += __shfl_xor_sync(0xffffffffu, s, off);
    if (lane == 0) slog[w] = s + bd[w];
    __syncthreads();
    if (tid == 0) {
        float m = fmaxf(fmaxf(slog[0], slog[1]), fmaxf(slog[2], slog[3]));
        float se = expf(slog[0]-m)+expf(slog[1]-m)+expf(slog[2]-m)+expf(slog[3]-m);
        float lse = logf(se);
        #pragma unroll
        for (int j = 0; j < 4; ++j) out[b*4 + j] = slog[j] - m - lse;
    }
}

// ---------------- launch ----------------
extern "C" void kernel_launch(void* const* d_in, const int* in_sizes, int n_in,
                              void* d_out, int out_size) {
    const float* x   = (const float*)d_in[0];
    const float* pos = (const float*)d_in[1];
    const int*   ei  = (const int*)d_in[2];
    const float* W1  = (const float*)d_in[4];
    const float* g1  = (const float*)d_in[5];
    const float* b1  = (const float*)d_in[6];
    const float* Wp1 = (const float*)d_in[7];
    const float* bp1 = (const float*)d_in[8];
    const float* Wp2 = (const float*)d_in[9];
    const float* bp2 = (const float*)d_in[10];
    const float* Wg1 = (const float*)d_in[11];
    const float* bg1 = (const float*)d_in[12];
    const float* Wg2 = (const float*)d_in[13];
    const float* bg2 = (const float*)d_in[14];
    const float* W2  = (const float*)d_in[15];
    const float* g2  = (const float*)d_in[16];
    const float* b2  = (const float*)d_in[17];
    const float* W3  = (const float*)d_in[18];
    const float* g3  = (const float*)d_in[19];
    const float* b3  = (const float*)d_in[20];
    const float* Wd  = (const float*)d_in[21];
    const float* bd  = (const float*)d_in[22];
    float* out = (float*)d_out;

    float *pGbuf, *pY3;
    __nv_bfloat16 *pH0h, *pH0l, *pA0h, *pA0l, *pWg1h, *pWg1l;
    __half *pH1h, *pH1l, *pA1h, *pA1l, *pH2h, *pH2l, *pWg2f;
    cudaGetSymbolAddress((void**)&pGbuf, g_gbuf);
    cudaGetSymbolAddress((void**)&pY3,   g_y3);
    cudaGetSymbolAddress((void**)&pH0h,  g_h0h);
    cudaGetSymbolAddress((void**)&pH0l,  g_h0l);
    cudaGetSymbolAddress((void**)&pA0h,  g_agg0h);
    cudaGetSymbolAddress((void**)&pA0l,  g_agg0l);
    cudaGetSymbolAddress((void**)&pH1h,  g_h1h);
    cudaGetSymbolAddress((void**)&pH1l,  g_h1l);
    cudaGetSymbolAddress((void**)&pA1h,  g_agg1h);
    cudaGetSymbolAddress((void**)&pA1l,  g_agg1l);
    cudaGetSymbolAddress((void**)&pH2h,  g_h2h);
    cudaGetSymbolAddress((void**)&pH2l,  g_h2l);
    cudaGetSymbolAddress((void**)&pWg1h, g_Wg1th);
    cudaGetSymbolAddress((void**)&pWg1l, g_Wg1tl);
    cudaGetSymbolAddress((void**)&pWg2f, g_Wg2tf);

    const int DSM = NSTAGE*STAGE_BYTES;   // 98304
    cudaFuncSetAttribute(k_gemm_tc, cudaFuncAttributeMaxDynamicSharedMemorySize, DSM);
    cudaFuncSetAttribute(k_gemm_tc_h16, cudaFuncAttributeMaxDynamicSharedMemorySize, NSTAGE*STAGE_H);
    cudaFuncSetAttribute(k_agg_tc, cudaFuncAttributeMaxDynamicSharedMemorySize, AGG_SMEM);
    cudaFuncSetAttribute(k_agg_tc_h16, cudaFuncAttributeMaxDynamicSharedMemorySize, AGGH_SMEM);
    cudaFuncSetAttribute(k_conv2_sw, cudaFuncAttributeMaxDynamicSharedMemorySize, CV_SMEM);

    k_zero<<<120, 256>>>();
    k_graph<<<8, 256>>>(ei);
    k_wprep<<<1216, 256>>>(Wg1, Wg2, W2);
    k_pe<<<512, 64>>>(pos, Wp1, bp1, Wp2, bp2);
    k_conv1stats<<<1024, 256>>>(x, W1);
    k_bn1pe<<<1024, 256>>>(x, W1, g1, b1);

    // agg0 = A @ h0  (bf16 3-chain)
    k_agg_tc<<<dim3(32, 8), 256, AGG_SMEM>>>(pH0h, pH0l, pA0h, pA0l, 8192);
    // gcn1: h1 = relu(agg0 @ Wg1^T + bg1)  (bf16 3-chain -> fp16 split out)
    k_gemm_tc<<<dim3(2, 512), 256, DSM>>>(pA0h, pA0l, pWg1h, pWg1l, bg1,
                                          pH1h, pH1l, 64, 256);
    // agg1 = A @ h1  (fp16 2-chain)
    k_agg_tc_h16<<<dim3(128, 8), 256, AGGH_SMEM>>>(pH1h, pH1l, pA1h, pA1l, 32768);
    // gcn2: h2 = relu(agg1 @ Wg2^T + bg2)  (fp16 2-chain)
    k_gemm_tc_h16<<<dim3(2, 512), 256, NSTAGE*STAGE_H>>>(pA1h, pA1l, pWg2f, bg2,
                                                         pH2h, pH2l, 256, 256);
    // conv2 sliding-window fp16 2-chain + fused BN2 stats
    k_conv2_sw<<<dim3(1, 512), 256, CV_SMEM>>>();
    k_pool<<<dim3(4, 30, 8), 128>>>(g2, b2);
    // conv3 (k=3 VALID, 128->128) SIMT
    k_gemm<<<dim3(2, 4, 1), 256>>>(pGbuf, W3, pY3, 224, 128, 384, 28, 30, 128);
    k_bn3stats<<<1, 256>>>();
    k_tail<<<8, 128>>>(g3, b3, Wd, bd, out);
}

// round 14
// speedup vs baseline: 1.3922x; 1.0218x over previous
#include <cuda_runtime.h>
#include <cuda_fp16.h>
#include <math.h>
#include <stdint.h>

#define N_NODES 512
#define TT 128
#define NE 4096
#define C0 64
#define C1 128
#define C2 128
#define EMB 256
#define NG 8
#define EPSV 1e-5f

// ---------------- scratch (device globals; no allocs allowed) ----------------
__device__ float g_y2[N_NODES*122*C1];
__device__ float g_gbuf[NG*30*C1];
__device__ float g_y3[NG*28*C2];
__device__ float g_pe[N_NODES*C0];
__device__ float g_s1[C0], g_sq1[C0];
__device__ float g_s2[C1], g_sq2[C1];
__device__ float g_mu3[C2], g_rs3[C2];

// fp16 buffers (entire TC pipeline, 2-chain)
__device__ __half g_Asf[NG*64*64];                               // adjacency single
__device__ __half g_h0h[N_NODES*TT*C0],   g_h0l[N_NODES*TT*C0];
__device__ __half g_agg0h[N_NODES*TT*C0], g_agg0l[N_NODES*TT*C0];
__device__ __half g_h1h[N_NODES*TT*EMB],  g_h1l[N_NODES*TT*EMB];
__device__ __half g_agg1h[N_NODES*TT*EMB],g_agg1l[N_NODES*TT*EMB];
__device__ __half g_Wg1tf[EMB*C0];                               // [256][64] single
__device__ __half g_Wg2tf[EMB*EMB];                              // [256][256] single
__device__ __half g_h2h[N_NODES*TT*EMB], g_h2l[N_NODES*TT*EMB];
__device__ __half g_W2t[C1*7*EMB];                               // [128][1792] single

// ---------------- helpers ----------------
__device__ __forceinline__ uint32_t smem_u32(const void* p) {
    uint32_t a;
    asm("{ .reg .u64 t; cvta.to.shared.u64 t, %1; cvt.u32.u64 %0, t; }" : "=r"(a) : "l"(p));
    return a;
}
#define CP16(dst, src) asm volatile("cp.async.cg.shared.global [%0], [%1], 16;" :: "r"(dst), "l"(src))
#define CP_COMMIT()    asm volatile("cp.async.commit_group;" ::: "memory")
#define CP_WAITG1()    asm volatile("cp.async.wait_group 1;" ::: "memory")
#define CP_WAITG2()    asm volatile("cp.async.wait_group 2;" ::: "memory")
#define CP_WAIT0()     asm volatile("cp.async.wait_group 0;" ::: "memory")
#define LDSM_X4(r0, r1, r2, r3, addr) \
    asm volatile("ldmatrix.sync.aligned.m8n8.x4.shared.b16 {%0,%1,%2,%3}, [%4];" \
        : "=r"(r0), "=r"(r1), "=r"(r2), "=r"(r3) : "r"(addr))
#define LDSM_X4T(r0, r1, r2, r3, addr) \
    asm volatile("ldmatrix.sync.aligned.m8n8.x4.trans.shared.b16 {%0,%1,%2,%3}, [%4];" \
        : "=r"(r0), "=r"(r1), "=r"(r2), "=r"(r3) : "r"(addr))
#define MMA16816H(d, a, b) \
    asm volatile("mma.sync.aligned.m16n8k16.row.col.f32.f16.f16.f32 " \
        "{%0,%1,%2,%3}, {%4,%5,%6,%7}, {%8,%9}, {%0,%1,%2,%3};" \
        : "+f"((d)[0]), "+f"((d)[1]), "+f"((d)[2]), "+f"((d)[3]) \
        : "r"((a)[0]), "r"((a)[1]), "r"((a)[2]), "r"((a)[3]), "r"((b)[0]), "r"((b)[1]))

__device__ __forceinline__ void split_store_h(__half* H, __half* L,
                                              long long idx, float v0, float v1) {
    __half h0 = __float2half(v0), h1 = __float2half(v1);
    __half2 hv; hv.x = h0; hv.y = h1;
    __half2 lv;
    lv.x = __float2half(v0 - __half2float(h0));
    lv.y = __float2half(v1 - __half2float(h1));
    *(__half2*)&H[idx] = hv;
    *(__half2*)&L[idx] = lv;
}

// ---------------- setup kernels ----------------
__global__ void k_zero() {
    int i = blockIdx.x*256 + threadIdx.x;
    if (i < C0) { g_s1[i]=0.f; g_sq1[i]=0.f; }
    if (i < C1) { g_s2[i]=0.f; g_sq2[i]=0.f; }
    if (i < NG*30*C1) g_gbuf[i] = 0.f;
}

// fused setup: blocks 0..7 adjacency; 8..135 pe (4 nodes/block); 136..1351 wprep
__global__ void k_setup(const int* __restrict__ ei,
                        const float* __restrict__ pos, const float* __restrict__ Wp1,
                        const float* __restrict__ bp1, const float* __restrict__ Wp2,
                        const float* __restrict__ bp2,
                        const float* __restrict__ Wg1, const float* __restrict__ Wg2,
                        const float* __restrict__ W2) {
    int b = blockIdx.x, tid = threadIdx.x;
    if (b < 8) {
        __shared__ int sdeg[64];
        __shared__ float sA[64*64];
        int g = b;
        if (tid < 64) sdeg[tid] = 1;
        for (int i = tid; i < 4096; i += 256) sA[i] = 0.f;
        __syncthreads();
        int e0 = g*512 + tid;
        atomicAdd(&sdeg[ei[NE + e0] & 63], 1);
        atomicAdd(&sdeg[ei[NE + e0 + 256] & 63], 1);
        __syncthreads();
        #pragma unroll
        for (int it = 0; it < 2; ++it) {
            int e = e0 + it*256;
            int s = ei[e] & 63, d = ei[NE + e] & 63;
            float nr = rsqrtf((float)sdeg[s]) * rsqrtf((float)sdeg[d]);
            atomicAdd(&sA[(d << 6) + s], nr);
        }
        __syncthreads();
        if (tid < 64) atomicAdd(&sA[tid*64 + tid], 1.f/(float)sdeg[tid]);
        __syncthreads();
        for (int i = tid; i < 4096; i += 256)
            g_Asf[g*4096 + i] = __float2half(sA[i]);
    } else if (b < 136) {
        __shared__ float t1[4][64];
        int n = (b - 8)*4 + (tid >> 6);
        int j = tid & 63;
        int sl = tid >> 6;
        float p0 = pos[n*3], p1 = pos[n*3+1], p2 = pos[n*3+2];
        t1[sl][j] = fmaxf(p0*Wp1[j] + p1*Wp1[64+j] + p2*Wp1[128+j] + bp1[j], 0.f);
        __syncthreads();
        float s = bp2[j];
        #pragma unroll 8
        for (int k = 0; k < 64; ++k) s += t1[sl][k]*Wp2[k*64 + j];
        g_pe[n*64 + j] = s;
    } else {
        int i = (b - 136)*256 + tid;
        if (i < 16384) {
            int n = i >> 6, k = i & 63;
            g_Wg1tf[i] = __float2half(Wg1[k*256 + n]);
        } else if (i < 81920) {
            int j = i - 16384;
            int n = j >> 8, k = j & 255;
            g_Wg2tf[j] = __float2half(Wg2[k*256 + n]);
        } else if (i < 311296) {
            int j = i - 81920;
            int n = j / 1792, k = j - n*1792;
            g_W2t[j] = __float2half(W2[k*128 + n]);
        }
    }
}

__global__ void k_conv1stats(const float* __restrict__ x, const float* __restrict__ W1) {
    __shared__ float sx[70];
    __shared__ float red[256];
    int b = blockIdx.x;
    int n = b >> 1;
    int t0 = (b & 1) * 64;
    int tid = threadIdx.x;
    if (tid < 70) {
        int t = t0 - 3 + tid;
        sx[tid] = (t >= 0 && t < TT) ? x[n*TT + t] : 0.f;
    }
    __syncthreads();
    int c = tid & 63, r0 = tid >> 6;
    float w[7];
    #pragma unroll
    for (int k = 0; k < 7; ++k) w[k] = W1[k*64 + c];
    float ls = 0.f, lq = 0.f;
    for (int rr = r0; rr < 64; rr += 4) {
        float y = 0.f;
        #pragma unroll
        for (int k = 0; k < 7; ++k) y += sx[rr + k] * w[k];
        ls += y; lq += y*y;
    }
    red[tid] = ls; __syncthreads();
    if (tid < 64) atomicAdd(&g_s1[c], red[tid]+red[tid+64]+red[tid+128]+red[tid+192]);
    __syncthreads();
    red[tid] = lq; __syncthreads();
    if (tid < 64) atomicAdd(&g_sq1[c], red[tid]+red[tid+64]+red[tid+128]+red[tid+192]);
}

// recompute conv1 + BN1 apply + ReLU + add pe -> h0 fp16 split
__global__ void k_bn1pe(const float* __restrict__ x, const float* __restrict__ W1,
                        const float* __restrict__ g1w, const float* __restrict__ b1w) {
    __shared__ float sx[70];
    int b = blockIdx.x;
    int n = b >> 1;
    int t0 = (b & 1) * 64;
    int tid = threadIdx.x;
    if (tid < 70) {
        int t = t0 - 3 + tid;
        sx[tid] = (t >= 0 && t < TT) ? x[n*TT + t] : 0.f;
    }
    __syncthreads();
    int c0 = (tid & 31) * 2;
    int r0 = tid >> 5;
    float w0[7], w1[7];
    #pragma unroll
    for (int k = 0; k < 7; ++k) { w0[k] = W1[k*64 + c0]; w1[k] = W1[k*64 + c0 + 1]; }
    float mu0  = g_s1[c0]   * (1.f/65536.f);
    float var0 = g_sq1[c0]  * (1.f/65536.f) - mu0*mu0;
    float a0 = g1w[c0] * rsqrtf(var0 + EPSV);
    float bb0 = b1w[c0] - mu0*a0;
    float mu1  = g_s1[c0+1]  * (1.f/65536.f);
    float var1 = g_sq1[c0+1] * (1.f/65536.f) - mu1*mu1;
    float a1 = g1w[c0+1] * rsqrtf(var1 + EPSV);
    float bb1 = b1w[c0+1] - mu1*a1;
    float pe0 = g_pe[n*64 + c0], pe1 = g_pe[n*64 + c0 + 1];
    for (int r = r0; r < 64; r += 8) {
        float y0 = 0.f, y1 = 0.f;
        #pragma unroll
        for (int k = 0; k < 7; ++k) { y0 += sx[r+k]*w0[k]; y1 += sx[r+k]*w1[k]; }
        float v0 = fmaxf(a0*y0 + bb0, 0.f) + pe0;
        float v1 = fmaxf(a1*y1 + bb1, 0.f) + pe1;
        split_store_h(g_h0h, g_h0l, (long long)(b*64 + r)*64 + c0, v0, v1);
    }
}

// ---------------- fp32 SIMT GEMM (conv3 only) ----------------
__global__ void k_gemm(const float* __restrict__ Aall, const float* __restrict__ Ball,
                       float* __restrict__ Call,
                       int M, int N, int K, int Tout, int Tin, int rowC)
{
    const float* A = Aall;
    const float* B = Ball;

    __shared__ __align__(16) float As[16][68];
    __shared__ __align__(16) float Bs[16][68];

    int tid = threadIdx.x;
    int tx = tid & 15, ty = tid >> 4;
    int m0 = blockIdx.y * 64;
    int n0 = blockIdx.x * 64;

    int abase[4]; bool aok[4];
    #pragma unroll
    for (int p = 0; p < 4; ++p) {
        int row = m0 + p*16 + (tid >> 4);
        aok[p] = (row < M);
        abase[p] = aok[p] ? ((row / Tout) * Tin + (row % Tout)) * rowC : 0;
    }
    int akk = tid & 15;

    float acc[4][4] = {};

    for (int k0 = 0; k0 < K; k0 += 16) {
        #pragma unroll
        for (int p = 0; p < 4; ++p) {
            float v = aok[p] ? A[abase[p] + k0 + akk] : 0.f;
            As[akk][p*16 + (tid >> 4)] = v;
        }
        #pragma unroll
        for (int p = 0; p < 4; ++p) {
            int kk = p*4 + (tid >> 6);
            Bs[kk][tid & 63] = B[(k0 + kk) * N + n0 + (tid & 63)];
        }
        __syncthreads();
        #pragma unroll
        for (int kk = 0; kk < 16; ++kk) {
            float4 av = *(const float4*)&As[kk][ty*4];
            float4 bv = *(const float4*)&Bs[kk][tx*4];
            float a_[4] = {av.x, av.y, av.z, av.w};
            float b_[4] = {bv.x, bv.y, bv.z, bv.w};
            #pragma unroll
            for (int i = 0; i < 4; ++i)
                #pragma unroll
                for (int j = 0; j < 4; ++j)
                    acc[i][j] += a_[i] * b_[j];
        }
        __syncthreads();
    }

    #pragma unroll
    for (int i = 0; i < 4; ++i) {
        int row = m0 + ty*4 + i;
        if (row >= M) continue;
        #pragma unroll
        for (int j = 0; j < 4; ++j) {
            int col = n0 + tx*4 + j;
            Call[(long long)row * N + col] = acc[i][j];
        }
    }
}

// ---------------- TC aggregation (fp16, 2-chain: A single, H split) ----------
#define ASTR 72
#define HSTR 264
#define AGGH_SMEM (64*ASTR*2 + 2*64*HSTR*2)    // 76800

__global__ void __launch_bounds__(256, 2)
k_agg_tc_h16(const __half* __restrict__ Hh, const __half* __restrict__ Hl,
             __half* __restrict__ Oh, __half* __restrict__ Ol, int F)
{
    extern __shared__ char dsm[];
    uint32_t sA  = smem_u32(dsm);
    uint32_t sHh = sA + 64*ASTR*2;
    uint32_t sHl = sHh + 64*HSTR*2;

    int g = blockIdx.y;
    int n0 = blockIdx.x * 256;
    int tid = threadIdx.x, lane = tid & 31, wid = tid >> 5;

    const char* Agf = (const char*)(g_Asf + g*4096);
    #pragma unroll
    for (int it = 0; it < 2; ++it) {
        int sid = it*256 + tid;
        int row = sid >> 3, seg = (sid & 7) * 8;
        CP16(sA + (row*ASTR + seg)*2, Agf + (row*64 + seg)*2);
    }
    long long hbase = (long long)(g*64) * F + n0;
    #pragma unroll
    for (int it = 0; it < 8; ++it) {
        int sid = it*256 + tid;
        int row = sid >> 5, seg = (sid & 31) * 8;
        long long go = (hbase + (long long)row*F + seg) * 2;
        CP16(sHh + (row*HSTR + seg)*2, (const char*)Hh + go);
        CP16(sHl + (row*HSTR + seg)*2, (const char*)Hl + go);
    }
    CP_COMMIT();
    CP_WAIT0();
    __syncthreads();

    float acc[4][4][4] = {};
    int nw = wid * 32;
    uint32_t arow = lane & 15, ahi = (lane >> 4) * 8;

    #pragma unroll
    for (int kk = 0; kk < 4; ++kk) {
        uint32_t ah[4][4];
        uint32_t acol = kk*16 + ahi;
        #pragma unroll
        for (int i = 0; i < 4; ++i)
            LDSM_X4(ah[i][0], ah[i][1], ah[i][2], ah[i][3],
                    sA + ((i*16 + arow)*ASTR + acol)*2);
        uint32_t brow = kk*16 + (lane & 15);
        #pragma unroll
        for (int jp = 0; jp < 2; ++jp) {
            uint32_t bh2[2][2], bl2[2][2];
            uint32_t bcol = nw + jp*16 + ahi;
            uint32_t t0, t1, t2, t3;
            LDSM_X4T(t0, t1, t2, t3, sHh + (brow*HSTR + bcol)*2);
            bh2[0][0] = t0; bh2[0][1] = t1; bh2[1][0] = t2; bh2[1][1] = t3;
            LDSM_X4T(t0, t1, t2, t3, sHl + (brow*HSTR + bcol)*2);
            bl2[0][0] = t0; bl2[0][1] = t1; bl2[1][0] = t2; bl2[1][1] = t3;
            #pragma unroll
            for (int i = 0; i < 4; ++i)
                #pragma unroll
                for (int j2 = 0; j2 < 2; ++j2) {
                    MMA16816H(acc[i][jp*2+j2], ah[i], bh2[j2]);
                    MMA16816H(acc[i][jp*2+j2], ah[i], bl2[j2]);
                }
        }
    }

    int rb = lane >> 2;
    int cb = n0 + nw + (lane & 3)*2;
    #pragma unroll
    for (int i = 0; i < 4; ++i)
        #pragma unroll
        for (int j = 0; j < 4; ++j)
            #pragma unroll
            for (int half = 0; half < 2; ++half) {
                int row = i*16 + rb + half*8;
                long long idx = (long long)(g*64 + row) * F + cb + j*8;
                split_store_h(Oh, Ol, idx, acc[i][j][half*2], acc[i][j][half*2+1]);
            }
}

// ---------------- fp16 2-chain GEMM (gcn1/gcn2: A split, B single) ------------
#define KC 32
#define ROWB 64
#define ARR_BYTES (128*ROWB)                // 8192
#define NSTAGE 3
#define STAGE_H (3*ARR_BYTES)               // 24576

__global__ void __launch_bounds__(256, 2)
k_gemm_tc_h16(const __half* __restrict__ Ah, const __half* __restrict__ Al,
              const __half* __restrict__ B, const float* __restrict__ bias,
              __half* __restrict__ Chi, __half* __restrict__ Clo,
              int K, int ldc)
{
    extern __shared__ char dsm[];
    uint32_t sbase = smem_u32(dsm);
    int tid = threadIdx.x, lane = tid & 31, wid = tid >> 5;
    int m0 = blockIdx.y * 128, n0 = blockIdx.x * 128;

    long long gA0, gB0, gA1, gB1;
    uint32_t so0, so1;
    {
        int row = tid >> 2, seg = tid & 3;
        gA0 = (long long)(m0 + row) * K + seg*8;
        gB0 = (long long)(n0 + row) * K + seg*8;
        so0 = (uint32_t)(row*ROWB + (seg ^ ((row >> 1) & 3))*16);
        row += 64;
        gA1 = (long long)(m0 + row) * K + seg*8;
        gB1 = (long long)(n0 + row) * K + seg*8;
        so1 = (uint32_t)(row*ROWB + (seg ^ ((row >> 1) & 3))*16);
    }

    int wm = wid & 1, wn = wid >> 1;
    uint32_t aRowB = (uint32_t)(wm*64 + (lane & 15)) * ROWB;
    uint32_t aSub  = lane >> 4;
    uint32_t xorA  = ((lane & 15) >> 1) & 3;
    uint32_t bRowB = (uint32_t)(wn*32 + ((lane >> 4) & 1)*8 + (lane & 7)) * ROWB;
    uint32_t bSub  = (lane >> 3) & 1;
    uint32_t xorB  = ((lane & 7) >> 1) & 3;

    float acc[4][4][4] = {};

    int nc = K >> 5;
    #pragma unroll
    for (int pc = 0; pc < 2; ++pc) {
        uint32_t st = sbase + pc*STAGE_H;
        long long k0 = (long long)pc*KC;
        CP16(st +              so0, (const char*)Ah + (gA0+k0)*2);
        CP16(st +              so1, (const char*)Ah + (gA1+k0)*2);
        CP16(st + ARR_BYTES  + so0, (const char*)Al + (gA0+k0)*2);
        CP16(st + ARR_BYTES  + so1, (const char*)Al + (gA1+k0)*2);
        CP16(st + 2*ARR_BYTES+ so0, (const char*)B  + (gB0+k0)*2);
        CP16(st + 2*ARR_BYTES+ so1, (const char*)B  + (gB1+k0)*2);
        CP_COMMIT();
    }

    int scur = 0, snext2 = 2;
    for (int c = 0; c < nc; ++c) {
        CP_WAITG1();
        __syncthreads();

        if (c + 2 < nc) {
            uint32_t st = sbase + snext2*STAGE_H;
            long long k0 = (long long)(c+2)*KC;
            CP16(st +              so0, (const char*)Ah + (gA0+k0)*2);
            CP16(st +              so1, (const char*)Ah + (gA1+k0)*2);
            CP16(st + ARR_BYTES  + so0, (const char*)Al + (gA0+k0)*2);
            CP16(st + ARR_BYTES  + so1, (const char*)Al + (gA1+k0)*2);
            CP16(st + 2*ARR_BYTES+ so0, (const char*)B  + (gB0+k0)*2);
            CP16(st + 2*ARR_BYTES+ so1, (const char*)B  + (gB1+k0)*2);
        }
        CP_COMMIT();

        uint32_t st = sbase + scur*STAGE_H;

        #pragma unroll
        for (int k16 = 0; k16 < 2; ++k16) {
            uint32_t physA = (((uint32_t)k16*2 + aSub) ^ xorA) * 16;
            uint32_t physB = (((uint32_t)k16*2 + bSub) ^ xorB) * 16;
            uint32_t ah[4][4], al[4][4];
            #pragma unroll
            for (int i = 0; i < 4; ++i) {
                uint32_t ro = aRowB + i*(16*ROWB) + physA;
                LDSM_X4(ah[i][0], ah[i][1], ah[i][2], ah[i][3], st + ro);
                LDSM_X4(al[i][0], al[i][1], al[i][2], al[i][3], st + ARR_BYTES + ro);
            }
            #pragma unroll
            for (int jj = 0; jj < 2; ++jj) {
                uint32_t bh2[2][2];
                uint32_t ro = bRowB + jj*(16*ROWB) + physB;
                uint32_t t0, t1, t2, t3;
                LDSM_X4(t0, t1, t2, t3, st + 2*ARR_BYTES + ro);
                bh2[0][0] = t0; bh2[0][1] = t1; bh2[1][0] = t2; bh2[1][1] = t3;
                #pragma unroll
                for (int i = 0; i < 4; ++i)
                    #pragma unroll
                    for (int j2 = 0; j2 < 2; ++j2) {
                        MMA16816H(acc[i][jj*2+j2], ah[i], bh2[j2]);
                        MMA16816H(acc[i][jj*2+j2], al[i], bh2[j2]);
                    }
            }
        }
        scur = (scur == NSTAGE-1) ? 0 : scur+1;
        snext2 = (snext2 == NSTAGE-1) ? 0 : snext2+1;
    }

    int rbase = m0 + wm*64 + (lane >> 2);
    int cbase = n0 + wn*32 + (lane & 3)*2;
    #pragma unroll
    for (int i = 0; i < 4; ++i) {
        #pragma unroll
        for (int j = 0; j < 4; ++j) {
            int gc = cbase + j*8;
            #pragma unroll
            for (int half = 0; half < 2; ++half) {
                long long gr = rbase + i*16 + half*8;
                float v0 = fmaxf(acc[i][j][half*2]     + bias[gc],   0.f);
                float v1 = fmaxf(acc[i][j][half*2 + 1] + bias[gc+1], 0.f);
                split_store_h(Chi, Clo, gr * ldc + gc, v0, v1);
            }
        }
    }
}

// ---------------- sliding-window conv2 (fp16, 2-chain) -----------------------
#define CV_AROWS 144
#define CV_ASPL (CV_AROWS*ROWB)            // 9216
#define CV_BSPL (128*ROWB)                 // 8192
#define CV_BBASE (4*CV_ASPL)               // 36864
#define CV_SMEM (CV_BBASE + 4*CV_BSPL)     // 69632
#define CV_NC 56

__global__ void __launch_bounds__(256, 2)
k_conv2_sw()
{
    extern __shared__ char dsm[];
    __shared__ float s_sum[128], s_sq[128];
    uint32_t sb = smem_u32(dsm);
    int tid = threadIdx.x, lane = tid & 31, wid = tid >> 5;
    int n = blockIdx.y;

    {
        int arr = tid >> 6;
        int off = tid & 63;
        int row = 128 + (off >> 2);
        int seg = off & 3;
        *(uint4*)(dsm + arr*CV_ASPL + row*ROWB + seg*16) = make_uint4(0,0,0,0);
    }

    int crow0 = tid >> 2, seg = tid & 3;
    int crow1 = crow0 + 64;
    uint32_t soA0 = (uint32_t)(crow0*ROWB + (seg ^ ((crow0 >> 1) & 3))*16);
    uint32_t soA1 = (uint32_t)(crow1*ROWB + (seg ^ ((crow1 >> 1) & 3))*16);
    long long hbase = ((long long)n*128) * 256 + seg*8;

    int wm = wid & 1, wn = wid >> 1;
    uint32_t aRowT = (uint32_t)(wm*64 + (lane & 15));
    uint32_t aSub  = lane >> 4;
    uint32_t bRowB = (uint32_t)(wn*32 + ((lane >> 4) & 1)*8 + (lane & 7)) * ROWB;
    uint32_t bSub  = (lane >> 3) & 1;
    uint32_t xorB  = ((lane & 7) >> 1) & 3;

    float acc[4][4][4] = {};

    #pragma unroll
    for (int pc = 0; pc < 3; ++pc) {
        if (pc == 0) {
            CP16(sb +            soA0, (const char*)g_h2h + (hbase + (long long)crow0*256)*2);
            CP16(sb +            soA1, (const char*)g_h2h + (hbase + (long long)crow1*256)*2);
            CP16(sb + CV_ASPL +  soA0, (const char*)g_h2l + (hbase + (long long)crow0*256)*2);
            CP16(sb + CV_ASPL +  soA1, (const char*)g_h2l + (hbase + (long long)crow1*256)*2);
        }
        {
            uint32_t bst = sb + CV_BBASE + pc*CV_BSPL;
            long long bcol = (long long)pc*256 + seg*8;
            CP16(bst + soA0, (const char*)g_W2t + ((long long)crow0*1792 + bcol)*2);
            CP16(bst + soA1, (const char*)g_W2t + ((long long)crow1*1792 + bcol)*2);
        }
        CP_COMMIT();
    }

    int cg = 0, tap = 0;
    for (int c = 0; c < CV_NC; ++c) {
        CP_WAITG2();
        __syncthreads();

        int cn = c + 3;
        if (cn < CV_NC) {
            int cgn = cn / 7, tapn = cn - cgn*7;
            if (tapn == 0) {
                uint32_t ast = sb + (cgn & 1)*(2*CV_ASPL);
                long long ac = hbase + cgn*32;
                CP16(ast +            soA0, (const char*)g_h2h + (ac + (long long)crow0*256)*2);
                CP16(ast +            soA1, (const char*)g_h2h + (ac + (long long)crow1*256)*2);
                CP16(ast + CV_ASPL +  soA0, (const char*)g_h2l + (ac + (long long)crow0*256)*2);
                CP16(ast + CV_ASPL +  soA1, (const char*)g_h2l + (ac + (long long)crow1*256)*2);
            }
            uint32_t bst = sb + CV_BBASE + (cn & 3)*CV_BSPL;
            long long bcol = (long long)tapn*256 + cgn*32 + seg*8;
            CP16(bst + soA0, (const char*)g_W2t + ((long long)crow0*1792 + bcol)*2);
            CP16(bst + soA1, (const char*)g_W2t + ((long long)crow1*1792 + bcol)*2);
        }
        CP_COMMIT();

        uint32_t ast = sb + (cg & 1)*(2*CV_ASPL);
        uint32_t bst = sb + CV_BBASE + (c & 3)*CV_BSPL;
        uint32_t arow = aRowT + tap;
        uint32_t xorA = ((arow >> 1) & 3);
        uint32_t aBase = arow * ROWB;

        #pragma unroll
        for (int k16 = 0; k16 < 2; ++k16) {
            uint32_t physA = (((uint32_t)k16*2 + aSub) ^ xorA) * 16;
            uint32_t physB = (((uint32_t)k16*2 + bSub) ^ xorB) * 16;
            uint32_t ah[4][4], al[4][4];
            #pragma unroll
            for (int i = 0; i < 4; ++i) {
                uint32_t ro = aBase + i*(16*ROWB) + physA;
                LDSM_X4(ah[i][0], ah[i][1], ah[i][2], ah[i][3], ast + ro);
                LDSM_X4(al[i][0], al[i][1], al[i][2], al[i][3], ast + CV_ASPL + ro);
            }
            #pragma unroll
            for (int jj = 0; jj < 2; ++jj) {
                uint32_t bh2[2][2];
                uint32_t ro = bRowB + jj*(16*ROWB) + physB;
                uint32_t t0, t1, t2, t3;
                LDSM_X4(t0, t1, t2, t3, bst + ro);
                bh2[0][0] = t0; bh2[0][1] = t1; bh2[1][0] = t2; bh2[1][1] = t3;
                #pragma unroll
                for (int i = 0; i < 4; ++i)
                    #pragma unroll
                    for (int j2 = 0; j2 < 2; ++j2) {
                        MMA16816H(acc[i][jj*2+j2], ah[i], bh2[j2]);
                        MMA16816H(acc[i][jj*2+j2], al[i], bh2[j2]);
                    }
            }
        }
        if (++tap == 7) { tap = 0; ++cg; }
    }

    __syncthreads();
    if (tid < 128) { s_sum[tid] = 0.f; s_sq[tid] = 0.f; }
    __syncthreads();

    float psum[8] = {}, psq[8] = {};
    int rloc = wm*64 + (lane >> 2);
    int cbase = wn*32 + (lane & 3)*2;
    #pragma unroll
    for (int i = 0; i < 4; ++i) {
        #pragma unroll
        for (int j = 0; j < 4; ++j) {
            int gc = cbase + j*8;
            #pragma unroll
            for (int half = 0; half < 2; ++half) {
                int lr = rloc + i*16 + half*8;
                if (lr < 122) {
                    float v0 = acc[i][j][half*2], v1 = acc[i][j][half*2 + 1];
                    long long idx = (long long)(n*122 + lr)*128 + gc;
                    *(float2*)&g_y2[idx] = make_float2(v0, v1);
                    psum[j*2]   += v0;  psq[j*2]   += v0*v0;
                    psum[j*2+1] += v1;  psq[j*2+1] += v1*v1;
                }
            }
        }
    }
    #pragma unroll
    for (int j = 0; j < 4; ++j) {
        atomicAdd(&s_sum[cbase + j*8],     psum[j*2]);
        atomicAdd(&s_sum[cbase + j*8 + 1], psum[j*2+1]);
        atomicAdd(&s_sq[cbase + j*8],      psq[j*2]);
        atomicAdd(&s_sq[cbase + j*8 + 1],  psq[j*2+1]);
    }
    __syncthreads();
    if (tid < 128) {
        atomicAdd(&g_s2[tid],  s_sum[tid]);
        atomicAdd(&g_sq2[tid], s_sq[tid]);
    }
}

// ---------------- pool / BN3 / tail ----------------
__global__ void k_pool(const float* __restrict__ g2w, const float* __restrict__ b2w) {
    int c = threadIdx.x;
    int chunk = blockIdx.x;
    int tp = blockIdx.y;
    int g = blockIdx.z;
    float mu  = g_s2[c]  * (1.f/62464.f);
    float var = g_sq2[c] * (1.f/62464.f) - mu*mu;
    float a = g2w[c] * rsqrtf(var + EPSV);
    float bb = b2w[c] - mu*a;
    float acc = 0.f;
    for (int nl = 0; nl < 16; ++nl) {
        int n = g*64 + chunk*16 + nl;
        const float* p = &g_y2[(n*122 + tp*4)*128 + c];
        float s4 = p[0] + p[128] + p[256] + p[384];
        acc += fmaxf(a * (s4 * 0.25f) + bb, 0.f);
    }
    atomicAdd(&g_gbuf[(g*30 + tp)*128 + c], acc * (1.f/64.f));
}

__global__ void k_bn3stats() {
    __shared__ float red[256];
    int tid = threadIdx.x;
    int c = tid & 127, r0 = tid >> 7;
    float ls = 0.f, lq = 0.f;
    for (int r = r0; r < 224; r += 2) { float v = g_y3[r*128 + c]; ls += v; lq += v*v; }
    red[tid] = ls; __syncthreads();
    float ssum = 0.f;
    if (tid < 128) ssum = red[tid] + red[tid+128];
    __syncthreads();
    red[tid] = lq; __syncthreads();
    if (tid < 128) {
        float q = red[tid] + red[tid+128];
        float mu = ssum * (1.f/224.f);
        float var = q * (1.f/224.f) - mu*mu;
        g_mu3[tid] = mu;
        g_rs3[tid] = rsqrtf(var + EPSV);
    }
}

__global__ void k_tail(const float* __restrict__ g3w, const float* __restrict__ b3w,
                       const float* __restrict__ Wd, const float* __restrict__ bd,
                       float* __restrict__ out) {
    __shared__ float gg[896];
    __shared__ float slog[4];
    int b = blockIdx.x, tid = threadIdx.x;
    int c = tid;
    float a = g3w[c] * g_rs3[c];
    float bb = b3w[c] - g_mu3[c]*a;
    #pragma unroll
    for (int tp = 0; tp < 7; ++tp) {
        const float* p = &g_y3[(b*28 + tp*4)*128 + c];
        float s4 = (p[0] + p[128] + p[256] + p[384]) * 0.25f;
        gg[tp*128 + c] = fmaxf(a*s4 + bb, 0.f);
    }
    __syncthreads();
    int w = tid >> 5, lane = tid & 31;
    float s = 0.f;
    for (int i = lane; i < 896; i += 32) s += gg[i] * Wd[i*4 + w];
    #pragma unroll
    for (int off = 16; off; off >>= 1) s += __shfl_xor_sync(0xffffffffu, s, off);
    if (lane == 0) slog[w] = s + bd[w];
    __syncthreads();
    if (tid == 0) {
        float m = fmaxf(fmaxf(slog[0], slog[1]), fmaxf(slog[2], slog[3]));
        float se = expf(slog[0]-m)+expf(slog[1]-m)+expf(slog[2]-m)+expf(slog[3]-m);
        float lse = logf(se);
        #pragma unroll
        for (int j = 0; j < 4; ++j) out[b*4 + j] = slog[j] - m - lse;
    }
}

// ---------------- launch ----------------
extern "C" void kernel_launch(void* const* d_in, const int* in_sizes, int n_in,
                              void* d_out, int out_size) {
    const float* x   = (const float*)d_in[0];
    const float* pos = (const float*)d_in[1];
    const int*   ei  = (const int*)d_in[2];
    const float* W1  = (const float*)d_in[4];
    const float* g1  = (const float*)d_in[5];
    const float* b1  = (const float*)d_in[6];
    const float* Wp1 = (const float*)d_in[7];
    const float* bp1 = (const float*)d_in[8];
    const float* Wp2 = (const float*)d_in[9];
    const float* bp2 = (const float*)d_in[10];
    const float* Wg1 = (const float*)d_in[11];
    const float* bg1 = (const float*)d_in[12];
    const float* Wg2 = (const float*)d_in[13];
    const float* bg2 = (const float*)d_in[14];
    const float* W2  = (const float*)d_in[15];
    const float* g2  = (const float*)d_in[16];
    const float* b2  = (const float*)d_in[17];
    const float* W3  = (const float*)d_in[18];
    const float* g3  = (const float*)d_in[19];
    const float* b3  = (const float*)d_in[20];
    const float* Wd  = (const float*)d_in[21];
    const float* bd  = (const float*)d_in[22];
    float* out = (float*)d_out;

    float *pGbuf, *pY3;
    __half *pH0h, *pH0l, *pA0h, *pA0l, *pH1h, *pH1l, *pA1h, *pA1l, *pH2h, *pH2l;
    __half *pWg1f, *pWg2f;
    cudaGetSymbolAddress((void**)&pGbuf, g_gbuf);
    cudaGetSymbolAddress((void**)&pY3,   g_y3);
    cudaGetSymbolAddress((void**)&pH0h,  g_h0h);
    cudaGetSymbolAddress((void**)&pH0l,  g_h0l);
    cudaGetSymbolAddress((void**)&pA0h,  g_agg0h);
    cudaGetSymbolAddress((void**)&pA0l,  g_agg0l);
    cudaGetSymbolAddress((void**)&pH1h,  g_h1h);
    cudaGetSymbolAddress((void**)&pH1l,  g_h1l);
    cudaGetSymbolAddress((void**)&pA1h,  g_agg1h);
    cudaGetSymbolAddress((void**)&pA1l,  g_agg1l);
    cudaGetSymbolAddress((void**)&pH2h,  g_h2h);
    cudaGetSymbolAddress((void**)&pH2l,  g_h2l);
    cudaGetSymbolAddress((void**)&pWg1f, g_Wg1tf);
    cudaGetSymbolAddress((void**)&pWg2f, g_Wg2tf);

    cudaFuncSetAttribute(k_gemm_tc_h16, cudaFuncAttributeMaxDynamicSharedMemorySize, NSTAGE*STAGE_H);
    cudaFuncSetAttribute(k_agg_tc_h16, cudaFuncAttributeMaxDynamicSharedMemorySize, AGGH_SMEM);
    cudaFuncSetAttribute(k_conv2_sw, cudaFuncAttributeMaxDynamicSharedMemorySize, CV_SMEM);

    k_zero<<<120, 256>>>();
    k_setup<<<1352, 256>>>(ei, pos, Wp1, bp1, Wp2, bp2, Wg1, Wg2, W2);
    k_conv1stats<<<1024, 256>>>(x, W1);
    k_bn1pe<<<1024, 256>>>(x, W1, g1, b1);

    // agg0 = A @ h0  (fp16 2-chain), F = T*C0 = 8192
    k_agg_tc_h16<<<dim3(32, 8), 256, AGGH_SMEM>>>(pH0h, pH0l, pA0h, pA0l, 8192);
    // gcn1: h1 = relu(agg0 @ Wg1^T + bg1)  (fp16 2-chain)
    k_gemm_tc_h16<<<dim3(2, 512), 256, NSTAGE*STAGE_H>>>(pA0h, pA0l, pWg1f, bg1,
                                                         pH1h, pH1l, 64, 256);
    // agg1 = A @ h1  (fp16 2-chain), F = T*EMB = 32768
    k_agg_tc_h16<<<dim3(128, 8), 256, AGGH_SMEM>>>(pH1h, pH1l, pA1h, pA1l, 32768);
    // gcn2: h2 = relu(agg1 @ Wg2^T + bg2)  (fp16 2-chain)
    k_gemm_tc_h16<<<dim3(2, 512), 256, NSTAGE*STAGE_H>>>(pA1h, pA1l, pWg2f, bg2,
                                                         pH2h, pH2l, 256, 256);
    // conv2 sliding-window fp16 2-chain + fused BN2 stats
    k_conv2_sw<<<dim3(1, 512), 256, CV_SMEM>>>();
    k_pool<<<dim3(4, 30, 8), 128>>>(g2, b2);
    // conv3 (k=3 VALID, 128->128) SIMT
    k_gemm<<<dim3(2, 4, 1), 256>>>(pGbuf, W3, pY3, 224, 128, 384, 28, 30, 128);
    k_bn3stats<<<1, 256>>>();
    k_tail<<<8, 128>>>(g3, b3, Wd, bd, out);
}

// round 15
// speedup vs baseline: 2.0527x; 1.4744x over previous
#include <cuda_runtime.h>
#include <cuda_fp16.h>
#include <math.h>
#include <stdint.h>

#define N_NODES 512
#define TT 128
#define NE 4096
#define C0 64
#define C1 128
#define C2 128
#define EMB 256
#define NG 8
#define EPSV 1e-5f

// ---------------- scratch (device globals; no allocs allowed) ----------------
__device__ float g_y2[N_NODES*122*C1];
__device__ float g_gbuf[NG*30*C1];
__device__ float g_y3[NG*28*C2];
__device__ float g_pe[N_NODES*C0];
__device__ float g_s1[C0], g_sq1[C0];
__device__ float g_s2[C1], g_sq2[C1];
__device__ float g_mu3[C2], g_rs3[C2];

// fp16 single buffers (entire TC pipeline, 1-chain)
__device__ __half g_Asf[NG*64*64];
__device__ __half g_h0[N_NODES*TT*C0];
__device__ __half g_agg0[N_NODES*TT*C0];
__device__ __half g_h1[N_NODES*TT*EMB];
__device__ __half g_agg1[N_NODES*TT*EMB];
__device__ __half g_Wg1tf[EMB*C0];       // [256][64]
__device__ __half g_Wg2tf[EMB*EMB];      // [256][256]
__device__ __half g_h2[N_NODES*TT*EMB];
__device__ __half g_W2t[C1*7*EMB];       // [128][1792]

// ---------------- helpers ----------------
__device__ __forceinline__ uint32_t smem_u32(const void* p) {
    uint32_t a;
    asm("{ .reg .u64 t; cvta.to.shared.u64 t, %1; cvt.u32.u64 %0, t; }" : "=r"(a) : "l"(p));
    return a;
}
#define CP16(dst, src) asm volatile("cp.async.cg.shared.global [%0], [%1], 16;" :: "r"(dst), "l"(src))
#define CP_COMMIT()    asm volatile("cp.async.commit_group;" ::: "memory")
#define CP_WAITG1()    asm volatile("cp.async.wait_group 1;" ::: "memory")
#define CP_WAITG2()    asm volatile("cp.async.wait_group 2;" ::: "memory")
#define CP_WAIT0()     asm volatile("cp.async.wait_group 0;" ::: "memory")
#define LDSM_X4(r0, r1, r2, r3, addr) \
    asm volatile("ldmatrix.sync.aligned.m8n8.x4.shared.b16 {%0,%1,%2,%3}, [%4];" \
        : "=r"(r0), "=r"(r1), "=r"(r2), "=r"(r3) : "r"(addr))
#define LDSM_X4T(r0, r1, r2, r3, addr) \
    asm volatile("ldmatrix.sync.aligned.m8n8.x4.trans.shared.b16 {%0,%1,%2,%3}, [%4];" \
        : "=r"(r0), "=r"(r1), "=r"(r2), "=r"(r3) : "r"(addr))
#define MMA16816H(d, a, b) \
    asm volatile("mma.sync.aligned.m16n8k16.row.col.f32.f16.f16.f32 " \
        "{%0,%1,%2,%3}, {%4,%5,%6,%7}, {%8,%9}, {%0,%1,%2,%3};" \
        : "+f"((d)[0]), "+f"((d)[1]), "+f"((d)[2]), "+f"((d)[3]) \
        : "r"((a)[0]), "r"((a)[1]), "r"((a)[2]), "r"((a)[3]), "r"((b)[0]), "r"((b)[1]))

__device__ __forceinline__ void store_h2v(__half* H, long long idx, float v0, float v1) {
    __half2 hv; hv.x = __float2half(v0); hv.y = __float2half(v1);
    *(__half2*)&H[idx] = hv;
}

// ---------------- setup kernels ----------------
__global__ void k_zero() {
    int i = blockIdx.x*256 + threadIdx.x;
    if (i < C0) { g_s1[i]=0.f; g_sq1[i]=0.f; }
    if (i < C1) { g_s2[i]=0.f; g_sq2[i]=0.f; }
    if (i < NG*30*C1) g_gbuf[i] = 0.f;
}

// fused setup: blocks 0..7 adjacency; 8..135 pe (4 nodes/block); 136..1351 wprep
__global__ void k_setup(const int* __restrict__ ei,
                        const float* __restrict__ pos, const float* __restrict__ Wp1,
                        const float* __restrict__ bp1, const float* __restrict__ Wp2,
                        const float* __restrict__ bp2,
                        const float* __restrict__ Wg1, const float* __restrict__ Wg2,
                        const float* __restrict__ W2) {
    int b = blockIdx.x, tid = threadIdx.x;
    if (b < 8) {
        __shared__ int sdeg[64];
        __shared__ float sA[64*64];
        int g = b;
        if (tid < 64) sdeg[tid] = 1;
        for (int i = tid; i < 4096; i += 256) sA[i] = 0.f;
        __syncthreads();
        int e0 = g*512 + tid;
        atomicAdd(&sdeg[ei[NE + e0] & 63], 1);
        atomicAdd(&sdeg[ei[NE + e0 + 256] & 63], 1);
        __syncthreads();
        #pragma unroll
        for (int it = 0; it < 2; ++it) {
            int e = e0 + it*256;
            int s = ei[e] & 63, d = ei[NE + e] & 63;
            float nr = rsqrtf((float)sdeg[s]) * rsqrtf((float)sdeg[d]);
            atomicAdd(&sA[(d << 6) + s], nr);
        }
        __syncthreads();
        if (tid < 64) atomicAdd(&sA[tid*64 + tid], 1.f/(float)sdeg[tid]);
        __syncthreads();
        for (int i = tid; i < 4096; i += 256)
            g_Asf[g*4096 + i] = __float2half(sA[i]);
    } else if (b < 136) {
        __shared__ float t1[4][64];
        int n = (b - 8)*4 + (tid >> 6);
        int j = tid & 63;
        int sl = tid >> 6;
        float p0 = pos[n*3], p1 = pos[n*3+1], p2 = pos[n*3+2];
        t1[sl][j] = fmaxf(p0*Wp1[j] + p1*Wp1[64+j] + p2*Wp1[128+j] + bp1[j], 0.f);
        __syncthreads();
        float s = bp2[j];
        #pragma unroll 8
        for (int k = 0; k < 64; ++k) s += t1[sl][k]*Wp2[k*64 + j];
        g_pe[n*64 + j] = s;
    } else {
        int i = (b - 136)*256 + tid;
        if (i < 16384) {
            int n = i >> 6, k = i & 63;
            g_Wg1tf[i] = __float2half(Wg1[k*256 + n]);
        } else if (i < 81920) {
            int j = i - 16384;
            int n = j >> 8, k = j & 255;
            g_Wg2tf[j] = __float2half(Wg2[k*256 + n]);
        } else if (i < 311296) {
            int j = i - 81920;
            int n = j / 1792, k = j - n*1792;
            g_W2t[j] = __float2half(W2[k*128 + n]);
        }
    }
}

__global__ void k_conv1stats(const float* __restrict__ x, const float* __restrict__ W1) {
    __shared__ float sx[70];
    __shared__ float red[256];
    int b = blockIdx.x;
    int n = b >> 1;
    int t0 = (b & 1) * 64;
    int tid = threadIdx.x;
    if (tid < 70) {
        int t = t0 - 3 + tid;
        sx[tid] = (t >= 0 && t < TT) ? x[n*TT + t] : 0.f;
    }
    __syncthreads();
    int c = tid & 63, r0 = tid >> 6;
    float w[7];
    #pragma unroll
    for (int k = 0; k < 7; ++k) w[k] = W1[k*64 + c];
    float ls = 0.f, lq = 0.f;
    for (int rr = r0; rr < 64; rr += 4) {
        float y = 0.f;
        #pragma unroll
        for (int k = 0; k < 7; ++k) y += sx[rr + k] * w[k];
        ls += y; lq += y*y;
    }
    red[tid] = ls; __syncthreads();
    if (tid < 64) atomicAdd(&g_s1[c], red[tid]+red[tid+64]+red[tid+128]+red[tid+192]);
    __syncthreads();
    red[tid] = lq; __syncthreads();
    if (tid < 64) atomicAdd(&g_sq1[c], red[tid]+red[tid+64]+red[tid+128]+red[tid+192]);
}

// recompute conv1 + BN1 apply + ReLU + add pe -> h0 fp16 single
__global__ void k_bn1pe(const float* __restrict__ x, const float* __restrict__ W1,
                        const float* __restrict__ g1w, const float* __restrict__ b1w) {
    __shared__ float sx[70];
    int b = blockIdx.x;
    int n = b >> 1;
    int t0 = (b & 1) * 64;
    int tid = threadIdx.x;
    if (tid < 70) {
        int t = t0 - 3 + tid;
        sx[tid] = (t >= 0 && t < TT) ? x[n*TT + t] : 0.f;
    }
    __syncthreads();
    int c0 = (tid & 31) * 2;
    int r0 = tid >> 5;
    float w0[7], w1[7];
    #pragma unroll
    for (int k = 0; k < 7; ++k) { w0[k] = W1[k*64 + c0]; w1[k] = W1[k*64 + c0 + 1]; }
    float mu0  = g_s1[c0]   * (1.f/65536.f);
    float var0 = g_sq1[c0]  * (1.f/65536.f) - mu0*mu0;
    float a0 = g1w[c0] * rsqrtf(var0 + EPSV);
    float bb0 = b1w[c0] - mu0*a0;
    float mu1  = g_s1[c0+1]  * (1.f/65536.f);
    float var1 = g_sq1[c0+1] * (1.f/65536.f) - mu1*mu1;
    float a1 = g1w[c0+1] * rsqrtf(var1 + EPSV);
    float bb1 = b1w[c0+1] - mu1*a1;
    float pe0 = g_pe[n*64 + c0], pe1 = g_pe[n*64 + c0 + 1];
    for (int r = r0; r < 64; r += 8) {
        float y0 = 0.f, y1 = 0.f;
        #pragma unroll
        for (int k = 0; k < 7; ++k) { y0 += sx[r+k]*w0[k]; y1 += sx[r+k]*w1[k]; }
        float v0 = fmaxf(a0*y0 + bb0, 0.f) + pe0;
        float v1 = fmaxf(a1*y1 + bb1, 0.f) + pe1;
        store_h2v(g_h0, (long long)(b*64 + r)*64 + c0, v0, v1);
    }
}

// ---------------- fp32 SIMT GEMM (conv3 only) ----------------
__global__ void k_gemm(const float* __restrict__ Aall, const float* __restrict__ Ball,
                       float* __restrict__ Call,
                       int M, int N, int K, int Tout, int Tin, int rowC)
{
    const float* A = Aall;
    const float* B = Ball;

    __shared__ __align__(16) float As[16][68];
    __shared__ __align__(16) float Bs[16][68];

    int tid = threadIdx.x;
    int tx = tid & 15, ty = tid >> 4;
    int m0 = blockIdx.y * 64;
    int n0 = blockIdx.x * 64;

    int abase[4]; bool aok[4];
    #pragma unroll
    for (int p = 0; p < 4; ++p) {
        int row = m0 + p*16 + (tid >> 4);
        aok[p] = (row < M);
        abase[p] = aok[p] ? ((row / Tout) * Tin + (row % Tout)) * rowC : 0;
    }
    int akk = tid & 15;

    float acc[4][4] = {};

    for (int k0 = 0; k0 < K; k0 += 16) {
        #pragma unroll
        for (int p = 0; p < 4; ++p) {
            float v = aok[p] ? A[abase[p] + k0 + akk] : 0.f;
            As[akk][p*16 + (tid >> 4)] = v;
        }
        #pragma unroll
        for (int p = 0; p < 4; ++p) {
            int kk = p*4 + (tid >> 6);
            Bs[kk][tid & 63] = B[(k0 + kk) * N + n0 + (tid & 63)];
        }
        __syncthreads();
        #pragma unroll
        for (int kk = 0; kk < 16; ++kk) {
            float4 av = *(const float4*)&As[kk][ty*4];
            float4 bv = *(const float4*)&Bs[kk][tx*4];
            float a_[4] = {av.x, av.y, av.z, av.w};
            float b_[4] = {bv.x, bv.y, bv.z, bv.w};
            #pragma unroll
            for (int i = 0; i < 4; ++i)
                #pragma unroll
                for (int j = 0; j < 4; ++j)
                    acc[i][j] += a_[i] * b_[j];
        }
        __syncthreads();
    }

    #pragma unroll
    for (int i = 0; i < 4; ++i) {
        int row = m0 + ty*4 + i;
        if (row >= M) continue;
        #pragma unroll
        for (int j = 0; j < 4; ++j) {
            int col = n0 + tx*4 + j;
            Call[(long long)row * N + col] = acc[i][j];
        }
    }
}

// ---------------- TC aggregation (fp16 single, 1-chain) ----------------------
#define ASTR 72
#define HSTR 264
#define AGGH_SMEM (64*ASTR*2 + 64*HSTR*2)      // 43008

__global__ void __launch_bounds__(256, 2)
k_agg_tc_h16(const __half* __restrict__ H, __half* __restrict__ O, int F)
{
    extern __shared__ char dsm[];
    uint32_t sA  = smem_u32(dsm);
    uint32_t sH  = sA + 64*ASTR*2;

    int g = blockIdx.y;
    int n0 = blockIdx.x * 256;
    int tid = threadIdx.x, lane = tid & 31, wid = tid >> 5;

    const char* Agf = (const char*)(g_Asf + g*4096);
    #pragma unroll
    for (int it = 0; it < 2; ++it) {
        int sid = it*256 + tid;
        int row = sid >> 3, seg = (sid & 7) * 8;
        CP16(sA + (row*ASTR + seg)*2, Agf + (row*64 + seg)*2);
    }
    long long hbase = (long long)(g*64) * F + n0;
    #pragma unroll
    for (int it = 0; it < 8; ++it) {
        int sid = it*256 + tid;
        int row = sid >> 5, seg = (sid & 31) * 8;
        long long go = (hbase + (long long)row*F + seg) * 2;
        CP16(sH + (row*HSTR + seg)*2, (const char*)H + go);
    }
    CP_COMMIT();
    CP_WAIT0();
    __syncthreads();

    float acc[4][4][4] = {};
    int nw = wid * 32;
    uint32_t arow = lane & 15, ahi = (lane >> 4) * 8;

    #pragma unroll
    for (int kk = 0; kk < 4; ++kk) {
        uint32_t ah[4][4];
        uint32_t acol = kk*16 + ahi;
        #pragma unroll
        for (int i = 0; i < 4; ++i)
            LDSM_X4(ah[i][0], ah[i][1], ah[i][2], ah[i][3],
                    sA + ((i*16 + arow)*ASTR + acol)*2);
        uint32_t brow = kk*16 + (lane & 15);
        #pragma unroll
        for (int jp = 0; jp < 2; ++jp) {
            uint32_t bh2[2][2];
            uint32_t bcol = nw + jp*16 + ahi;
            uint32_t t0, t1, t2, t3;
            LDSM_X4T(t0, t1, t2, t3, sH + (brow*HSTR + bcol)*2);
            bh2[0][0] = t0; bh2[0][1] = t1; bh2[1][0] = t2; bh2[1][1] = t3;
            #pragma unroll
            for (int i = 0; i < 4; ++i)
                #pragma unroll
                for (int j2 = 0; j2 < 2; ++j2)
                    MMA16816H(acc[i][jp*2+j2], ah[i], bh2[j2]);
        }
    }

    int rb = lane >> 2;
    int cb = n0 + nw + (lane & 3)*2;
    #pragma unroll
    for (int i = 0; i < 4; ++i)
        #pragma unroll
        for (int j = 0; j < 4; ++j)
            #pragma unroll
            for (int half = 0; half < 2; ++half) {
                int row = i*16 + rb + half*8;
                long long idx = (long long)(g*64 + row) * F + cb + j*8;
                store_h2v(O, idx, acc[i][j][half*2], acc[i][j][half*2+1]);
            }
}

// ---------------- fp16 1-chain GEMM (gcn1/gcn2) -------------------------------
#define KC 32
#define ROWB 64
#define ARR_BYTES (128*ROWB)                // 8192
#define NSTAGE 3
#define STAGE_1 (2*ARR_BYTES)               // 16384

__global__ void __launch_bounds__(256, 2)
k_gemm_tc_h16(const __half* __restrict__ A, const __half* __restrict__ B,
              const float* __restrict__ bias,
              __half* __restrict__ C, int K, int ldc)
{
    extern __shared__ char dsm[];
    uint32_t sbase = smem_u32(dsm);
    int tid = threadIdx.x, lane = tid & 31, wid = tid >> 5;
    int m0 = blockIdx.y * 128, n0 = blockIdx.x * 128;

    long long gA0, gB0, gA1, gB1;
    uint32_t so0, so1;
    {
        int row = tid >> 2, seg = tid & 3;
        gA0 = (long long)(m0 + row) * K + seg*8;
        gB0 = (long long)(n0 + row) * K + seg*8;
        so0 = (uint32_t)(row*ROWB + (seg ^ ((row >> 1) & 3))*16);
        row += 64;
        gA1 = (long long)(m0 + row) * K + seg*8;
        gB1 = (long long)(n0 + row) * K + seg*8;
        so1 = (uint32_t)(row*ROWB + (seg ^ ((row >> 1) & 3))*16);
    }

    int wm = wid & 1, wn = wid >> 1;
    uint32_t aRowB = (uint32_t)(wm*64 + (lane & 15)) * ROWB;
    uint32_t aSub  = lane >> 4;
    uint32_t xorA  = ((lane & 15) >> 1) & 3;
    uint32_t bRowB = (uint32_t)(wn*32 + ((lane >> 4) & 1)*8 + (lane & 7)) * ROWB;
    uint32_t bSub  = (lane >> 3) & 1;
    uint32_t xorB  = ((lane & 7) >> 1) & 3;

    float acc[4][4][4] = {};

    int nc = K >> 5;
    #pragma unroll
    for (int pc = 0; pc < 2; ++pc) {
        uint32_t st = sbase + pc*STAGE_1;
        long long k0 = (long long)pc*KC;
        CP16(st +             so0, (const char*)A + (gA0+k0)*2);
        CP16(st +             so1, (const char*)A + (gA1+k0)*2);
        CP16(st + ARR_BYTES + so0, (const char*)B + (gB0+k0)*2);
        CP16(st + ARR_BYTES + so1, (const char*)B + (gB1+k0)*2);
        CP_COMMIT();
    }

    int scur = 0, snext2 = 2;
    for (int c = 0; c < nc; ++c) {
        CP_WAITG1();
        __syncthreads();

        if (c + 2 < nc) {
            uint32_t st = sbase + snext2*STAGE_1;
            long long k0 = (long long)(c+2)*KC;
            CP16(st +             so0, (const char*)A + (gA0+k0)*2);
            CP16(st +             so1, (const char*)A + (gA1+k0)*2);
            CP16(st + ARR_BYTES + so0, (const char*)B + (gB0+k0)*2);
            CP16(st + ARR_BYTES + so1, (const char*)B + (gB1+k0)*2);
        }
        CP_COMMIT();

        uint32_t st = sbase + scur*STAGE_1;

        #pragma unroll
        for (int k16 = 0; k16 < 2; ++k16) {
            uint32_t physA = (((uint32_t)k16*2 + aSub) ^ xorA) * 16;
            uint32_t physB = (((uint32_t)k16*2 + bSub) ^ xorB) * 16;
            uint32_t ah[4][4];
            #pragma unroll
            for (int i = 0; i < 4; ++i) {
                uint32_t ro = aRowB + i*(16*ROWB) + physA;
                LDSM_X4(ah[i][0], ah[i][1], ah[i][2], ah[i][3], st + ro);
            }
            #pragma unroll
            for (int jj = 0; jj < 2; ++jj) {
                uint32_t bh2[2][2];
                uint32_t ro = bRowB + jj*(16*ROWB) + physB;
                uint32_t t0, t1, t2, t3;
                LDSM_X4(t0, t1, t2, t3, st + ARR_BYTES + ro);
                bh2[0][0] = t0; bh2[0][1] = t1; bh2[1][0] = t2; bh2[1][1] = t3;
                #pragma unroll
                for (int i = 0; i < 4; ++i)
                    #pragma unroll
                    for (int j2 = 0; j2 < 2; ++j2)
                        MMA16816H(acc[i][jj*2+j2], ah[i], bh2[j2]);
            }
        }
        scur = (scur == NSTAGE-1) ? 0 : scur+1;
        snext2 = (snext2 == NSTAGE-1) ? 0 : snext2+1;
    }

    int rbase = m0 + wm*64 + (lane >> 2);
    int cbase = n0 + wn*32 + (lane & 3)*2;
    #pragma unroll
    for (int i = 0; i < 4; ++i) {
        #pragma unroll
        for (int j = 0; j < 4; ++j) {
            int gc = cbase + j*8;
            #pragma unroll
            for (int half = 0; half < 2; ++half) {
                long long gr = rbase + i*16 + half*8;
                float v0 = fmaxf(acc[i][j][half*2]     + bias[gc],   0.f);
                float v1 = fmaxf(acc[i][j][half*2 + 1] + bias[gc+1], 0.f);
                store_h2v(C, gr * ldc + gc, v0, v1);
            }
        }
    }
}

// ---------------- sliding-window conv2 (fp16 single, 1-chain) -----------------
#define CV_AROWS 144
#define CV_ASPL (CV_AROWS*ROWB)            // 9216
#define CV_BSPL (128*ROWB)                 // 8192
#define CV_BBASE (2*CV_ASPL)               // 18432
#define CV_SMEM (CV_BBASE + 4*CV_BSPL)     // 51200
#define CV_NC 56

__global__ void __launch_bounds__(256, 2)
k_conv2_sw()
{
    extern __shared__ char dsm[];
    __shared__ float s_sum[128], s_sq[128];
    uint32_t sb = smem_u32(dsm);
    int tid = threadIdx.x, lane = tid & 31, wid = tid >> 5;
    int n = blockIdx.y;

    // zero A pad rows 128..143 in both A stages
    if (tid < 128) {
        int arr = tid >> 6;
        int off = tid & 63;
        int row = 128 + (off >> 2);
        int seg = off & 3;
        *(uint4*)(dsm + arr*CV_ASPL + row*ROWB + seg*16) = make_uint4(0,0,0,0);
    }

    int crow0 = tid >> 2, seg = tid & 3;
    int crow1 = crow0 + 64;
    uint32_t soA0 = (uint32_t)(crow0*ROWB + (seg ^ ((crow0 >> 1) & 3))*16);
    uint32_t soA1 = (uint32_t)(crow1*ROWB + (seg ^ ((crow1 >> 1) & 3))*16);
    long long hbase = ((long long)n*128) * 256 + seg*8;

    int wm = wid & 1, wn = wid >> 1;
    uint32_t aRowT = (uint32_t)(wm*64 + (lane & 15));
    uint32_t aSub  = lane >> 4;
    uint32_t bRowB = (uint32_t)(wn*32 + ((lane >> 4) & 1)*8 + (lane & 7)) * ROWB;
    uint32_t bSub  = (lane >> 3) & 1;
    uint32_t xorB  = ((lane & 7) >> 1) & 3;

    float acc[4][4][4] = {};

    #pragma unroll
    for (int pc = 0; pc < 3; ++pc) {
        if (pc == 0) {
            CP16(sb + soA0, (const char*)g_h2 + (hbase + (long long)crow0*256)*2);
            CP16(sb + soA1, (const char*)g_h2 + (hbase + (long long)crow1*256)*2);
        }
        {
            uint32_t bst = sb + CV_BBASE + pc*CV_BSPL;
            long long bcol = (long long)pc*256 + seg*8;
            CP16(bst + soA0, (const char*)g_W2t + ((long long)crow0*1792 + bcol)*2);
            CP16(bst + soA1, (const char*)g_W2t + ((long long)crow1*1792 + bcol)*2);
        }
        CP_COMMIT();
    }

    int cg = 0, tap = 0;
    for (int c = 0; c < CV_NC; ++c) {
        CP_WAITG2();
        __syncthreads();

        int cn = c + 3;
        if (cn < CV_NC) {
            int cgn = cn / 7, tapn = cn - cgn*7;
            if (tapn == 0) {
                uint32_t ast = sb + (cgn & 1)*CV_ASPL;
                long long ac = hbase + cgn*32;
                CP16(ast + soA0, (const char*)g_h2 + (ac + (long long)crow0*256)*2);
                CP16(ast + soA1, (const char*)g_h2 + (ac + (long long)crow1*256)*2);
            }
            uint32_t bst = sb + CV_BBASE + (cn & 3)*CV_BSPL;
            long long bcol = (long long)tapn*256 + cgn*32 + seg*8;
            CP16(bst + soA0, (const char*)g_W2t + ((long long)crow0*1792 + bcol)*2);
            CP16(bst + soA1, (const char*)g_W2t + ((long long)crow1*1792 + bcol)*2);
        }
        CP_COMMIT();

        uint32_t ast = sb + (cg & 1)*CV_ASPL;
        uint32_t bst = sb + CV_BBASE + (c & 3)*CV_BSPL;
        uint32_t arow = aRowT + tap;
        uint32_t xorA = ((arow >> 1) & 3);
        uint32_t aBase = arow * ROWB;

        #pragma unroll
        for (int k16 = 0; k16 < 2; ++k16) {
            uint32_t physA = (((uint32_t)k16*2 + aSub) ^ xorA) * 16;
            uint32_t physB = (((uint32_t)k16*2 + bSub) ^ xorB) * 16;
            uint32_t ah[4][4];
            #pragma unroll
            for (int i = 0; i < 4; ++i) {
                uint32_t ro = aBase + i*(16*ROWB) + physA;
                LDSM_X4(ah[i][0], ah[i][1], ah[i][2], ah[i][3], ast + ro);
            }
            #pragma unroll
            for (int jj = 0; jj < 2; ++jj) {
                uint32_t bh2[2][2];
                uint32_t ro = bRowB + jj*(16*ROWB) + physB;
                uint32_t t0, t1, t2, t3;
                LDSM_X4(t0, t1, t2, t3, bst + ro);
                bh2[0][0] = t0; bh2[0][1] = t1; bh2[1][0] = t2; bh2[1][1] = t3;
                #pragma unroll
                for (int i = 0; i < 4; ++i)
                    #pragma unroll
                    for (int j2 = 0; j2 < 2; ++j2)
                        MMA16816H(acc[i][jj*2+j2], ah[i], bh2[j2]);
            }
        }
        if (++tap == 7) { tap = 0; ++cg; }
    }

    __syncthreads();
    if (tid < 128) { s_sum[tid] = 0.f; s_sq[tid] = 0.f; }
    __syncthreads();

    float psum[8] = {}, psq[8] = {};
    int rloc = wm*64 + (lane >> 2);
    int cbase = wn*32 + (lane & 3)*2;
    #pragma unroll
    for (int i = 0; i < 4; ++i) {
        #pragma unroll
        for (int j = 0; j < 4; ++j) {
            int gc = cbase + j*8;
            #pragma unroll
            for (int half = 0; half < 2; ++half) {
                int lr = rloc + i*16 + half*8;
                if (lr < 122) {
                    float v0 = acc[i][j][half*2], v1 = acc[i][j][half*2 + 1];
                    long long idx = (long long)(n*122 + lr)*128 + gc;
                    *(float2*)&g_y2[idx] = make_float2(v0, v1);
                    psum[j*2]   += v0;  psq[j*2]   += v0*v0;
                    psum[j*2+1] += v1;  psq[j*2+1] += v1*v1;
                }
            }
        }
    }
    #pragma unroll
    for (int j = 0; j < 4; ++j) {
        atomicAdd(&s_sum[cbase + j*8],     psum[j*2]);
        atomicAdd(&s_sum[cbase + j*8 + 1], psum[j*2+1]);
        atomicAdd(&s_sq[cbase + j*8],      psq[j*2]);
        atomicAdd(&s_sq[cbase + j*8 + 1],  psq[j*2+1]);
    }
    __syncthreads();
    if (tid < 128) {
        atomicAdd(&g_s2[tid],  s_sum[tid]);
        atomicAdd(&g_sq2[tid], s_sq[tid]);
    }
}

// ---------------- pool / BN3 / tail ----------------
__global__ void k_pool(const float* __restrict__ g2w, const float* __restrict__ b2w) {
    int c = threadIdx.x;
    int chunk = blockIdx.x;
    int tp = blockIdx.y;
    int g = blockIdx.z;
    float mu  = g_s2[c]  * (1.f/62464.f);
    float var = g_sq2[c] * (1.f/62464.f) - mu*mu;
    float a = g2w[c] * rsqrtf(var + EPSV);
    float bb = b2w[c] - mu*a;
    float acc = 0.f;
    for (int nl = 0; nl < 16; ++nl) {
        int n = g*64 + chunk*16 + nl;
        const float* p = &g_y2[(n*122 + tp*4)*128 + c];
        float s4 = p[0] + p[128] + p[256] + p[384];
        acc += fmaxf(a * (s4 * 0.25f) + bb, 0.f);
    }
    atomicAdd(&g_gbuf[(g*30 + tp)*128 + c], acc * (1.f/64.f));
}

__global__ void k_bn3stats() {
    __shared__ float red[256];
    int tid = threadIdx.x;
    int c = tid & 127, r0 = tid >> 7;
    float ls = 0.f, lq = 0.f;
    for (int r = r0; r < 224; r += 2) { float v = g_y3[r*128 + c]; ls += v; lq += v*v; }
    red[tid] = ls; __syncthreads();
    float ssum = 0.f;
    if (tid < 128) ssum = red[tid] + red[tid+128];
    __syncthreads();
    red[tid] = lq; __syncthreads();
    if (tid < 128) {
        float q = red[tid] + red[tid+128];
        float mu = ssum * (1.f/224.f);
        float var = q * (1.f/224.f) - mu*mu;
        g_mu3[tid] = mu;
        g_rs3[tid] = rsqrtf(var + EPSV);
    }
}

__global__ void k_tail(const float* __restrict__ g3w, const float* __restrict__ b3w,
                       const float* __restrict__ Wd, const float* __restrict__ bd,
                       float* __restrict__ out) {
    __shared__ float gg[896];
    __shared__ float slog[4];
    int b = blockIdx.x, tid = threadIdx.x;
    int c = tid;
    float a = g3w[c] * g_rs3[c];
    float bb = b3w[c] - g_mu3[c]*a;
    #pragma unroll
    for (int tp = 0; tp < 7; ++tp) {
        const float* p = &g_y3[(b*28 + tp*4)*128 + c];
        float s4 = (p[0] + p[128] + p[256] + p[384]) * 0.25f;
        gg[tp*128 + c] = fmaxf(a*s4 + bb, 0.f);
    }
    __syncthreads();
    int w = tid >> 5, lane = tid & 31;
    float s = 0.f;
    for (int i = lane; i < 896; i += 32) s += gg[i] * Wd[i*4 + w];
    #pragma unroll
    for (int off = 16; off; off >>= 1) s += __shfl_xor_sync(0xffffffffu, s, off);
    if (lane == 0) slog[w] = s + bd[w];
    __syncthreads();
    if (tid == 0) {
        float m = fmaxf(fmaxf(slog[0], slog[1]), fmaxf(slog[2], slog[3]));
        float se = expf(slog[0]-m)+expf(slog[1]-m)+expf(slog[2]-m)+expf(slog[3]-m);
        float lse = logf(se);
        #pragma unroll
        for (int j = 0; j < 4; ++j) out[b*4 + j] = slog[j] - m - lse;
    }
}

// ---------------- launch ----------------
extern "C" void kernel_launch(void* const* d_in, const int* in_sizes, int n_in,
                              void* d_out, int out_size) {
    const float* x   = (const float*)d_in[0];
    const float* pos = (const float*)d_in[1];
    const int*   ei  = (const int*)d_in[2];
    const float* W1  = (const float*)d_in[4];
    const float* g1  = (const float*)d_in[5];
    const float* b1  = (const float*)d_in[6];
    const float* Wp1 = (const float*)d_in[7];
    const float* bp1 = (const float*)d_in[8];
    const float* Wp2 = (const float*)d_in[9];
    const float* bp2 = (const float*)d_in[10];
    const float* Wg1 = (const float*)d_in[11];
    const float* bg1 = (const float*)d_in[12];
    const float* Wg2 = (const float*)d_in[13];
    const float* bg2 = (const float*)d_in[14];
    const float* W2  = (const float*)d_in[15];
    const float* g2  = (const float*)d_in[16];
    const float* b2  = (const float*)d_in[17];
    const float* W3  = (const float*)d_in[18];
    const float* g3  = (const float*)d_in[19];
    const float* b3  = (const float*)d_in[20];
    const float* Wd  = (const float*)d_in[21];
    const float* bd  = (const float*)d_in[22];
    float* out = (float*)d_out;

    float *pGbuf, *pY3;
    __half *pH0, *pA0, *pH1, *pA1, *pH2, *pWg1f, *pWg2f;
    cudaGetSymbolAddress((void**)&pGbuf, g_gbuf);
    cudaGetSymbolAddress((void**)&pY3,   g_y3);
    cudaGetSymbolAddress((void**)&pH0,   g_h0);
    cudaGetSymbolAddress((void**)&pA0,   g_agg0);
    cudaGetSymbolAddress((void**)&pH1,   g_h1);
    cudaGetSymbolAddress((void**)&pA1,   g_agg1);
    cudaGetSymbolAddress((void**)&pH2,   g_h2);
    cudaGetSymbolAddress((void**)&pWg1f, g_Wg1tf);
    cudaGetSymbolAddress((void**)&pWg2f, g_Wg2tf);

    cudaFuncSetAttribute(k_gemm_tc_h16, cudaFuncAttributeMaxDynamicSharedMemorySize, NSTAGE*STAGE_1);
    cudaFuncSetAttribute(k_agg_tc_h16, cudaFuncAttributeMaxDynamicSharedMemorySize, AGGH_SMEM);
    cudaFuncSetAttribute(k_conv2_sw, cudaFuncAttributeMaxDynamicSharedMemorySize, CV_SMEM);

    k_zero<<<120, 256>>>();
    k_setup<<<1352, 256>>>(ei, pos, Wp1, bp1, Wp2, bp2, Wg1, Wg2, W2);
    k_conv1stats<<<1024, 256>>>(x, W1);
    k_bn1pe<<<1024, 256>>>(x, W1, g1, b1);

    // agg0 = A @ h0  (fp16 1-chain), F = T*C0 = 8192
    k_agg_tc_h16<<<dim3(32, 8), 256, AGGH_SMEM>>>(pH0, pA0, 8192);
    // gcn1: h1 = relu(agg0 @ Wg1^T + bg1)  (fp16 1-chain)
    k_gemm_tc_h16<<<dim3(2, 512), 256, NSTAGE*STAGE_1>>>(pA0, pWg1f, bg1, pH1, 64, 256);
    // agg1 = A @ h1  (fp16 1-chain), F = T*EMB = 32768
    k_agg_tc_h16<<<dim3(128, 8), 256, AGGH_SMEM>>>(pH1, pA1, 32768);
    // gcn2: h2 = relu(agg1 @ Wg2^T + bg2)  (fp16 1-chain)
    k_gemm_tc_h16<<<dim3(2, 512), 256, NSTAGE*STAGE_1>>>(pA1, pWg2f, bg2, pH2, 256, 256);
    // conv2 sliding-window fp16 1-chain + fused BN2 stats
    k_conv2_sw<<<dim3(1, 512), 256, CV_SMEM>>>();
    k_pool<<<dim3(4, 30, 8), 128>>>(g2, b2);
    // conv3 (k=3 VALID, 128->128) SIMT
    k_gemm<<<dim3(2, 4, 1), 256>>>(pGbuf, W3, pY3, 224, 128, 384, 28, 30, 128);
    k_bn3stats<<<1, 256>>>();
    k_tail<<<8, 128>>>(g3, b3, Wd, bd, out);
}

// round 16
// speedup vs baseline: 2.1624x; 1.0535x over previous
#include <cuda_runtime.h>
#include <cuda_fp16.h>
#include <math.h>
#include <stdint.h>

#define N_NODES 512
#define TT 128
#define NE 4096
#define C0 64
#define C1 128
#define C2 128
#define EMB 256
#define NG 8
#define EPSV 1e-5f

// ---------------- scratch (device globals; no allocs allowed) ----------------
__device__ __half g_y2h[N_NODES*122*C1];
__device__ float g_gbuf[NG*30*C1];
__device__ float g_y3[NG*28*C2];
__device__ float g_pe[N_NODES*C0];
__device__ float g_s1[C0], g_sq1[C0];
__device__ float g_s2[C1], g_sq2[C1];
__device__ float g_mu3[C2], g_rs3[C2];

// fp16 single buffers (entire TC pipeline, 1-chain)
__device__ __half g_Asf[NG*64*64];
__device__ __half g_h0[N_NODES*TT*C0];
__device__ __half g_agg0[N_NODES*TT*C0];
__device__ __half g_h1[N_NODES*TT*EMB];
__device__ __half g_agg1[N_NODES*TT*EMB];
__device__ __half g_Wg1tf[EMB*C0];       // [256][64]
__device__ __half g_Wg2tf[EMB*EMB];      // [256][256]
__device__ __half g_h2[N_NODES*TT*EMB];
__device__ __half g_W2t[C1*7*EMB];       // [128][1792]

// ---------------- helpers ----------------
__device__ __forceinline__ uint32_t smem_u32(const void* p) {
    uint32_t a;
    asm("{ .reg .u64 t; cvta.to.shared.u64 t, %1; cvt.u32.u64 %0, t; }" : "=r"(a) : "l"(p));
    return a;
}
#define CP16(dst, src) asm volatile("cp.async.cg.shared.global [%0], [%1], 16;" :: "r"(dst), "l"(src))
#define CP_COMMIT()    asm volatile("cp.async.commit_group;" ::: "memory")
#define CP_WAITG1()    asm volatile("cp.async.wait_group 1;" ::: "memory")
#define CP_WAITG2()    asm volatile("cp.async.wait_group 2;" ::: "memory")
#define CP_WAIT0()     asm volatile("cp.async.wait_group 0;" ::: "memory")
#define LDSM_X4(r0, r1, r2, r3, addr) \
    asm volatile("ldmatrix.sync.aligned.m8n8.x4.shared.b16 {%0,%1,%2,%3}, [%4];" \
        : "=r"(r0), "=r"(r1), "=r"(r2), "=r"(r3) : "r"(addr))
#define LDSM_X4T(r0, r1, r2, r3, addr) \
    asm volatile("ldmatrix.sync.aligned.m8n8.x4.trans.shared.b16 {%0,%1,%2,%3}, [%4];" \
        : "=r"(r0), "=r"(r1), "=r"(r2), "=r"(r3) : "r"(addr))
#define MMA16816H(d, a, b) \
    asm volatile("mma.sync.aligned.m16n8k16.row.col.f32.f16.f16.f32 " \
        "{%0,%1,%2,%3}, {%4,%5,%6,%7}, {%8,%9}, {%0,%1,%2,%3};" \
        : "+f"((d)[0]), "+f"((d)[1]), "+f"((d)[2]), "+f"((d)[3]) \
        : "r"((a)[0]), "r"((a)[1]), "r"((a)[2]), "r"((a)[3]), "r"((b)[0]), "r"((b)[1]))

__device__ __forceinline__ void store_h2v(__half* H, long long idx, float v0, float v1) {
    __half2 hv; hv.x = __float2half(v0); hv.y = __float2half(v1);
    *(__half2*)&H[idx] = hv;
}

// ---------------- fused setup ----------------
// blocks 0..7 adjacency; 8..135 pe (4 nodes/block); 136..1351 wprep; 1352..1471 zero
__global__ void k_setup(const int* __restrict__ ei,
                        const float* __restrict__ pos, const float* __restrict__ Wp1,
                        const float* __restrict__ bp1, const float* __restrict__ Wp2,
                        const float* __restrict__ bp2,
                        const float* __restrict__ Wg1, const float* __restrict__ Wg2,
                        const float* __restrict__ W2) {
    int b = blockIdx.x, tid = threadIdx.x;
    if (b < 8) {
        __shared__ int sdeg[64];
        __shared__ float sA[64*64];
        int g = b;
        if (tid < 64) sdeg[tid] = 1;
        for (int i = tid; i < 4096; i += 256) sA[i] = 0.f;
        __syncthreads();
        int e0 = g*512 + tid;
        atomicAdd(&sdeg[ei[NE + e0] & 63], 1);
        atomicAdd(&sdeg[ei[NE + e0 + 256] & 63], 1);
        __syncthreads();
        #pragma unroll
        for (int it = 0; it < 2; ++it) {
            int e = e0 + it*256;
            int s = ei[e] & 63, d = ei[NE + e] & 63;
            float nr = rsqrtf((float)sdeg[s]) * rsqrtf((float)sdeg[d]);
            atomicAdd(&sA[(d << 6) + s], nr);
        }
        __syncthreads();
        if (tid < 64) atomicAdd(&sA[tid*64 + tid], 1.f/(float)sdeg[tid]);
        __syncthreads();
        for (int i = tid; i < 4096; i += 256)
            g_Asf[g*4096 + i] = __float2half(sA[i]);
    } else if (b < 136) {
        __shared__ float t1[4][64];
        int n = (b - 8)*4 + (tid >> 6);
        int j = tid & 63;
        int sl = tid >> 6;
        float p0 = pos[n*3], p1 = pos[n*3+1], p2 = pos[n*3+2];
        t1[sl][j] = fmaxf(p0*Wp1[j] + p1*Wp1[64+j] + p2*Wp1[128+j] + bp1[j], 0.f);
        __syncthreads();
        float s = bp2[j];
        #pragma unroll 8
        for (int k = 0; k < 64; ++k) s += t1[sl][k]*Wp2[k*64 + j];
        g_pe[n*64 + j] = s;
    } else if (b < 1352) {
        int i = (b - 136)*256 + tid;
        if (i < 16384) {
            int n = i >> 6, k = i & 63;
            g_Wg1tf[i] = __float2half(Wg1[k*256 + n]);
        } else if (i < 81920) {
            int j = i - 16384;
            int n = j >> 8, k = j & 255;
            g_Wg2tf[j] = __float2half(Wg2[k*256 + n]);
        } else if (i < 311296) {
            int j = i - 81920;
            int n = j / 1792, k = j - n*1792;
            g_W2t[j] = __float2half(W2[k*128 + n]);
        }
    } else {
        int i = (b - 1352)*256 + tid;
        if (i < C0) { g_s1[i]=0.f; g_sq1[i]=0.f; }
        if (i < C1) { g_s2[i]=0.f; g_sq2[i]=0.f; }
        if (i < NG*30*C1) g_gbuf[i] = 0.f;
    }
}

__global__ void k_conv1stats(const float* __restrict__ x, const float* __restrict__ W1) {
    __shared__ float sx[70];
    __shared__ float red[256];
    int b = blockIdx.x;
    int n = b >> 1;
    int t0 = (b & 1) * 64;
    int tid = threadIdx.x;
    if (tid < 70) {
        int t = t0 - 3 + tid;
        sx[tid] = (t >= 0 && t < TT) ? x[n*TT + t] : 0.f;
    }
    __syncthreads();
    int c = tid & 63, r0 = tid >> 6;
    float w[7];
    #pragma unroll
    for (int k = 0; k < 7; ++k) w[k] = W1[k*64 + c];
    float ls = 0.f, lq = 0.f;
    for (int rr = r0; rr < 64; rr += 4) {
        float y = 0.f;
        #pragma unroll
        for (int k = 0; k < 7; ++k) y += sx[rr + k] * w[k];
        ls += y; lq += y*y;
    }
    red[tid] = ls; __syncthreads();
    if (tid < 64) atomicAdd(&g_s1[c], red[tid]+red[tid+64]+red[tid+128]+red[tid+192]);
    __syncthreads();
    red[tid] = lq; __syncthreads();
    if (tid < 64) atomicAdd(&g_sq1[c], red[tid]+red[tid+64]+red[tid+128]+red[tid+192]);
}

// recompute conv1 + BN1 apply + ReLU + add pe -> h0 fp16 single
__global__ void k_bn1pe(const float* __restrict__ x, const float* __restrict__ W1,
                        const float* __restrict__ g1w, const float* __restrict__ b1w) {
    __shared__ float sx[70];
    int b = blockIdx.x;
    int n = b >> 1;
    int t0 = (b & 1) * 64;
    int tid = threadIdx.x;
    if (tid < 70) {
        int t = t0 - 3 + tid;
        sx[tid] = (t >= 0 && t < TT) ? x[n*TT + t] : 0.f;
    }
    __syncthreads();
    int c0 = (tid & 31) * 2;
    int r0 = tid >> 5;
    float w0[7], w1[7];
    #pragma unroll
    for (int k = 0; k < 7; ++k) { w0[k] = W1[k*64 + c0]; w1[k] = W1[k*64 + c0 + 1]; }
    float mu0  = g_s1[c0]   * (1.f/65536.f);
    float var0 = g_sq1[c0]  * (1.f/65536.f) - mu0*mu0;
    float a0 = g1w[c0] * rsqrtf(var0 + EPSV);
    float bb0 = b1w[c0] - mu0*a0;
    float mu1  = g_s1[c0+1]  * (1.f/65536.f);
    float var1 = g_sq1[c0+1] * (1.f/65536.f) - mu1*mu1;
    float a1 = g1w[c0+1] * rsqrtf(var1 + EPSV);
    float bb1 = b1w[c0+1] - mu1*a1;
    float pe0 = g_pe[n*64 + c0], pe1 = g_pe[n*64 + c0 + 1];
    for (int r = r0; r < 64; r += 8) {
        float y0 = 0.f, y1 = 0.f;
        #pragma unroll
        for (int k = 0; k < 7; ++k) { y0 += sx[r+k]*w0[k]; y1 += sx[r+k]*w1[k]; }
        float v0 = fmaxf(a0*y0 + bb0, 0.f) + pe0;
        float v1 = fmaxf(a1*y1 + bb1, 0.f) + pe1;
        store_h2v(g_h0, (long long)(b*64 + r)*64 + c0, v0, v1);
    }
}

// ---------------- fp32 SIMT GEMM (conv3 only) ----------------
__global__ void k_gemm(const float* __restrict__ Aall, const float* __restrict__ Ball,
                       float* __restrict__ Call,
                       int M, int N, int K, int Tout, int Tin, int rowC)
{
    const float* A = Aall;
    const float* B = Ball;

    __shared__ __align__(16) float As[16][68];
    __shared__ __align__(16) float Bs[16][68];

    int tid = threadIdx.x;
    int tx = tid & 15, ty = tid >> 4;
    int m0 = blockIdx.y * 64;
    int n0 = blockIdx.x * 64;

    int abase[4]; bool aok[4];
    #pragma unroll
    for (int p = 0; p < 4; ++p) {
        int row = m0 + p*16 + (tid >> 4);
        aok[p] = (row < M);
        abase[p] = aok[p] ? ((row / Tout) * Tin + (row % Tout)) * rowC : 0;
    }
    int akk = tid & 15;

    float acc[4][4] = {};

    for (int k0 = 0; k0 < K; k0 += 16) {
        #pragma unroll
        for (int p = 0; p < 4; ++p) {
            float v = aok[p] ? A[abase[p] + k0 + akk] : 0.f;
            As[akk][p*16 + (tid >> 4)] = v;
        }
        #pragma unroll
        for (int p = 0; p < 4; ++p) {
            int kk = p*4 + (tid >> 6);
            Bs[kk][tid & 63] = B[(k0 + kk) * N + n0 + (tid & 63)];
        }
        __syncthreads();
        #pragma unroll
        for (int kk = 0; kk < 16; ++kk) {
            float4 av = *(const float4*)&As[kk][ty*4];
            float4 bv = *(const float4*)&Bs[kk][tx*4];
            float a_[4] = {av.x, av.y, av.z, av.w};
            float b_[4] = {bv.x, bv.y, bv.z, bv.w};
            #pragma unroll
            for (int i = 0; i < 4; ++i)
                #pragma unroll
                for (int j = 0; j < 4; ++j)
                    acc[i][j] += a_[i] * b_[j];
        }
        __syncthreads();
    }

    #pragma unroll
    for (int i = 0; i < 4; ++i) {
        int row = m0 + ty*4 + i;
        if (row >= M) continue;
        #pragma unroll
        for (int j = 0; j < 4; ++j) {
            int col = n0 + tx*4 + j;
            Call[(long long)row * N + col] = acc[i][j];
        }
    }
}

// ---------------- TC aggregation (fp16 single, 1-chain) ----------------------
#define ASTR 72
#define HSTR 264
#define AGGH_SMEM (64*ASTR*2 + 64*HSTR*2)      // 43008

__global__ void __launch_bounds__(256, 2)
k_agg_tc_h16(const __half* __restrict__ H, __half* __restrict__ O, int F)
{
    extern __shared__ char dsm[];
    uint32_t sA  = smem_u32(dsm);
    uint32_t sH  = sA + 64*ASTR*2;

    int g = blockIdx.y;
    int n0 = blockIdx.x * 256;
    int tid = threadIdx.x, lane = tid & 31, wid = tid >> 5;

    const char* Agf = (const char*)(g_Asf + g*4096);
    #pragma unroll
    for (int it = 0; it < 2; ++it) {
        int sid = it*256 + tid;
        int row = sid >> 3, seg = (sid & 7) * 8;
        CP16(sA + (row*ASTR + seg)*2, Agf + (row*64 + seg)*2);
    }
    long long hbase = (long long)(g*64) * F + n0;
    #pragma unroll
    for (int it = 0; it < 8; ++it) {
        int sid = it*256 + tid;
        int row = sid >> 5, seg = (sid & 31) * 8;
        long long go = (hbase + (long long)row*F + seg) * 2;
        CP16(sH + (row*HSTR + seg)*2, (const char*)H + go);
    }
    CP_COMMIT();
    CP_WAIT0();
    __syncthreads();

    float acc[4][4][4] = {};
    int nw = wid * 32;
    uint32_t arow = lane & 15, ahi = (lane >> 4) * 8;

    #pragma unroll
    for (int kk = 0; kk < 4; ++kk) {
        uint32_t ah[4][4];
        uint32_t acol = kk*16 + ahi;
        #pragma unroll
        for (int i = 0; i < 4; ++i)
            LDSM_X4(ah[i][0], ah[i][1], ah[i][2], ah[i][3],
                    sA + ((i*16 + arow)*ASTR + acol)*2);
        uint32_t brow = kk*16 + (lane & 15);
        #pragma unroll
        for (int jp = 0; jp < 2; ++jp) {
            uint32_t bh2[2][2];
            uint32_t bcol = nw + jp*16 + ahi;
            uint32_t t0, t1, t2, t3;
            LDSM_X4T(t0, t1, t2, t3, sH + (brow*HSTR + bcol)*2);
            bh2[0][0] = t0; bh2[0][1] = t1; bh2[1][0] = t2; bh2[1][1] = t3;
            #pragma unroll
            for (int i = 0; i < 4; ++i)
                #pragma unroll
                for (int j2 = 0; j2 < 2; ++j2)
                    MMA16816H(acc[i][jp*2+j2], ah[i], bh2[j2]);
        }
    }

    int rb = lane >> 2;
    int cb = n0 + nw + (lane & 3)*2;
    #pragma unroll
    for (int i = 0; i < 4; ++i)
        #pragma unroll
        for (int j = 0; j < 4; ++j)
            #pragma unroll
            for (int half = 0; half < 2; ++half) {
                int row = i*16 + rb + half*8;
                long long idx = (long long)(g*64 + row) * F + cb + j*8;
                store_h2v(O, idx, acc[i][j][half*2], acc[i][j][half*2+1]);
            }
}

// ---------------- fp16 1-chain GEMM (gcn1/gcn2) -------------------------------
#define KC 32
#define ROWB 64
#define ARR_BYTES (128*ROWB)                // 8192
#define NSTAGE 3
#define STAGE_1 (2*ARR_BYTES)               // 16384

__global__ void __launch_bounds__(256, 2)
k_gemm_tc_h16(const __half* __restrict__ A, const __half* __restrict__ B,
              const float* __restrict__ bias,
              __half* __restrict__ C, int K, int ldc)
{
    extern __shared__ char dsm[];
    uint32_t sbase = smem_u32(dsm);
    int tid = threadIdx.x, lane = tid & 31, wid = tid >> 5;
    int m0 = blockIdx.y * 128, n0 = blockIdx.x * 128;

    long long gA0, gB0, gA1, gB1;
    uint32_t so0, so1;
    {
        int row = tid >> 2, seg = tid & 3;
        gA0 = (long long)(m0 + row) * K + seg*8;
        gB0 = (long long)(n0 + row) * K + seg*8;
        so0 = (uint32_t)(row*ROWB + (seg ^ ((row >> 1) & 3))*16);
        row += 64;
        gA1 = (long long)(m0 + row) * K + seg*8;
        gB1 = (long long)(n0 + row) * K + seg*8;
        so1 = (uint32_t)(row*ROWB + (seg ^ ((row >> 1) & 3))*16);
    }

    int wm = wid & 1, wn = wid >> 1;
    uint32_t aRowB = (uint32_t)(wm*64 + (lane & 15)) * ROWB;
    uint32_t aSub  = lane >> 4;
    uint32_t xorA  = ((lane & 15) >> 1) & 3;
    uint32_t bRowB = (uint32_t)(wn*32 + ((lane >> 4) & 1)*8 + (lane & 7)) * ROWB;
    uint32_t bSub  = (lane >> 3) & 1;
    uint32_t xorB  = ((lane & 7) >> 1) & 3;

    float acc[4][4][4] = {};

    int nc = K >> 5;
    #pragma unroll
    for (int pc = 0; pc < 2; ++pc) {
        uint32_t st = sbase + pc*STAGE_1;
        long long k0 = (long long)pc*KC;
        CP16(st +             so0, (const char*)A + (gA0+k0)*2);
        CP16(st +             so1, (const char*)A + (gA1+k0)*2);
        CP16(st + ARR_BYTES + so0, (const char*)B + (gB0+k0)*2);
        CP16(st + ARR_BYTES + so1, (const char*)B + (gB1+k0)*2);
        CP_COMMIT();
    }

    int scur = 0, snext2 = 2;
    for (int c = 0; c < nc; ++c) {
        CP_WAITG1();
        __syncthreads();

        if (c + 2 < nc) {
            uint32_t st = sbase + snext2*STAGE_1;
            long long k0 = (long long)(c+2)*KC;
            CP16(st +             so0, (const char*)A + (gA0+k0)*2);
            CP16(st +             so1, (const char*)A + (gA1+k0)*2);
            CP16(st + ARR_BYTES + so0, (const char*)B + (gB0+k0)*2);
            CP16(st + ARR_BYTES + so1, (const char*)B + (gB1+k0)*2);
        }
        CP_COMMIT();

        uint32_t st = sbase + scur*STAGE_1;

        #pragma unroll
        for (int k16 = 0; k16 < 2; ++k16) {
            uint32_t physA = (((uint32_t)k16*2 + aSub) ^ xorA) * 16;
            uint32_t physB = (((uint32_t)k16*2 + bSub) ^ xorB) * 16;
            uint32_t ah[4][4];
            #pragma unroll
            for (int i = 0; i < 4; ++i) {
                uint32_t ro = aRowB + i*(16*ROWB) + physA;
                LDSM_X4(ah[i][0], ah[i][1], ah[i][2], ah[i][3], st + ro);
            }
            #pragma unroll
            for (int jj = 0; jj < 2; ++jj) {
                uint32_t bh2[2][2];
                uint32_t ro = bRowB + jj*(16*ROWB) + physB;
                uint32_t t0, t1, t2, t3;
                LDSM_X4(t0, t1, t2, t3, st + ARR_BYTES + ro);
                bh2[0][0] = t0; bh2[0][1] = t1; bh2[1][0] = t2; bh2[1][1] = t3;
                #pragma unroll
                for (int i = 0; i < 4; ++i)
                    #pragma unroll
                    for (int j2 = 0; j2 < 2; ++j2)
                        MMA16816H(acc[i][jj*2+j2], ah[i], bh2[j2]);
            }
        }
        scur = (scur == NSTAGE-1) ? 0 : scur+1;
        snext2 = (snext2 == NSTAGE-1) ? 0 : snext2+1;
    }

    int rbase = m0 + wm*64 + (lane >> 2);
    int cbase = n0 + wn*32 + (lane & 3)*2;
    #pragma unroll
    for (int i = 0; i < 4; ++i) {
        #pragma unroll
        for (int j = 0; j < 4; ++j) {
            int gc = cbase + j*8;
            #pragma unroll
            for (int half = 0; half < 2; ++half) {
                long long gr = rbase + i*16 + half*8;
                float v0 = fmaxf(acc[i][j][half*2]     + bias[gc],   0.f);
                float v1 = fmaxf(acc[i][j][half*2 + 1] + bias[gc+1], 0.f);
                store_h2v(C, gr * ldc + gc, v0, v1);
            }
        }
    }
}

// ---------------- sliding-window conv2 (fp16 1-chain, 64-k chunks) -----------
// A-group = 64 channels (p=0..3), loaded once per p, reused over 7 taps.
// 28 iterations of KC=64. Rows are 128B; swizzle phys = chunk ^ (row & 7).
#define CW_ROWB 128
#define CW_ASPL (144*CW_ROWB)              // 18432
#define CW_BSPL (128*CW_ROWB)              // 16384
#define CW_BBASE (2*CW_ASPL)               // 36864
#define CW_SMEM (CW_BBASE + 4*CW_BSPL)     // 102400
#define CW_NC 28

__global__ void __launch_bounds__(256, 2)
k_conv2_sw()
{
    extern __shared__ char dsm[];
    __shared__ float s_sum[128], s_sq[128];
    uint32_t sb = smem_u32(dsm);
    int tid = threadIdx.x, lane = tid & 31, wid = tid >> 5;
    int n = blockIdx.x;

    // zero A pad rows 128..143 in both A stages (2 x 16 rows x 8 segs = 256)
    {
        int arr = tid >> 7;
        int off = tid & 127;
        int row = 128 + (off >> 3);
        int seg = off & 7;
        *(uint4*)(dsm + arr*CW_ASPL + row*CW_ROWB + seg*16) = make_uint4(0,0,0,0);
    }

    long long abase = (long long)n * 32768;   // n*128*256

    int wm = wid & 1, wn = wid >> 1;
    uint32_t aRowT = (uint32_t)(wm*64 + (lane & 15));
    uint32_t aSub  = lane >> 4;
    uint32_t bRow  = (uint32_t)(wn*32 + ((lane >> 4) & 1)*8 + (lane & 7));
    uint32_t bSub  = (lane >> 3) & 1;
    uint32_t xorB  = bRow & 7;

    float acc[4][4][4] = {};

    // prologue: c = 0,1,2  (p=0, tap=c); A group 0 with c=0
    #pragma unroll
    for (int pc = 0; pc < 3; ++pc) {
        if (pc == 0) {
            #pragma unroll
            for (int it = 0; it < 4; ++it) {
                int sid = it*256 + tid;
                int row = sid >> 3, seg = sid & 7;
                int phys = seg ^ (row & 7);
                CP16(sb + row*CW_ROWB + phys*16,
                     (const char*)g_h2 + (abase + (long long)row*256 + seg*8)*2);
            }
        }
        #pragma unroll
        for (int it = 0; it < 4; ++it) {
            int sid = it*256 + tid;
            int row = sid >> 3, seg = sid & 7;
            int phys = seg ^ (row & 7);
            CP16(sb + CW_BBASE + pc*CW_BSPL + row*CW_ROWB + phys*16,
                 (const char*)g_W2t + ((long long)row*1792 + pc*256 + seg*8)*2);
        }
        CP_COMMIT();
    }

    int p = 0, tap = 0;
    for (int c = 0; c < CW_NC; ++c) {
        CP_WAITG2();
        __syncthreads();

        int cn = c + 3;
        if (cn < CW_NC) {
            int pn = cn / 7, tapn = cn - pn*7;
            if (tapn == 0) {
                uint32_t ast = sb + (pn & 1)*CW_ASPL;
                long long ac = abase + pn*64;
                #pragma unroll
                for (int it = 0; it < 4; ++it) {
                    int sid = it*256 + tid;
                    int row = sid >> 3, seg = sid & 7;
                    int phys = seg ^ (row & 7);
                    CP16(ast + row*CW_ROWB + phys*16,
                         (const char*)g_h2 + (ac + (long long)row*256 + seg*8)*2);
                }
            }
            uint32_t bst = sb + CW_BBASE + (cn & 3)*CW_BSPL;
            long long bc = (long long)tapn*256 + pn*64;
            #pragma unroll
            for (int it = 0; it < 4; ++it) {
                int sid = it*256 + tid;
                int row = sid >> 3, seg = sid & 7;
                int phys = seg ^ (row & 7);
                CP16(bst + row*CW_ROWB + phys*16,
                     (const char*)g_W2t + ((long long)row*1792 + bc + seg*8)*2);
            }
        }
        CP_COMMIT();

        uint32_t ast = sb + (p & 1)*CW_ASPL;
        uint32_t bst = sb + CW_BBASE + (c & 3)*CW_BSPL;
        uint32_t arow = aRowT + tap;
        uint32_t xorA = arow & 7;
        uint32_t aBase = arow * CW_ROWB;

        #pragma unroll
        for (int k16 = 0; k16 < 4; ++k16) {
            uint32_t physA = (((uint32_t)k16*2 + aSub) ^ xorA) * 16;
            uint32_t physB = (((uint32_t)k16*2 + bSub) ^ xorB) * 16;
            uint32_t ah[4][4];
            #pragma unroll
            for (int i = 0; i < 4; ++i) {
                uint32_t ro = aBase + i*(16*CW_ROWB) + physA;
                LDSM_X4(ah[i][0], ah[i][1], ah[i][2], ah[i][3], ast + ro);
            }
            #pragma unroll
            for (int jj = 0; jj < 2; ++jj) {
                uint32_t bh2[2][2];
                uint32_t ro = bRow*CW_ROWB + jj*(16*CW_ROWB) + physB;
                uint32_t t0, t1, t2, t3;
                LDSM_X4(t0, t1, t2, t3, bst + ro);
                bh2[0][0] = t0; bh2[0][1] = t1; bh2[1][0] = t2; bh2[1][1] = t3;
                #pragma unroll
                for (int i = 0; i < 4; ++i)
                    #pragma unroll
                    for (int j2 = 0; j2 < 2; ++j2)
                        MMA16816H(acc[i][jj*2+j2], ah[i], bh2[j2]);
            }
        }
        if (++tap == 7) { tap = 0; ++p; }
    }

    __syncthreads();
    if (tid < 128) { s_sum[tid] = 0.f; s_sq[tid] = 0.f; }
    __syncthreads();

    float psum[8] = {}, psq[8] = {};
    int rloc = wm*64 + (lane >> 2);
    int cbase = wn*32 + (lane & 3)*2;
    #pragma unroll
    for (int i = 0; i < 4; ++i) {
        #pragma unroll
        for (int j = 0; j < 4; ++j) {
            int gc = cbase + j*8;
            #pragma unroll
            for (int half = 0; half < 2; ++half) {
                int lr = rloc + i*16 + half*8;
                if (lr < 122) {
                    float v0 = acc[i][j][half*2], v1 = acc[i][j][half*2 + 1];
                    long long idx = (long long)(n*122 + lr)*128 + gc;
                    store_h2v(g_y2h, idx, v0, v1);
                    psum[j*2]   += v0;  psq[j*2]   += v0*v0;
                    psum[j*2+1] += v1;  psq[j*2+1] += v1*v1;
                }
            }
        }
    }
    #pragma unroll
    for (int j = 0; j < 4; ++j) {
        atomicAdd(&s_sum[cbase + j*8],     psum[j*2]);
        atomicAdd(&s_sum[cbase + j*8 + 1], psum[j*2+1]);
        atomicAdd(&s_sq[cbase + j*8],      psq[j*2]);
        atomicAdd(&s_sq[cbase + j*8 + 1],  psq[j*2+1]);
    }
    __syncthreads();
    if (tid < 128) {
        atomicAdd(&g_s2[tid],  s_sum[tid]);
        atomicAdd(&g_sq2[tid], s_sq[tid]);
    }
}

// ---------------- pool / BN3 / tail ----------------
__global__ void k_pool(const float* __restrict__ g2w, const float* __restrict__ b2w) {
    int c = threadIdx.x;
    int chunk = blockIdx.x;
    int tp = blockIdx.y;
    int g = blockIdx.z;
    float mu  = g_s2[c]  * (1.f/62464.f);
    float var = g_sq2[c] * (1.f/62464.f) - mu*mu;
    float a = g2w[c] * rsqrtf(var + EPSV);
    float bb = b2w[c] - mu*a;
    float acc = 0.f;
    for (int nl = 0; nl < 16; ++nl) {
        int n = g*64 + chunk*16 + nl;
        const __half* p = &g_y2h[(n*122 + tp*4)*128 + c];
        float s4 = __half2float(p[0]) + __half2float(p[128])
                 + __half2float(p[256]) + __half2float(p[384]);
        acc += fmaxf(a * (s4 * 0.25f) + bb, 0.f);
    }
    atomicAdd(&g_gbuf[(g*30 + tp)*128 + c], acc * (1.f/64.f));
}

__global__ void k_bn3stats() {
    __shared__ float red[256];
    int tid = threadIdx.x;
    int c = tid & 127, r0 = tid >> 7;
    float ls = 0.f, lq = 0.f;
    for (int r = r0; r < 224; r += 2) { float v = g_y3[r*128 + c]; ls += v; lq += v*v; }
    red[tid] = ls; __syncthreads();
    float ssum = 0.f;
    if (tid < 128) ssum = red[tid] + red[tid+128];
    __syncthreads();
    red[tid] = lq; __syncthreads();
    if (tid < 128) {
        float q = red[tid] + red[tid+128];
        float mu = ssum * (1.f/224.f);
        float var = q * (1.f/224.f) - mu*mu;
        g_mu3[tid] = mu;
        g_rs3[tid] = rsqrtf(var + EPSV);
    }
}

__global__ void k_tail(const float* __restrict__ g3w, const float* __restrict__ b3w,
                       const float* __restrict__ Wd, const float* __restrict__ bd,
                       float* __restrict__ out) {
    __shared__ float gg[896];
    __shared__ float slog[4];
    int b = blockIdx.x, tid = threadIdx.x;
    int c = tid;
    float a = g3w[c] * g_rs3[c];
    float bb = b3w[c] - g_mu3[c]*a;
    #pragma unroll
    for (int tp = 0; tp < 7; ++tp) {
        const float* p = &g_y3[(b*28 + tp*4)*128 + c];
        float s4 = (p[0] + p[128] + p[256] + p[384]) * 0.25f;
        gg[tp*128 + c] = fmaxf(a*s4 + bb, 0.f);
    }
    __syncthreads();
    int w = tid >> 5, lane = tid & 31;
    float s = 0.f;
    for (int i = lane; i < 896; i += 32) s += gg[i] * Wd[i*4 + w];
    #pragma unroll
    for (int off = 16; off; off >>= 1) s += __shfl_xor_sync(0xffffffffu, s, off);
    if (lane == 0) slog[w] = s + bd[w];
    __syncthreads();
    if (tid == 0) {
        float m = fmaxf(fmaxf(slog[0], slog[1]), fmaxf(slog[2], slog[3]));
        float se = expf(slog[0]-m)+expf(slog[1]-m)+expf(slog[2]-m)+expf(slog[3]-m);
        float lse = logf(se);
        #pragma unroll
        for (int j = 0; j < 4; ++j) out[b*4 + j] = slog[j] - m - lse;
    }
}

// ---------------- launch ----------------
extern "C" void kernel_launch(void* const* d_in, const int* in_sizes, int n_in,
                              void* d_out, int out_size) {
    const float* x   = (const float*)d_in[0];
    const float* pos = (const float*)d_in[1];
    const int*   ei  = (const int*)d_in[2];
    const float* W1  = (const float*)d_in[4];
    const float* g1  = (const float*)d_in[5];
    const float* b1  = (const float*)d_in[6];
    const float* Wp1 = (const float*)d_in[7];
    const float* bp1 = (const float*)d_in[8];
    const float* Wp2 = (const float*)d_in[9];
    const float* bp2 = (const float*)d_in[10];
    const float* Wg1 = (const float*)d_in[11];
    const float* bg1 = (const float*)d_in[12];
    const float* Wg2 = (const float*)d_in[13];
    const float* bg2 = (const float*)d_in[14];
    const float* W2  = (const float*)d_in[15];
    const float* g2  = (const float*)d_in[16];
    const float* b2  = (const float*)d_in[17];
    const float* W3  = (const float*)d_in[18];
    const float* g3  = (const float*)d_in[19];
    const float* b3  = (const float*)d_in[20];
    const float* Wd  = (const float*)d_in[21];
    const float* bd  = (const float*)d_in[22];
    float* out = (float*)d_out;

    float *pGbuf, *pY3;
    __half *pH0, *pA0, *pH1, *pA1, *pH2, *pWg1f, *pWg2f;
    cudaGetSymbolAddress((void**)&pGbuf, g_gbuf);
    cudaGetSymbolAddress((void**)&pY3,   g_y3);
    cudaGetSymbolAddress((void**)&pH0,   g_h0);
    cudaGetSymbolAddress((void**)&pA0,   g_agg0);
    cudaGetSymbolAddress((void**)&pH1,   g_h1);
    cudaGetSymbolAddress((void**)&pA1,   g_agg1);
    cudaGetSymbolAddress((void**)&pH2,   g_h2);
    cudaGetSymbolAddress((void**)&pWg1f, g_Wg1tf);
    cudaGetSymbolAddress((void**)&pWg2f, g_Wg2tf);

    cudaFuncSetAttribute(k_gemm_tc_h16, cudaFuncAttributeMaxDynamicSharedMemorySize, NSTAGE*STAGE_1);
    cudaFuncSetAttribute(k_agg_tc_h16, cudaFuncAttributeMaxDynamicSharedMemorySize, AGGH_SMEM);
    cudaFuncSetAttribute(k_conv2_sw, cudaFuncAttributeMaxDynamicSharedMemorySize, CW_SMEM);

    k_setup<<<1472, 256>>>(ei, pos, Wp1, bp1, Wp2, bp2, Wg1, Wg2, W2);
    k_conv1stats<<<1024, 256>>>(x, W1);
    k_bn1pe<<<1024, 256>>>(x, W1, g1, b1);

    // agg0 = A @ h0  (fp16 1-chain), F = T*C0 = 8192
    k_agg_tc_h16<<<dim3(32, 8), 256, AGGH_SMEM>>>(pH0, pA0, 8192);
    // gcn1: h1 = relu(agg0 @ Wg1^T + bg1)  (fp16 1-chain)
    k_gemm_tc_h16<<<dim3(2, 512), 256, NSTAGE*STAGE_1>>>(pA0, pWg1f, bg1, pH1, 64, 256);
    // agg1 = A @ h1  (fp16 1-chain), F = T*EMB = 32768
    k_agg_tc_h16<<<dim3(128, 8), 256, AGGH_SMEM>>>(pH1, pA1, 32768);
    // gcn2: h2 = relu(agg1 @ Wg2^T + bg2)  (fp16 1-chain)
    k_gemm_tc_h16<<<dim3(2, 512), 256, NSTAGE*STAGE_1>>>(pA1, pWg2f, bg2, pH2, 256, 256);
    // conv2 sliding-window fp16 1-chain (64-k chunks) + fused BN2 stats
    k_conv2_sw<<<512, 256, CW_SMEM>>>();
    k_pool<<<dim3(4, 30, 8), 128>>>(g2, b2);
    // conv3 (k=3 VALID, 128->128) SIMT
    k_gemm<<<dim3(2, 4, 1), 256>>>(pGbuf, W3, pY3, 224, 128, 384, 28, 30, 128);
    k_bn3stats<<<1, 256>>>();
    k_tail<<<8, 128>>>(g3, b3, Wd, bd, out);
}

// round 17
// speedup vs baseline: 2.2519x; 1.0414x over previous
#include <cuda_runtime.h>
#include <cuda_fp16.h>
#include <math.h>
#include <stdint.h>

#define N_NODES 512
#define TT 128
#define NE 4096
#define C0 64
#define C1 128
#define C2 128
#define EMB 256
#define NG 8
#define EPSV 1e-5f

// ---------------- scratch (device globals; no allocs allowed) ----------------
__device__ __half g_y2h[N_NODES*122*C1];
__device__ float g_gbuf[NG*30*C1];
__device__ float g_y3[NG*28*C2];
__device__ float g_pe[N_NODES*C0];
__device__ float g_s1[C0], g_sq1[C0];
__device__ float g_s2[C1], g_sq2[C1];
__device__ float g_mu3[C2], g_rs3[C2];

// fp16 single buffers
__device__ __half g_Asf[NG*64*64];
__device__ __half g_h0[N_NODES*TT*C0];
__device__ __half g_agg0[N_NODES*TT*C0];
__device__ __half g_h1[N_NODES*TT*EMB];
__device__ __half g_Wg1tf[EMB*C0];       // [256][64]
__device__ __half g_Wg2tf[EMB*EMB];      // [256][256]
__device__ __half g_h2[N_NODES*TT*EMB];
__device__ __half g_W2t[C1*7*EMB];       // [128][1792]

// ---------------- helpers ----------------
__device__ __forceinline__ uint32_t smem_u32(const void* p) {
    uint32_t a;
    asm("{ .reg .u64 t; cvta.to.shared.u64 t, %1; cvt.u32.u64 %0, t; }" : "=r"(a) : "l"(p));
    return a;
}
#define CP16(dst, src) asm volatile("cp.async.cg.shared.global [%0], [%1], 16;" :: "r"(dst), "l"(src))
#define CP_COMMIT()    asm volatile("cp.async.commit_group;" ::: "memory")
#define CP_WAITG1()    asm volatile("cp.async.wait_group 1;" ::: "memory")
#define CP_WAITG2()    asm volatile("cp.async.wait_group 2;" ::: "memory")
#define CP_WAIT0()     asm volatile("cp.async.wait_group 0;" ::: "memory")
#define LDSM_X4(r0, r1, r2, r3, addr) \
    asm volatile("ldmatrix.sync.aligned.m8n8.x4.shared.b16 {%0,%1,%2,%3}, [%4];" \
        : "=r"(r0), "=r"(r1), "=r"(r2), "=r"(r3) : "r"(addr))
#define LDSM_X4T(r0, r1, r2, r3, addr) \
    asm volatile("ldmatrix.sync.aligned.m8n8.x4.trans.shared.b16 {%0,%1,%2,%3}, [%4];" \
        : "=r"(r0), "=r"(r1), "=r"(r2), "=r"(r3) : "r"(addr))
#define MMA16816H(d, a, b) \
    asm volatile("mma.sync.aligned.m16n8k16.row.col.f32.f16.f16.f32 " \
        "{%0,%1,%2,%3}, {%4,%5,%6,%7}, {%8,%9}, {%0,%1,%2,%3};" \
        : "+f"((d)[0]), "+f"((d)[1]), "+f"((d)[2]), "+f"((d)[3]) \
        : "r"((a)[0]), "r"((a)[1]), "r"((a)[2]), "r"((a)[3]), "r"((b)[0]), "r"((b)[1]))

__device__ __forceinline__ void store_h2v(__half* H, long long idx, float v0, float v1) {
    __half2 hv; hv.x = __float2half(v0); hv.y = __float2half(v1);
    *(__half2*)&H[idx] = hv;
}

// ---------------- fused setup ----------------
__global__ void k_setup(const int* __restrict__ ei,
                        const float* __restrict__ pos, const float* __restrict__ Wp1,
                        const float* __restrict__ bp1, const float* __restrict__ Wp2,
                        const float* __restrict__ bp2,
                        const float* __restrict__ Wg1, const float* __restrict__ Wg2,
                        const float* __restrict__ W2) {
    int b = blockIdx.x, tid = threadIdx.x;
    if (b < 8) {
        __shared__ int sdeg[64];
        __shared__ float sA[64*64];
        int g = b;
        if (tid < 64) sdeg[tid] = 1;
        for (int i = tid; i < 4096; i += 256) sA[i] = 0.f;
        __syncthreads();
        int e0 = g*512 + tid;
        atomicAdd(&sdeg[ei[NE + e0] & 63], 1);
        atomicAdd(&sdeg[ei[NE + e0 + 256] & 63], 1);
        __syncthreads();
        #pragma unroll
        for (int it = 0; it < 2; ++it) {
            int e = e0 + it*256;
            int s = ei[e] & 63, d = ei[NE + e] & 63;
            float nr = rsqrtf((float)sdeg[s]) * rsqrtf((float)sdeg[d]);
            atomicAdd(&sA[(d << 6) + s], nr);
        }
        __syncthreads();
        if (tid < 64) atomicAdd(&sA[tid*64 + tid], 1.f/(float)sdeg[tid]);
        __syncthreads();
        for (int i = tid; i < 4096; i += 256)
            g_Asf[g*4096 + i] = __float2half(sA[i]);
    } else if (b < 136) {
        __shared__ float t1[4][64];
        int n = (b - 8)*4 + (tid >> 6);
        int j = tid & 63;
        int sl = tid >> 6;
        float p0 = pos[n*3], p1 = pos[n*3+1], p2 = pos[n*3+2];
        t1[sl][j] = fmaxf(p0*Wp1[j] + p1*Wp1[64+j] + p2*Wp1[128+j] + bp1[j], 0.f);
        __syncthreads();
        float s = bp2[j];
        #pragma unroll 8
        for (int k = 0; k < 64; ++k) s += t1[sl][k]*Wp2[k*64 + j];
        g_pe[n*64 + j] = s;
    } else if (b < 1352) {
        int i = (b - 136)*256 + tid;
        if (i < 16384) {
            int n = i >> 6, k = i & 63;
            g_Wg1tf[i] = __float2half(Wg1[k*256 + n]);
        } else if (i < 81920) {
            int j = i - 16384;
            int n = j >> 8, k = j & 255;
            g_Wg2tf[j] = __float2half(Wg2[k*256 + n]);
        } else if (i < 311296) {
            int j = i - 81920;
            int n = j / 1792, k = j - n*1792;
            g_W2t[j] = __float2half(W2[k*128 + n]);
        }
    } else {
        int i = (b - 1352)*256 + tid;
        if (i < C0) { g_s1[i]=0.f; g_sq1[i]=0.f; }
        if (i < C1) { g_s2[i]=0.f; g_sq2[i]=0.f; }
        if (i < NG*30*C1) g_gbuf[i] = 0.f;
    }
}

__global__ void k_conv1stats(const float* __restrict__ x, const float* __restrict__ W1) {
    __shared__ float sx[70];
    __shared__ float red[256];
    int b = blockIdx.x;
    int n = b >> 1;
    int t0 = (b & 1) * 64;
    int tid = threadIdx.x;
    if (tid < 70) {
        int t = t0 - 3 + tid;
        sx[tid] = (t >= 0 && t < TT) ? x[n*TT + t] : 0.f;
    }
    __syncthreads();
    int c = tid & 63, r0 = tid >> 6;
    float w[7];
    #pragma unroll
    for (int k = 0; k < 7; ++k) w[k] = W1[k*64 + c];
    float ls = 0.f, lq = 0.f;
    for (int rr = r0; rr < 64; rr += 4) {
        float y = 0.f;
        #pragma unroll
        for (int k = 0; k < 7; ++k) y += sx[rr + k] * w[k];
        ls += y; lq += y*y;
    }
    red[tid] = ls; __syncthreads();
    if (tid < 64) atomicAdd(&g_s1[c], red[tid]+red[tid+64]+red[tid+128]+red[tid+192]);
    __syncthreads();
    red[tid] = lq; __syncthreads();
    if (tid < 64) atomicAdd(&g_sq1[c], red[tid]+red[tid+64]+red[tid+128]+red[tid+192]);
}

__global__ void k_bn1pe(const float* __restrict__ x, const float* __restrict__ W1,
                        const float* __restrict__ g1w, const float* __restrict__ b1w) {
    __shared__ float sx[70];
    int b = blockIdx.x;
    int n = b >> 1;
    int t0 = (b & 1) * 64;
    int tid = threadIdx.x;
    if (tid < 70) {
        int t = t0 - 3 + tid;
        sx[tid] = (t >= 0 && t < TT) ? x[n*TT + t] : 0.f;
    }
    __syncthreads();
    int c0 = (tid & 31) * 2;
    int r0 = tid >> 5;
    float w0[7], w1[7];
    #pragma unroll
    for (int k = 0; k < 7; ++k) { w0[k] = W1[k*64 + c0]; w1[k] = W1[k*64 + c0 + 1]; }
    float mu0  = g_s1[c0]   * (1.f/65536.f);
    float var0 = g_sq1[c0]  * (1.f/65536.f) - mu0*mu0;
    float a0 = g1w[c0] * rsqrtf(var0 + EPSV);
    float bb0 = b1w[c0] - mu0*a0;
    float mu1  = g_s1[c0+1]  * (1.f/65536.f);
    float var1 = g_sq1[c0+1] * (1.f/65536.f) - mu1*mu1;
    float a1 = g1w[c0+1] * rsqrtf(var1 + EPSV);
    float bb1 = b1w[c0+1] - mu1*a1;
    float pe0 = g_pe[n*64 + c0], pe1 = g_pe[n*64 + c0 + 1];
    for (int r = r0; r < 64; r += 8) {
        float y0 = 0.f, y1 = 0.f;
        #pragma unroll
        for (int k = 0; k < 7; ++k) { y0 += sx[r+k]*w0[k]; y1 += sx[r+k]*w1[k]; }
        float v0 = fmaxf(a0*y0 + bb0, 0.f) + pe0;
        float v1 = fmaxf(a1*y1 + bb1, 0.f) + pe1;
        store_h2v(g_h0, (long long)(b*64 + r)*64 + c0, v0, v1);
    }
}

// ---------------- fp32 SIMT GEMM (conv3 only) ----------------
__global__ void k_gemm(const float* __restrict__ Aall, const float* __restrict__ Ball,
                       float* __restrict__ Call,
                       int M, int N, int K, int Tout, int Tin, int rowC)
{
    const float* A = Aall;
    const float* B = Ball;

    __shared__ __align__(16) float As[16][68];
    __shared__ __align__(16) float Bs[16][68];

    int tid = threadIdx.x;
    int tx = tid & 15, ty = tid >> 4;
    int m0 = blockIdx.y * 64;
    int n0 = blockIdx.x * 64;

    int abase[4]; bool aok[4];
    #pragma unroll
    for (int p = 0; p < 4; ++p) {
        int row = m0 + p*16 + (tid >> 4);
        aok[p] = (row < M);
        abase[p] = aok[p] ? ((row / Tout) * Tin + (row % Tout)) * rowC : 0;
    }
    int akk = tid & 15;

    float acc[4][4] = {};

    for (int k0 = 0; k0 < K; k0 += 16) {
        #pragma unroll
        for (int p = 0; p < 4; ++p) {
            float v = aok[p] ? A[abase[p] + k0 + akk] : 0.f;
            As[akk][p*16 + (tid >> 4)] = v;
        }
        #pragma unroll
        for (int p = 0; p < 4; ++p) {
            int kk = p*4 + (tid >> 6);
            Bs[kk][tid & 63] = B[(k0 + kk) * N + n0 + (tid & 63)];
        }
        __syncthreads();
        #pragma unroll
        for (int kk = 0; kk < 16; ++kk) {
            float4 av = *(const float4*)&As[kk][ty*4];
            float4 bv = *(const float4*)&Bs[kk][tx*4];
            float a_[4] = {av.x, av.y, av.z, av.w};
            float b_[4] = {bv.x, bv.y, bv.z, bv.w};
            #pragma unroll
            for (int i = 0; i < 4; ++i)
                #pragma unroll
                for (int j = 0; j < 4; ++j)
                    acc[i][j] += a_[i] * b_[j];
        }
        __syncthreads();
    }

    #pragma unroll
    for (int i = 0; i < 4; ++i) {
        int row = m0 + ty*4 + i;
        if (row >= M) continue;
        #pragma unroll
        for (int j = 0; j < 4; ++j) {
            int col = n0 + tx*4 + j;
            Call[(long long)row * N + col] = acc[i][j];
        }
    }
}

// ---------------- TC aggregation agg0 (fp16 single, 1-chain) -----------------
#define ASTR 72
#define HSTR 264
#define AGGH_SMEM (64*ASTR*2 + 64*HSTR*2)      // 43008

__global__ void __launch_bounds__(256, 2)
k_agg_tc_h16(const __half* __restrict__ H, __half* __restrict__ O, int F)
{
    extern __shared__ char dsm[];
    uint32_t sA  = smem_u32(dsm);
    uint32_t sH  = sA + 64*ASTR*2;

    int g = blockIdx.y;
    int n0 = blockIdx.x * 256;
    int tid = threadIdx.x, lane = tid & 31, wid = tid >> 5;

    const char* Agf = (const char*)(g_Asf + g*4096);
    #pragma unroll
    for (int it = 0; it < 2; ++it) {
        int sid = it*256 + tid;
        int row = sid >> 3, seg = (sid & 7) * 8;
        CP16(sA + (row*ASTR + seg)*2, Agf + (row*64 + seg)*2);
    }
    long long hbase = (long long)(g*64) * F + n0;
    #pragma unroll
    for (int it = 0; it < 8; ++it) {
        int sid = it*256 + tid;
        int row = sid >> 5, seg = (sid & 31) * 8;
        long long go = (hbase + (long long)row*F + seg) * 2;
        CP16(sH + (row*HSTR + seg)*2, (const char*)H + go);
    }
    CP_COMMIT();
    CP_WAIT0();
    __syncthreads();

    float acc[4][4][4] = {};
    int nw = wid * 32;
    uint32_t arow = lane & 15, ahi = (lane >> 4) * 8;

    #pragma unroll
    for (int kk = 0; kk < 4; ++kk) {
        uint32_t ah[4][4];
        uint32_t acol = kk*16 + ahi;
        #pragma unroll
        for (int i = 0; i < 4; ++i)
            LDSM_X4(ah[i][0], ah[i][1], ah[i][2], ah[i][3],
                    sA + ((i*16 + arow)*ASTR + acol)*2);
        uint32_t brow = kk*16 + (lane & 15);
        #pragma unroll
        for (int jp = 0; jp < 2; ++jp) {
            uint32_t bh2[2][2];
            uint32_t bcol = nw + jp*16 + ahi;
            uint32_t t0, t1, t2, t3;
            LDSM_X4T(t0, t1, t2, t3, sH + (brow*HSTR + bcol)*2);
            bh2[0][0] = t0; bh2[0][1] = t1; bh2[1][0] = t2; bh2[1][1] = t3;
            #pragma unroll
            for (int i = 0; i < 4; ++i)
                #pragma unroll
                for (int j2 = 0; j2 < 2; ++j2)
                    MMA16816H(acc[i][jp*2+j2], ah[i], bh2[j2]);
        }
    }

    int rb = lane >> 2;
    int cb = n0 + nw + (lane & 3)*2;
    #pragma unroll
    for (int i = 0; i < 4; ++i)
        #pragma unroll
        for (int j = 0; j < 4; ++j)
            #pragma unroll
            for (int half = 0; half < 2; ++half) {
                int row = i*16 + rb + half*8;
                long long idx = (long long)(g*64 + row) * F + cb + j*8;
                store_h2v(O, idx, acc[i][j][half*2], acc[i][j][half*2+1]);
            }
}

// ---------------- fp16 1-chain GEMM (gcn1) ------------------------------------
#define KC 32
#define ROWB 64
#define ARR_BYTES (128*ROWB)                // 8192
#define NSTAGE 3
#define STAGE_1 (2*ARR_BYTES)               // 16384

__global__ void __launch_bounds__(256, 2)
k_gemm_tc_h16(const __half* __restrict__ A, const __half* __restrict__ B,
              const float* __restrict__ bias,
              __half* __restrict__ C, int K, int ldc)
{
    extern __shared__ char dsm[];
    uint32_t sbase = smem_u32(dsm);
    int tid = threadIdx.x, lane = tid & 31, wid = tid >> 5;
    int m0 = blockIdx.y * 128, n0 = blockIdx.x * 128;

    long long gA0, gB0, gA1, gB1;
    uint32_t so0, so1;
    {
        int row = tid >> 2, seg = tid & 3;
        gA0 = (long long)(m0 + row) * K + seg*8;
        gB0 = (long long)(n0 + row) * K + seg*8;
        so0 = (uint32_t)(row*ROWB + (seg ^ ((row >> 1) & 3))*16);
        row += 64;
        gA1 = (long long)(m0 + row) * K + seg*8;
        gB1 = (long long)(n0 + row) * K + seg*8;
        so1 = (uint32_t)(row*ROWB + (seg ^ ((row >> 1) & 3))*16);
    }

    int wm = wid & 1, wn = wid >> 1;
    uint32_t aRowB = (uint32_t)(wm*64 + (lane & 15)) * ROWB;
    uint32_t aSub  = lane >> 4;
    uint32_t xorA  = ((lane & 15) >> 1) & 3;
    uint32_t bRowB = (uint32_t)(wn*32 + ((lane >> 4) & 1)*8 + (lane & 7)) * ROWB;
    uint32_t bSub  = (lane >> 3) & 1;
    uint32_t xorB  = ((lane & 7) >> 1) & 3;

    float acc[4][4][4] = {};

    int nc = K >> 5;
    #pragma unroll
    for (int pc = 0; pc < 2; ++pc) {
        uint32_t st = sbase + pc*STAGE_1;
        long long k0 = (long long)pc*KC;
        CP16(st +             so0, (const char*)A + (gA0+k0)*2);
        CP16(st +             so1, (const char*)A + (gA1+k0)*2);
        CP16(st + ARR_BYTES + so0, (const char*)B + (gB0+k0)*2);
        CP16(st + ARR_BYTES + so1, (const char*)B + (gB1+k0)*2);
        CP_COMMIT();
    }

    int scur = 0, snext2 = 2;
    for (int c = 0; c < nc; ++c) {
        CP_WAITG1();
        __syncthreads();

        if (c + 2 < nc) {
            uint32_t st = sbase + snext2*STAGE_1;
            long long k0 = (long long)(c+2)*KC;
            CP16(st +             so0, (const char*)A + (gA0+k0)*2);
            CP16(st +             so1, (const char*)A + (gA1+k0)*2);
            CP16(st + ARR_BYTES + so0, (const char*)B + (gB0+k0)*2);
            CP16(st + ARR_BYTES + so1, (const char*)B + (gB1+k0)*2);
        }
        CP_COMMIT();

        uint32_t st = sbase + scur*STAGE_1;

        #pragma unroll
        for (int k16 = 0; k16 < 2; ++k16) {
            uint32_t physA = (((uint32_t)k16*2 + aSub) ^ xorA) * 16;
            uint32_t physB = (((uint32_t)k16*2 + bSub) ^ xorB) * 16;
            uint32_t ah[4][4];
            #pragma unroll
            for (int i = 0; i < 4; ++i) {
                uint32_t ro = aRowB + i*(16*ROWB) + physA;
                LDSM_X4(ah[i][0], ah[i][1], ah[i][2], ah[i][3], st + ro);
            }
            #pragma unroll
            for (int jj = 0; jj < 2; ++jj) {
                uint32_t bh2[2][2];
                uint32_t ro = bRowB + jj*(16*ROWB) + physB;
                uint32_t t0, t1, t2, t3;
                LDSM_X4(t0, t1, t2, t3, st + ARR_BYTES + ro);
                bh2[0][0] = t0; bh2[0][1] = t1; bh2[1][0] = t2; bh2[1][1] = t3;
                #pragma unroll
                for (int i = 0; i < 4; ++i)
                    #pragma unroll
                    for (int j2 = 0; j2 < 2; ++j2)
                        MMA16816H(acc[i][jj*2+j2], ah[i], bh2[j2]);
            }
        }
        scur = (scur == NSTAGE-1) ? 0 : scur+1;
        snext2 = (snext2 == NSTAGE-1) ? 0 : snext2+1;
    }

    int rbase = m0 + wm*64 + (lane >> 2);
    int cbase = n0 + wn*32 + (lane & 3)*2;
    #pragma unroll
    for (int i = 0; i < 4; ++i) {
        #pragma unroll
        for (int j = 0; j < 4; ++j) {
            int gc = cbase + j*8;
            #pragma unroll
            for (int half = 0; half < 2; ++half) {
                long long gr = rbase + i*16 + half*8;
                float v0 = fmaxf(acc[i][j][half*2]     + bias[gc],   0.f);
                float v1 = fmaxf(acc[i][j][half*2 + 1] + bias[gc+1], 0.f);
                store_h2v(C, gr * ldc + gc, v0, v1);
            }
        }
    }
}

// ---------------- fused agg1 + gcn2: block = (timestep, graph) ----------------
// Stage 1: S = A(64x64) @ h1[g, :, t, :]  (64 nodes x 256 EMB)
// Stage 2: h2 = relu(S @ Wg2^T + bg2)     (M=64, K=256, N=256)
// S stored in-place over the H SMEM tile (each warp overwrites only its own cols).
// Wg2 streamed in 8 K-chunks of 32 via 3-stage cp.async ring (prefetch in prologue).
#define FG_SA_B 9216                        // 64*72*2
#define FG_SH_B 33792                       // 64*264*2
#define FG_BROWB 80                         // 32 halves + 8 pad (conflict-free)
#define FG_BSPL (256*FG_BROWB)              // 20480
#define FG_SMEM (FG_SA_B + FG_SH_B + 3*FG_BSPL)   // 104448

__global__ void __launch_bounds__(256, 2)
k_agg_gcn2(const __half* __restrict__ H1, const __half* __restrict__ Wg2,
           const float* __restrict__ bias, __half* __restrict__ H2)
{
    extern __shared__ char dsm[];
    uint32_t sA = smem_u32(dsm);
    uint32_t sH = sA + FG_SA_B;
    uint32_t sB = sA + FG_SA_B + FG_SH_B;

    int t = blockIdx.x, g = blockIdx.y;
    int tid = threadIdx.x, lane = tid & 31, wid = tid >> 5;

    // group 1: adjacency + H tile (h1 rows for 64 nodes at timestep t)
    const char* Agf = (const char*)(g_Asf + g*4096);
    #pragma unroll
    for (int it = 0; it < 2; ++it) {
        int sid = it*256 + tid;
        int row = sid >> 3, seg = (sid & 7) * 8;
        CP16(sA + (row*ASTR + seg)*2, Agf + (row*64 + seg)*2);
    }
    long long hb = (((long long)(g*64))*128 + t) * 256;   // + node*32768
    #pragma unroll
    for (int it = 0; it < 8; ++it) {
        int sid = it*256 + tid;
        int row = sid >> 5, seg = (sid & 31) * 8;
        CP16(sH + (row*HSTR + seg)*2,
             (const char*)H1 + (hb + (long long)row*32768 + seg)*2);
    }
    CP_COMMIT();
    // groups 2,3: B chunks 0,1 (Wg2 [256 n][K chunk 32])
    #pragma unroll
    for (int pc = 0; pc < 2; ++pc) {
        #pragma unroll
        for (int it = 0; it < 4; ++it) {
            int sid = it*256 + tid;
            int row = sid >> 2, seg = sid & 3;
            CP16(sB + pc*FG_BSPL + row*FG_BROWB + seg*16,
                 (const char*)Wg2 + ((long long)row*256 + pc*32 + seg*8)*2);
        }
        CP_COMMIT();
    }
    CP_WAITG2();            // A+H done (B0/B1 may be in flight)
    __syncthreads();

    // ---- stage 1: aggregation ----
    float acc[4][4][4] = {};
    int nw = wid * 32;
    uint32_t arow = lane & 15, ahi = (lane >> 4) * 8;

    #pragma unroll
    for (int kk = 0; kk < 4; ++kk) {
        uint32_t ah[4][4];
        uint32_t acol = kk*16 + ahi;
        #pragma unroll
        for (int i = 0; i < 4; ++i)
            LDSM_X4(ah[i][0], ah[i][1], ah[i][2], ah[i][3],
                    sA + ((i*16 + arow)*ASTR + acol)*2);
        uint32_t brow = kk*16 + (lane & 15);
        #pragma unroll
        for (int jp = 0; jp < 2; ++jp) {
            uint32_t bh2[2][2];
            uint32_t bcol = nw + jp*16 + ahi;
            uint32_t t0, t1, t2, t3;
            LDSM_X4T(t0, t1, t2, t3, sH + (brow*HSTR + bcol)*2);
            bh2[0][0] = t0; bh2[0][1] = t1; bh2[1][0] = t2; bh2[1][1] = t3;
            #pragma unroll
            for (int i = 0; i < 4; ++i)
                #pragma unroll
                for (int j2 = 0; j2 < 2; ++j2)
                    MMA16816H(acc[i][jp*2+j2], ah[i], bh2[j2]);
        }
    }

    // store S (fp16) in place over H tile: warp writes only its own 32 cols
    {
        int rb = lane >> 2;
        int cb = nw + (lane & 3)*2;
        #pragma unroll
        for (int i = 0; i < 4; ++i)
            #pragma unroll
            for (int j = 0; j < 4; ++j)
                #pragma unroll
                for (int half = 0; half < 2; ++half) {
                    int row = i*16 + rb + half*8;
                    int col = cb + j*8;
                    __half2 hv;
                    hv.x = __float2half(acc[i][j][half*2]);
                    hv.y = __float2half(acc[i][j][half*2+1]);
                    *(__half2*)(dsm + FG_SA_B + row*(HSTR*2) + col*2) = hv;
                }
    }
    __syncthreads();

    // ---- stage 2: S(64x256) @ Wg2^T ----
    #pragma unroll
    for (int i = 0; i < 4; ++i)
        #pragma unroll
        for (int j = 0; j < 4; ++j)
            #pragma unroll
            for (int q = 0; q < 4; ++q)
                acc[i][j][q] = 0.f;

    uint32_t aSub = lane >> 4;
    uint32_t bRow = (uint32_t)(nw + ((lane >> 4) & 1)*8 + (lane & 7));
    uint32_t bSub = (lane >> 3) & 1;

    for (int kb = 0; kb < 8; ++kb) {
        CP_WAITG1();
        __syncthreads();

        if (kb + 2 < 8) {
            int slot = (kb + 2) % 3;
            #pragma unroll
            for (int it = 0; it < 4; ++it) {
                int sid = it*256 + tid;
                int row = sid >> 2, seg = sid & 3;
                CP16(sB + slot*FG_BSPL + row*FG_BROWB + seg*16,
                     (const char*)Wg2 + ((long long)row*256 + (kb+2)*32 + seg*8)*2);
            }
        }
        CP_COMMIT();

        uint32_t bst = sB + (kb % 3)*FG_BSPL;

        #pragma unroll
        for (int k16 = 0; k16 < 2; ++k16) {
            uint32_t physA = (uint32_t)kb*64 + ((uint32_t)k16*2 + aSub)*16;
            uint32_t physB = ((uint32_t)k16*2 + bSub)*16;
            uint32_t ah[4][4];
            #pragma unroll
            for (int i = 0; i < 4; ++i)
                LDSM_X4(ah[i][0], ah[i][1], ah[i][2], ah[i][3],
                        sH + (arow + i*16)*(HSTR*2) + physA);
            #pragma unroll
            for (int jj = 0; jj < 2; ++jj) {
                uint32_t bh2[2][2];
                uint32_t ro = bRow*FG_BROWB + jj*(16*FG_BROWB) + physB;
                uint32_t t0, t1, t2, t3;
                LDSM_X4(t0, t1, t2, t3, bst + ro);
                bh2[0][0] = t0; bh2[0][1] = t1; bh2[1][0] = t2; bh2[1][1] = t3;
                #pragma unroll
                for (int i = 0; i < 4; ++i)
                    #pragma unroll
                    for (int j2 = 0; j2 < 2; ++j2)
                        MMA16816H(acc[i][jj*2+j2], ah[i], bh2[j2]);
            }
        }
    }

    // epilogue: bias + relu -> h2[node][t][c]
    {
        int rb = lane >> 2;
        int cb = nw + (lane & 3)*2;
        #pragma unroll
        for (int i = 0; i < 4; ++i)
            #pragma unroll
            for (int j = 0; j < 4; ++j) {
                int gc = cb + j*8;
                #pragma unroll
                for (int half = 0; half < 2; ++half) {
                    int row = rb + i*16 + half*8;
                    float v0 = fmaxf(acc[i][j][half*2]     + bias[gc],   0.f);
                    float v1 = fmaxf(acc[i][j][half*2 + 1] + bias[gc+1], 0.f);
                    long long idx = (((long long)(g*64 + row))*128 + t)*256 + gc;
                    store_h2v(H2, idx, v0, v1);
                }
            }
    }
}

// ---------------- sliding-window conv2 (fp16 1-chain, 64-k chunks) -----------
#define CW_ROWB 128
#define CW_ASPL (144*CW_ROWB)
#define CW_BSPL (128*CW_ROWB)
#define CW_BBASE (2*CW_ASPL)
#define CW_SMEM (CW_BBASE + 4*CW_BSPL)
#define CW_NC 28

__global__ void __launch_bounds__(256, 2)
k_conv2_sw()
{
    extern __shared__ char dsm[];
    __shared__ float s_sum[128], s_sq[128];
    uint32_t sb = smem_u32(dsm);
    int tid = threadIdx.x, lane = tid & 31, wid = tid >> 5;
    int n = blockIdx.x;

    {
        int arr = tid >> 7;
        int off = tid & 127;
        int row = 128 + (off >> 3);
        int seg = off & 7;
        *(uint4*)(dsm + arr*CW_ASPL + row*CW_ROWB + seg*16) = make_uint4(0,0,0,0);
    }

    long long abase = (long long)n * 32768;

    int wm = wid & 1, wn = wid >> 1;
    uint32_t aRowT = (uint32_t)(wm*64 + (lane & 15));
    uint32_t aSub  = lane >> 4;
    uint32_t bRow  = (uint32_t)(wn*32 + ((lane >> 4) & 1)*8 + (lane & 7));
    uint32_t bSub  = (lane >> 3) & 1;
    uint32_t xorB  = bRow & 7;

    float acc[4][4][4] = {};

    #pragma unroll
    for (int pc = 0; pc < 3; ++pc) {
        if (pc == 0) {
            #pragma unroll
            for (int it = 0; it < 4; ++it) {
                int sid = it*256 + tid;
                int row = sid >> 3, seg = sid & 7;
                int phys = seg ^ (row & 7);
                CP16(sb + row*CW_ROWB + phys*16,
                     (const char*)g_h2 + (abase + (long long)row*256 + seg*8)*2);
            }
        }
        #pragma unroll
        for (int it = 0; it < 4; ++it) {
            int sid = it*256 + tid;
            int row = sid >> 3, seg = sid & 7;
            int phys = seg ^ (row & 7);
            CP16(sb + CW_BBASE + pc*CW_BSPL + row*CW_ROWB + phys*16,
                 (const char*)g_W2t + ((long long)row*1792 + pc*256 + seg*8)*2);
        }
        CP_COMMIT();
    }

    int p = 0, tap = 0;
    for (int c = 0; c < CW_NC; ++c) {
        CP_WAITG2();
        __syncthreads();

        int cn = c + 3;
        if (cn < CW_NC) {
            int pn = cn / 7, tapn = cn - pn*7;
            if (tapn == 0) {
                uint32_t ast = sb + (pn & 1)*CW_ASPL;
                long long ac = abase + pn*64;
                #pragma unroll
                for (int it = 0; it < 4; ++it) {
                    int sid = it*256 + tid;
                    int row = sid >> 3, seg = sid & 7;
                    int phys = seg ^ (row & 7);
                    CP16(ast + row*CW_ROWB + phys*16,
                         (const char*)g_h2 + (ac + (long long)row*256 + seg*8)*2);
                }
            }
            uint32_t bst = sb + CW_BBASE + (cn & 3)*CW_BSPL;
            long long bc = (long long)tapn*256 + pn*64;
            #pragma unroll
            for (int it = 0; it < 4; ++it) {
                int sid = it*256 + tid;
                int row = sid >> 3, seg = sid & 7;
                int phys = seg ^ (row & 7);
                CP16(bst + row*CW_ROWB + phys*16,
                     (const char*)g_W2t + ((long long)row*1792 + bc + seg*8)*2);
            }
        }
        CP_COMMIT();

        uint32_t ast = sb + (p & 1)*CW_ASPL;
        uint32_t bst = sb + CW_BBASE + (c & 3)*CW_BSPL;
        uint32_t arow = aRowT + tap;
        uint32_t xorA = arow & 7;
        uint32_t aBase = arow * CW_ROWB;

        #pragma unroll
        for (int k16 = 0; k16 < 4; ++k16) {
            uint32_t physA = (((uint32_t)k16*2 + aSub) ^ xorA) * 16;
            uint32_t physB = (((uint32_t)k16*2 + bSub) ^ xorB) * 16;
            uint32_t ah[4][4];
            #pragma unroll
            for (int i = 0; i < 4; ++i) {
                uint32_t ro = aBase + i*(16*CW_ROWB) + physA;
                LDSM_X4(ah[i][0], ah[i][1], ah[i][2], ah[i][3], ast + ro);
            }
            #pragma unroll
            for (int jj = 0; jj < 2; ++jj) {
                uint32_t bh2[2][2];
                uint32_t ro = bRow*CW_ROWB + jj*(16*CW_ROWB) + physB;
                uint32_t t0, t1, t2, t3;
                LDSM_X4(t0, t1, t2, t3, bst + ro);
                bh2[0][0] = t0; bh2[0][1] = t1; bh2[1][0] = t2; bh2[1][1] = t3;
                #pragma unroll
                for (int i = 0; i < 4; ++i)
                    #pragma unroll
                    for (int j2 = 0; j2 < 2; ++j2)
                        MMA16816H(acc[i][jj*2+j2], ah[i], bh2[j2]);
            }
        }
        if (++tap == 7) { tap = 0; ++p; }
    }

    __syncthreads();
    if (tid < 128) { s_sum[tid] = 0.f; s_sq[tid] = 0.f; }
    __syncthreads();

    float psum[8] = {}, psq[8] = {};
    int rloc = wm*64 + (lane >> 2);
    int cbase = wn*32 + (lane & 3)*2;
    #pragma unroll
    for (int i = 0; i < 4; ++i) {
        #pragma unroll
        for (int j = 0; j < 4; ++j) {
            int gc = cbase + j*8;
            #pragma unroll
            for (int half = 0; half < 2; ++half) {
                int lr = rloc + i*16 + half*8;
                if (lr < 122) {
                    float v0 = acc[i][j][half*2], v1 = acc[i][j][half*2 + 1];
                    long long idx = (long long)(n*122 + lr)*128 + gc;
                    store_h2v(g_y2h, idx, v0, v1);
                    psum[j*2]   += v0;  psq[j*2]   += v0*v0;
                    psum[j*2+1] += v1;  psq[j*2+1] += v1*v1;
                }
            }
        }
    }
    #pragma unroll
    for (int j = 0; j < 4; ++j) {
        atomicAdd(&s_sum[cbase + j*8],     psum[j*2]);
        atomicAdd(&s_sum[cbase + j*8 + 1], psum[j*2+1]);
        atomicAdd(&s_sq[cbase + j*8],      psq[j*2]);
        atomicAdd(&s_sq[cbase + j*8 + 1],  psq[j*2+1]);
    }
    __syncthreads();
    if (tid < 128) {
        atomicAdd(&g_s2[tid],  s_sum[tid]);
        atomicAdd(&g_sq2[tid], s_sq[tid]);
    }
}

// ---------------- pool / BN3 / tail ----------------
__global__ void k_pool(const float* __restrict__ g2w, const float* __restrict__ b2w) {
    int c = threadIdx.x;
    int chunk = blockIdx.x;
    int tp = blockIdx.y;
    int g = blockIdx.z;
    float mu  = g_s2[c]  * (1.f/62464.f);
    float var = g_sq2[c] * (1.f/62464.f) - mu*mu;
    float a = g2w[c] * rsqrtf(var + EPSV);
    float bb = b2w[c] - mu*a;
    float acc = 0.f;
    for (int nl = 0; nl < 16; ++nl) {
        int n = g*64 + chunk*16 + nl;
        const __half* p = &g_y2h[(n*122 + tp*4)*128 + c];
        float s4 = __half2float(p[0]) + __half2float(p[128])
                 + __half2float(p[256]) + __half2float(p[384]);
        acc += fmaxf(a * (s4 * 0.25f) + bb, 0.f);
    }
    atomicAdd(&g_gbuf[(g*30 + tp)*128 + c], acc * (1.f/64.f));
}

__global__ void k_bn3stats() {
    __shared__ float red[256];
    int tid = threadIdx.x;
    int c = tid & 127, r0 = tid >> 7;
    float ls = 0.f, lq = 0.f;
    for (int r = r0; r < 224; r += 2) { float v = g_y3[r*128 + c]; ls += v; lq += v*v; }
    red[tid] = ls; __syncthreads();
    float ssum = 0.f;
    if (tid < 128) ssum = red[tid] + red[tid+128];
    __syncthreads();
    red[tid] = lq; __syncthreads();
    if (tid < 128) {
        float q = red[tid] + red[tid+128];
        float mu = ssum * (1.f/224.f);
        float var = q * (1.f/224.f) - mu*mu;
        g_mu3[tid] = mu;
        g_rs3[tid] = rsqrtf(var + EPSV);
    }
}

__global__ void k_tail(const float* __restrict__ g3w, const float* __restrict__ b3w,
                       const float* __restrict__ Wd, const float* __restrict__ bd,
                       float* __restrict__ out) {
    __shared__ float gg[896];
    __shared__ float slog[4];
    int b = blockIdx.x, tid = threadIdx.x;
    int c = tid;
    float a = g3w[c] * g_rs3[c];
    float bb = b3w[c] - g_mu3[c]*a;
    #pragma unroll
    for (int tp = 0; tp < 7; ++tp) {
        const float* p = &g_y3[(b*28 + tp*4)*128 + c];
        float s4 = (p[0] + p[128] + p[256] + p[384]) * 0.25f;
        gg[tp*128 + c] = fmaxf(a*s4 + bb, 0.f);
    }
    __syncthreads();
    int w = tid >> 5, lane = tid & 31;
    float s = 0.f;
    for (int i = lane; i < 896; i += 32) s += gg[i] * Wd[i*4 + w];
    #pragma unroll
    for (int off = 16; off; off >>= 1) s += __shfl_xor_sync(0xffffffffu, s, off);
    if (lane == 0) slog[w] = s + bd[w];
    __syncthreads();
    if (tid == 0) {
        float m = fmaxf(fmaxf(slog[0], slog[1]), fmaxf(slog[2], slog[3]));
        float se = expf(slog[0]-m)+expf(slog[1]-m)+expf(slog[2]-m)+expf(slog[3]-m);
        float lse = logf(se);
        #pragma unroll
        for (int j = 0; j < 4; ++j) out[b*4 + j] = slog[j] - m - lse;
    }
}

// ---------------- launch ----------------
extern "C" void kernel_launch(void* const* d_in, const int* in_sizes, int n_in,
                              void* d_out, int out_size) {
    const float* x   = (const float*)d_in[0];
    const float* pos = (const float*)d_in[1];
    const int*   ei  = (const int*)d_in[2];
    const float* W1  = (const float*)d_in[4];
    const float* g1  = (const float*)d_in[5];
    const float* b1  = (const float*)d_in[6];
    const float* Wp1 = (const float*)d_in[7];
    const float* bp1 = (const float*)d_in[8];
    const float* Wp2 = (const float*)d_in[9];
    const float* bp2 = (const float*)d_in[10];
    const float* Wg1 = (const float*)d_in[11];
    const float* bg1 = (const float*)d_in[12];
    const float* Wg2 = (const float*)d_in[13];
    const float* bg2 = (const float*)d_in[14];
    const float* W2  = (const float*)d_in[15];
    const float* g2  = (const float*)d_in[16];
    const float* b2  = (const float*)d_in[17];
    const float* W3  = (const float*)d_in[18];
    const float* g3  = (const float*)d_in[19];
    const float* b3  = (const float*)d_in[20];
    const float* Wd  = (const float*)d_in[21];
    const float* bd  = (const float*)d_in[22];
    float* out = (float*)d_out;

    float *pGbuf, *pY3;
    __half *pH0, *pA0, *pH1, *pH2, *pWg1f, *pWg2f;
    cudaGetSymbolAddress((void**)&pGbuf, g_gbuf);
    cudaGetSymbolAddress((void**)&pY3,   g_y3);
    cudaGetSymbolAddress((void**)&pH0,   g_h0);
    cudaGetSymbolAddress((void**)&pA0,   g_agg0);
    cudaGetSymbolAddress((void**)&pH1,   g_h1);
    cudaGetSymbolAddress((void**)&pH2,   g_h2);
    cudaGetSymbolAddress((void**)&pWg1f, g_Wg1tf);
    cudaGetSymbolAddress((void**)&pWg2f, g_Wg2tf);

    cudaFuncSetAttribute(k_gemm_tc_h16, cudaFuncAttributeMaxDynamicSharedMemorySize, NSTAGE*STAGE_1);
    cudaFuncSetAttribute(k_agg_tc_h16, cudaFuncAttributeMaxDynamicSharedMemorySize, AGGH_SMEM);
    cudaFuncSetAttribute(k_agg_gcn2, cudaFuncAttributeMaxDynamicSharedMemorySize, FG_SMEM);
    cudaFuncSetAttribute(k_conv2_sw, cudaFuncAttributeMaxDynamicSharedMemorySize, CW_SMEM);

    k_setup<<<1472, 256>>>(ei, pos, Wp1, bp1, Wp2, bp2, Wg1, Wg2, W2);
    k_conv1stats<<<1024, 256>>>(x, W1);
    k_bn1pe<<<1024, 256>>>(x, W1, g1, b1);

    // agg0 = A @ h0  (fp16 1-chain), F = T*C0 = 8192
    k_agg_tc_h16<<<dim3(32, 8), 256, AGGH_SMEM>>>(pH0, pA0, 8192);
    // gcn1: h1 = relu(agg0 @ Wg1^T + bg1)  (fp16 1-chain)
    k_gemm_tc_h16<<<dim3(2, 512), 256, NSTAGE*STAGE_1>>>(pA0, pWg1f, bg1, pH1, 64, 256);
    // fused agg1 + gcn2: h2 = relu((A @ h1) @ Wg2^T + bg2)
    k_agg_gcn2<<<dim3(128, 8), 256, FG_SMEM>>>(pH1, pWg2f, bg2, pH2);
    // conv2 sliding-window fp16 1-chain + fused BN2 stats
    k_conv2_sw<<<512, 256, CW_SMEM>>>();
    k_pool<<<dim3(4, 30, 8), 128>>>(g2, b2);
    // conv3 (k=3 VALID, 128->128) SIMT
    k_gemm<<<dim3(2, 4, 1), 256>>>(pGbuf, W3, pY3, 224, 128, 384, 28, 30, 128);
    k_bn3stats<<<1, 256>>>();
    k_tail<<<8, 128>>>(g3, b3, Wd, bd, out);
}